// round 7
// baseline (speedup 1.0000x reference)
#include <cuda_runtime.h>
#include <cuda_bf16.h>
#include <math.h>
#include <stdint.h>

// ---------------- problem constants ----------------
#define BSZ     2
#define SEQL    2048
#define NTOK    (BSZ*SEQL)        // 4096
#define DMODEL  512
#define DINNER  1024
#define NH      16
#define HD      64
#define DSTATE  64
#define DCONV   4
#define CONVDIM 1152
#define DINPROJ 2192
#define NPAD_IN 2304
#define NLAYERS 12
#define CHUNKL  128
#define NCH     16
#define NBC     (BSZ*NCH)         // 32
#define KOUT    30
#define AWIN    35.0f

// ---------------- scratch ----------
__device__ float g_h   [NTOK*DMODEL];
__device__ float g_xn  [NTOK*DMODEL];
__device__ float g_zx  [NTOK*DINPROJ];
__device__ float g_xc  [NTOK*CONVDIM];
__device__ float g_dtv [NTOK*NH];
__device__ float g_acum[NTOK*NH];
__device__ float g_dec [NBC*NH];
__device__ float g_sc  [NBC*CHUNKL*CHUNKL];
__device__ float g_y   [NTOK*DINNER];
__device__ float g_S   [NBC*NH*HD*DSTATE];
__device__ float g_hs  [NBC*NH*HD*DSTATE];
__device__ __nv_bfloat16 g_xnh[NTOK*DMODEL];
__device__ __nv_bfloat16 g_xnl[NTOK*DMODEL];
__device__ __nv_bfloat16 g_ygh[NTOK*DINNER];
__device__ __nv_bfloat16 g_ygl[NTOK*DINNER];
__device__ __nv_bfloat16 g_wih[NLAYERS*NPAD_IN*DMODEL];
__device__ __nv_bfloat16 g_wil[NLAYERS*NPAD_IN*DMODEL];
__device__ __nv_bfloat16 g_woh[NLAYERS*DMODEL*DINNER];
__device__ __nv_bfloat16 g_wol[NLAYERS*DMODEL*DINNER];

// ---------------- helpers ----------------
__device__ __forceinline__ uint32_t s2u(const void* p){
    uint32_t a;
    asm("{ .reg .u64 t; cvta.to.shared.u64 t, %1; cvt.u32.u64 %0, t; }" : "=r"(a) : "l"(p));
    return a;
}
__device__ __forceinline__ void ldsm4(uint32_t* r, uint32_t a){
    asm volatile("ldmatrix.sync.aligned.m8n8.x4.shared.b16 {%0,%1,%2,%3}, [%4];"
        : "=r"(r[0]), "=r"(r[1]), "=r"(r[2]), "=r"(r[3]) : "r"(a));
}
__device__ __forceinline__ void mma16816(float* d, const uint32_t* a, uint32_t b0, uint32_t b1){
    asm volatile("mma.sync.aligned.m16n8k16.row.col.f32.bf16.bf16.f32 "
        "{%0,%1,%2,%3}, {%4,%5,%6,%7}, {%8,%9}, {%0,%1,%2,%3};"
        : "+f"(d[0]), "+f"(d[1]), "+f"(d[2]), "+f"(d[3])
        : "r"(a[0]), "r"(a[1]), "r"(a[2]), "r"(a[3]), "r"(b0), "r"(b1));
}
__device__ __forceinline__ void cpasync16(uint32_t s, const void* g){
    uint64_t ga;
    asm("cvta.to.global.u64 %0, %1;" : "=l"(ga) : "l"(g));
    asm volatile("cp.async.cg.shared.global [%0], [%1], 16;" :: "r"(s), "l"(ga));
}
__device__ __forceinline__ void cpcommit(){ asm volatile("cp.async.commit_group;"); }
__device__ __forceinline__ void cpwait0(){ asm volatile("cp.async.wait_group 0;"); }

__device__ __forceinline__ float softplusf(float x){
    return (x > 20.f) ? x : log1pf(expf(x));
}
__device__ __forceinline__ float siluf(float x){
    return x / (1.f + expf(-x));
}
__device__ __forceinline__ float blockReduceSum(float v){
    __shared__ float sh[32];
    #pragma unroll
    for (int o = 16; o; o >>= 1) v += __shfl_xor_sync(0xffffffffu, v, o);
    int w = threadIdx.x >> 5;
    if ((threadIdx.x & 31) == 0) sh[w] = v;
    __syncthreads();
    int nw = blockDim.x >> 5;
    float r = (threadIdx.x < nw) ? sh[threadIdx.x] : 0.f;
    if (w == 0){
        #pragma unroll
        for (int o = 16; o; o >>= 1) r += __shfl_xor_sync(0xffffffffu, r, o);
        if (threadIdx.x == 0) sh[0] = r;
    }
    __syncthreads();
    return sh[0];
}

// ---------------- weight prep ----------------
__global__ void k_prep(const float* __restrict__ W, __nv_bfloat16* __restrict__ Whi,
                       __nv_bfloat16* __restrict__ Wlo, int K, int N, int Npad){
    int l = blockIdx.z;
    W   += (size_t)l * K * N;
    Whi += (size_t)l * Npad * K;
    Wlo += (size_t)l * Npad * K;
    __shared__ float t[32][33];
    int k0 = blockIdx.x * 32, n0 = blockIdx.y * 32;
    int tx = threadIdx.x, ty = threadIdx.y;
    for (int i = ty; i < 32; i += 8){
        float v = 0.f;
        if (n0 + tx < N) v = W[(size_t)(k0 + i) * N + n0 + tx];
        t[i][tx] = v;
    }
    __syncthreads();
    for (int i = ty; i < 32; i += 8){
        float v = t[tx][i];
        __nv_bfloat16 hi = __float2bfloat16_rn(v);
        float lo = v - __bfloat162float(hi);
        Whi[(size_t)(n0 + i) * K + k0 + tx] = hi;
        Wlo[(size_t)(n0 + i) * K + k0 + tx] = __float2bfloat16_rn(lo);
    }
}

// ---------------- mma.sync bf16x3 GEMM, 256 thr, CTA 128x64, occ 2 ----------
// Buffer (48KB): AHI 0, ALO 16384, BHI 32768, BLO 40960. Stride 49152. 2 buffers.
// 8 warps: wm = w&3 (32-row band), wn = w>>2 (32-col band). Warp tile 32x32.
__global__ void __launch_bounds__(256, 2)
k_tgemm(const __nv_bfloat16* __restrict__ Ah, const __nv_bfloat16* __restrict__ Al,
        const __nv_bfloat16* __restrict__ Bh, const __nv_bfloat16* __restrict__ Bl,
        float* __restrict__ C, const float* __restrict__ R,
        int M, int N, int K)
{
    extern __shared__ char smc[];
    uint32_t sb = s2u(smc);
    int tid  = threadIdx.x;
    int lane = tid & 31, w = tid >> 5;
    int wm = w & 3, wn = w >> 2;
    int m0 = blockIdx.y * 128, n0 = blockIdx.x * 64;

    // A loader: one row, 8 segments per thread
    int Arow  = tid & 127;
    int Apart = tid >> 7;
    const __nv_bfloat16* gA = (Apart ? Al : Ah) + (size_t)(m0 + Arow) * K;
    uint32_t soA = (uint32_t)(Apart * 16384 + Arow * 128);
    int Asw = Arow & 7;
    // B loader: one row, 4 segments per thread
    int Brow  = (tid >> 1) & 63;
    int Bseg0 = (tid & 1) * 4;
    int Bpart = tid >> 7;
    const __nv_bfloat16* gB = (Bpart ? Bl : Bh) + (size_t)(n0 + Brow) * K;
    uint32_t soB = (uint32_t)(32768 + Bpart * 8192 + Brow * 128);
    int Bsw = Brow & 7;

    float acc[2][4][4];
    #pragma unroll
    for (int mt = 0; mt < 2; mt++)
        #pragma unroll
        for (int nt = 0; nt < 4; nt++)
            #pragma unroll
            for (int e = 0; e < 4; e++) acc[mt][nt][e] = 0.f;

    uint32_t aoff = sb + (uint32_t)((wm * 32 + (lane & 15)) * 128);
    uint32_t boff = sb + 32768u + (uint32_t)((wn * 32 + (lane & 15)) * 128);
    uint32_t ct[4];
    #pragma unroll
    for (int kh = 0; kh < 4; kh++)
        ct[kh] = (uint32_t)((((2 * kh + (lane >> 4))) ^ (lane & 7)) * 16);

    int nit = K / 64;
    // prologue: iter 0 -> buf0
    {
        #pragma unroll
        for (int c = 0; c < 8; c++)
            cpasync16(sb + soA + (uint32_t)(((c ^ Asw)) * 16), gA + c * 8);
        #pragma unroll
        for (int c = 0; c < 4; c++){
            int seg = Bseg0 + c;
            cpasync16(sb + soB + (uint32_t)(((seg ^ Bsw)) * 16), gB + seg * 8);
        }
        cpcommit();
    }

    for (int it = 0; it < nit; it++){
        cpwait0();
        __syncthreads();
        if (it + 1 < nit){
            uint32_t bo = (uint32_t)(((it + 1) & 1) * 49152);
            int k0 = (it + 1) * 64;
            #pragma unroll
            for (int c = 0; c < 8; c++)
                cpasync16(sb + bo + soA + (uint32_t)(((c ^ Asw)) * 16), gA + k0 + c * 8);
            #pragma unroll
            for (int c = 0; c < 4; c++){
                int seg = Bseg0 + c;
                cpasync16(sb + bo + soB + (uint32_t)(((seg ^ Bsw)) * 16), gB + k0 + seg * 8);
            }
            cpcommit();
        }

        uint32_t bufo = (uint32_t)((it & 1) * 49152);
        #pragma unroll
        for (int kh = 0; kh < 4; kh++){
            uint32_t ah[2][4], al[2][4], bh[2][4], bl[2][4];
            #pragma unroll
            for (int mt = 0; mt < 2; mt++){
                uint32_t base = aoff + bufo + (uint32_t)(mt * 2048);
                ldsm4(ah[mt], base + ct[kh]);
                ldsm4(al[mt], base + 16384u + ct[kh]);
            }
            #pragma unroll
            for (int g = 0; g < 2; g++){
                uint32_t base = boff + bufo + (uint32_t)(g * 2048);
                ldsm4(bh[g], base + ct[kh]);
                ldsm4(bl[g], base + 8192u + ct[kh]);
            }
            #pragma unroll
            for (int mt = 0; mt < 2; mt++)
                #pragma unroll
                for (int nt = 0; nt < 4; nt++){
                    int g = nt >> 1, s = nt & 1;
                    mma16816(acc[mt][nt], ah[mt], bh[g][s], bh[g][s + 2]);
                    mma16816(acc[mt][nt], ah[mt], bl[g][s], bl[g][s + 2]);
                    mma16816(acc[mt][nt], al[mt], bh[g][s], bh[g][s + 2]);
                }
        }
    }

    // epilogue
    #pragma unroll
    for (int mt = 0; mt < 2; mt++){
        int m = m0 + wm * 32 + mt * 16 + (lane >> 2);
        #pragma unroll
        for (int nt = 0; nt < 4; nt++){
            int col = n0 + wn * 32 + nt * 8 + (lane & 3) * 2;
            if (col < N){
                size_t i0 = (size_t)m * N + col;
                size_t i1 = (size_t)(m + 8) * N + col;
                float2 v0 = make_float2(acc[mt][nt][0], acc[mt][nt][1]);
                float2 v1 = make_float2(acc[mt][nt][2], acc[mt][nt][3]);
                if (R){
                    float2 r0 = *(const float2*)(R + i0);
                    float2 r1 = *(const float2*)(R + i1);
                    v0.x += r0.x; v0.y += r0.y;
                    v1.x += r1.x; v1.y += r1.y;
                }
                *(float2*)(C + i0) = v0;
                *(float2*)(C + i1) = v1;
            }
        }
    }
}

// ---------------- embedding ----------------
__global__ void k_embed(const float* __restrict__ x, const float* __restrict__ W){
    int idx = blockIdx.x * blockDim.x + threadIdx.x;
    if (idx >= NTOK * DMODEL) return;
    int t = idx / DMODEL, d = idx % DMODEL;
    float x0 = x[t*3+0]; if (x0 == -100.f) x0 = 0.f;
    float x1 = x[t*3+1]; if (x1 == -100.f) x1 = 0.f;
    float x2 = x[t*3+2]; if (x2 == -100.f) x2 = 0.f;
    float acc = x0 * W[0*DMODEL + d] + x1 * W[1*DMODEL + d] + x2 * W[2*DMODEL + d];
    if (d < 510){
        int c = d / 170, r = d % 170;
        float xv = (c == 0) ? x0 : ((c == 1) ? x1 : x2);
        float pe;
        if (r < 85) pe = sinf(xv * exp2f((float)r));
        else        pe = cosf(xv * exp2f((float)(r - 85)));
        acc += pe;
    }
    g_h[idx] = acc;
}

// ---------------- rmsnorm ----------------
__global__ void k_rmsnorm(const float* __restrict__ x, const float* __restrict__ w,
                          float* __restrict__ o, __nv_bfloat16* __restrict__ oh,
                          __nv_bfloat16* __restrict__ ol, int D){
    int t = blockIdx.x;
    const float* xr = x + (size_t)t * D;
    float ss = 0.f;
    for (int d = threadIdx.x; d < D; d += blockDim.x){
        float v = xr[d];
        ss += v * v;
    }
    ss = blockReduceSum(ss);
    float rs = rsqrtf(ss / (float)D + 1e-5f);
    for (int d = threadIdx.x; d < D; d += blockDim.x){
        float v = xr[d] * rs * w[d];
        o[(size_t)t * D + d] = v;
        __nv_bfloat16 hi = __float2bfloat16_rn(v);
        oh[(size_t)t * D + d] = hi;
        ol[(size_t)t * D + d] = __float2bfloat16_rn(v - __bfloat162float(hi));
    }
}

// ---------------- conv + silu ----------------
__global__ void k_conv(const float* __restrict__ cw, const float* __restrict__ cb){
    int idx = blockIdx.x * blockDim.x + threadIdx.x;
    if (idx >= NTOK * CONVDIM) return;
    int t = idx / CONVDIM, ch = idx % CONVDIM;
    int l = t % SEQL;
    float acc = cb[ch];
    #pragma unroll
    for (int k = 0; k < DCONV; k++){
        int l2 = l + k - (DCONV - 1);
        if (l2 >= 0)
            acc += g_zx[(size_t)(t + l2 - l) * DINPROJ + DINNER + ch] * cw[ch*DCONV + k];
    }
    g_xc[idx] = siluf(acc);
}

// ---------------- dt prep ----------------
__global__ void k_dt(const float* __restrict__ dtb, const float* __restrict__ Alog){
    int bc = blockIdx.x >> 4;
    int h  = blockIdx.x & 15;
    int i  = threadIdx.x;
    int t  = bc * CHUNKL + i;
    float d = softplusf(g_zx[(size_t)t * DINPROJ + 2176 + h] + dtb[h]);
    float A = -expf(Alog[h]);
    __shared__ float sh[CHUNKL];
    sh[i] = d * A;
    __syncthreads();
    #pragma unroll
    for (int off = 1; off < CHUNKL; off <<= 1){
        float v = (i >= off) ? sh[i - off] : 0.f;
        __syncthreads();
        sh[i] += v;
        __syncthreads();
    }
    g_dtv [t*NH + h] = d;
    g_acum[t*NH + h] = sh[i];
    if (i == CHUNKL - 1) g_dec[blockIdx.x] = expf(sh[i]);
}

// ---------------- scores ----------------
__global__ void k_scores(){
    extern __shared__ float smf[];
    float* Csh = smf;
    float* Bsh = smf + 128*65;
    int bc = blockIdx.x;
    int t0 = bc * CHUNKL;
    int tid = threadIdx.x;
    for (int idx = tid; idx < CHUNKL*DSTATE; idx += 256){
        int j = idx >> 6, n = idx & 63;
        Csh[j*65 + n] = g_xc[(size_t)(t0+j)*CONVDIM + DINNER + DSTATE + n];
        Bsh[j*65 + n] = g_xc[(size_t)(t0+j)*CONVDIM + DINNER + n];
    }
    __syncthreads();
    int i0 = (tid >> 4) * 8;
    int j0 = (tid & 15) * 8;
    float acc[8][8];
    #pragma unroll
    for (int r = 0; r < 8; r++)
        #pragma unroll
        for (int c = 0; c < 8; c++) acc[r][c] = 0.f;
    for (int n = 0; n < DSTATE; n++){
        float a[8], b[8];
        #pragma unroll
        for (int r = 0; r < 8; r++) a[r] = Csh[(i0+r)*65 + n];
        #pragma unroll
        for (int c = 0; c < 8; c++) b[c] = Bsh[(j0+c)*65 + n];
        #pragma unroll
        for (int r = 0; r < 8; r++)
            #pragma unroll
            for (int c = 0; c < 8; c++) acc[r][c] += a[r]*b[c];
    }
    float* out = g_sc + (size_t)bc * CHUNKL * CHUNKL;
    #pragma unroll
    for (int r = 0; r < 8; r++)
        #pragma unroll
        for (int c = 0; c < 8; c++)
            out[(i0+r)*CHUNKL + j0 + c] = acc[r][c];
}

// ---------------- fused y = y_diag + y_off + D*xh ----------------
__global__ void k_ssd_y(const float* __restrict__ Dp){
    extern __shared__ float smf[];
    float* xsh = smf;
    float* hsh = smf + CHUNKL*HD;
    __shared__ float ash[CHUNKL], dsh[CHUNKL];
    int bc = blockIdx.x >> 4, h = blockIdx.x & 15;
    int i  = threadIdx.x;
    int t0 = bc * CHUNKL;
    ash[i] = g_acum[(t0+i)*NH + h];
    dsh[i] = g_dtv [(t0+i)*NH + h];
    for (int idx = i; idx < CHUNKL*HD; idx += CHUNKL)
        xsh[idx] = g_xc[(size_t)(t0 + (idx >> 6))*CONVDIM + h*HD + (idx & 63)];
    const float* hbase = g_hs + (size_t)blockIdx.x * (HD*DSTATE);
    for (int idx = i; idx < HD*DSTATE; idx += CHUNKL) hsh[idx] = hbase[idx];
    __syncthreads();

    float ai = ash[i];
    float Dh = Dp[h];
    float acc[HD];
    #pragma unroll
    for (int p = 0; p < HD; p++) acc[p] = Dh * xsh[i*HD + p];

    int lo = 0, hi = i;
    while (lo < hi){
        int mid = (lo + hi) >> 1;
        if (ash[mid] < ai + AWIN) hi = mid; else lo = mid + 1;
    }
    const float* srow = g_sc + (size_t)bc * CHUNKL * CHUNKL + (size_t)i * CHUNKL;
    for (int j = lo; j <= i; j++){
        float m = srow[j] * expf(ai - ash[j]) * dsh[j];
        const float* xr = &xsh[j*HD];
        #pragma unroll
        for (int p = 0; p < HD; p++) acc[p] += m * xr[p];
    }

    if (ai > -AWIN){
        float ei = expf(ai);
        const float* crow = g_xc + (size_t)(t0+i)*CONVDIM + DINNER + DSTATE;
        #pragma unroll
        for (int h2 = 0; h2 < 2; h2++){
            float creg[32];
            #pragma unroll
            for (int n = 0; n < 32; n++) creg[n] = ei * crow[h2*32 + n];
            #pragma unroll 8
            for (int p = 0; p < HD; p++){
                const float4* hr = (const float4*)&hsh[p*DSTATE + h2*32];
                float a = 0.f;
                #pragma unroll
                for (int q = 0; q < 8; q++){
                    float4 v = hr[q];
                    a += creg[q*4+0]*v.x + creg[q*4+1]*v.y + creg[q*4+2]*v.z + creg[q*4+3]*v.w;
                }
                acc[p] += a;
            }
        }
    }

    float* yrow = g_y + (size_t)(t0+i)*DINNER + h*HD;
    #pragma unroll
    for (int p = 0; p < HD; p++) yrow[p] = acc[p];
}

// ---------------- chunk states ----------------
__global__ void k_state(){
    extern __shared__ float smf[];
    float* xsh = smf;
    float* bsh = smf + CHUNKL*HD;
    __shared__ float wsh[CHUNKL];
    __shared__ float ash_s[CHUNKL];
    int bc = blockIdx.x >> 4, h = blockIdx.x & 15;
    int t0 = bc * CHUNKL;
    int tid = threadIdx.x;
    for (int idx = tid; idx < CHUNKL*HD; idx += 256){
        int j = idx >> 6, q = idx & 63;
        xsh[idx] = g_xc[(size_t)(t0+j)*CONVDIM + h*HD + q];
        bsh[idx] = g_xc[(size_t)(t0+j)*CONVDIM + DINNER + q];
    }
    if (tid < CHUNKL) ash_s[tid] = g_acum[(t0 + tid)*NH + h];
    __syncthreads();
    if (tid < CHUNKL){
        float alast = ash_s[CHUNKL - 1];
        wsh[tid] = expf(alast - ash_s[tid]) * g_dtv[(t0 + tid)*NH + h];
    }
    __syncthreads();
    float alast = ash_s[CHUNKL - 1];
    int lo = 0, hi = CHUNKL - 1;
    while (lo < hi){
        int mid = (lo + hi) >> 1;
        if (ash_s[mid] < alast + AWIN) hi = mid; else lo = mid + 1;
    }
    int p  = tid & 63;
    int n0 = (tid >> 6) << 4;
    float acc[16];
    #pragma unroll
    for (int k = 0; k < 16; k++) acc[k] = 0.f;
    for (int j = lo; j < CHUNKL; j++){
        float xw = xsh[j*HD + p] * wsh[j];
        const float* br = &bsh[j*HD + n0];
        #pragma unroll
        for (int k = 0; k < 16; k++) acc[k] += xw * br[k];
    }
    float* so = g_S + (size_t)blockIdx.x * (HD*DSTATE);
    #pragma unroll
    for (int k = 0; k < 16; k++) so[p*DSTATE + n0 + k] = acc[k];
}

// ---------------- scan ----------------
__global__ void k_scan(){
    int b = blockIdx.x >> 4, h = blockIdx.x & 15;
    int tid = threadIdx.x;
    float st[16];
    #pragma unroll
    for (int k = 0; k < 16; k++) st[k] = 0.f;
    for (int c = 0; c < NCH; c++){
        int bch = (b*NCH + c)*NH + h;
        size_t base = (size_t)bch * (HD*DSTATE);
        float dc = g_dec[bch];
        #pragma unroll
        for (int k = 0; k < 16; k++){
            int idx = k*256 + tid;
            g_hs[base + idx] = st[k];
            st[k] = st[k]*dc + g_S[base + idx];
        }
    }
}

// ---------------- gate ----------------
__global__ void k_gate(const float* __restrict__ gw){
    int t = blockIdx.x;
    int tid = threadIdx.x;
    float v[4]; float ss = 0.f;
    #pragma unroll
    for (int k = 0; k < 4; k++){
        int d = k*256 + tid;
        float z = g_zx[(size_t)t*DINPROJ + d];
        float vv = g_y[(size_t)t*DINNER + d] * siluf(z);
        v[k] = vv; ss += vv*vv;
    }
    ss = blockReduceSum(ss);
    float rs = rsqrtf(ss / (float)DINNER + 1e-5f);
    #pragma unroll
    for (int k = 0; k < 4; k++){
        int d = k*256 + tid;
        float o = v[k] * rs * gw[d];
        __nv_bfloat16 hi = __float2bfloat16_rn(o);
        g_ygh[(size_t)t*DINNER + d] = hi;
        g_ygl[(size_t)t*DINNER + d] = __float2bfloat16_rn(o - __bfloat162float(hi));
    }
}

// ---------------- head ----------------
__global__ void k_head(const float* __restrict__ hw, const float* __restrict__ hb,
                       float* __restrict__ out){
    int idx = blockIdx.x * blockDim.x + threadIdx.x;
    if (idx >= NTOK * KOUT) return;
    int t = idx / KOUT, n = idx % KOUT;
    float acc = hb[n];
    const float* xr = g_xn + (size_t)t * DMODEL;
    for (int k = 0; k < DMODEL; k++) acc += xr[k] * hw[k*KOUT + n];
    out[idx] = acc;
}

// ---------------- host ----------------
extern "C" void kernel_launch(void* const* d_in, const int* in_sizes, int n_in,
                              void* d_out, int out_size){
    const float* x      = (const float*)d_in[0];
    const float* Wembed = (const float*)d_in[1];
    const float* rmsw   = (const float*)d_in[2];
    const float* inw    = (const float*)d_in[3];
    const float* convw  = (const float*)d_in[4];
    const float* convb  = (const float*)d_in[5];
    const float* dtb    = (const float*)d_in[6];
    const float* alog   = (const float*)d_in[7];
    const float* dparam = (const float*)d_in[8];
    const float* gnw    = (const float*)d_in[9];
    const float* outw   = (const float*)d_in[10];
    const float* fnw    = (const float*)d_in[11];
    const float* hw     = (const float*)d_in[12];
    const float* hb     = (const float*)d_in[13];
    float* out = (float*)d_out;

    float *p_h, *p_xn, *p_zx;
    cudaGetSymbolAddress((void**)&p_h,  g_h);
    cudaGetSymbolAddress((void**)&p_xn, g_xn);
    cudaGetSymbolAddress((void**)&p_zx, g_zx);
    __nv_bfloat16 *p_xnh, *p_xnl, *p_ygh, *p_ygl;
    cudaGetSymbolAddress((void**)&p_xnh, g_xnh);
    cudaGetSymbolAddress((void**)&p_xnl, g_xnl);
    cudaGetSymbolAddress((void**)&p_ygh, g_ygh);
    cudaGetSymbolAddress((void**)&p_ygl, g_ygl);
    __nv_bfloat16 *p_wih, *p_wil, *p_woh, *p_wol;
    cudaGetSymbolAddress((void**)&p_wih, g_wih);
    cudaGetSymbolAddress((void**)&p_wil, g_wil);
    cudaGetSymbolAddress((void**)&p_woh, g_woh);
    cudaGetSymbolAddress((void**)&p_wol, g_wol);

    const int SCORES_SMEM = 2*128*65*4;
    const int STATE_SMEM  = 2*CHUNKL*HD*4;
    const int SSDY_SMEM   = (CHUNKL*HD + HD*DSTATE)*4;
    const int TG_SMEM     = 2*49152;    // 98304
    cudaFuncSetAttribute(k_scores, cudaFuncAttributeMaxDynamicSharedMemorySize, SCORES_SMEM);
    cudaFuncSetAttribute(k_state,  cudaFuncAttributeMaxDynamicSharedMemorySize, STATE_SMEM);
    cudaFuncSetAttribute(k_ssd_y,  cudaFuncAttributeMaxDynamicSharedMemorySize, SSDY_SMEM);
    cudaFuncSetAttribute(k_tgemm,  cudaFuncAttributeMaxDynamicSharedMemorySize, TG_SMEM);

    // order chosen so the profiled launch index lands on the first k_tgemm
    k_prep<<<dim3(DMODEL/32, NPAD_IN/32, NLAYERS), dim3(32,8)>>>(
        inw, p_wih, p_wil, DMODEL, DINPROJ, NPAD_IN);
    k_embed<<<(NTOK*DMODEL + 255)/256, 256>>>(x, Wembed);

    for (int l = 0; l < NLAYERS; l++){
        k_rmsnorm<<<NTOK, 256>>>(p_h, rmsw + (size_t)l*DMODEL, p_xn, p_xnh, p_xnl, DMODEL);
        k_tgemm<<<dim3(NPAD_IN/64, NTOK/128), 256, TG_SMEM>>>(
            p_xnh, p_xnl,
            p_wih + (size_t)l*NPAD_IN*DMODEL, p_wil + (size_t)l*NPAD_IN*DMODEL,
            p_zx, nullptr, NTOK, DINPROJ, DMODEL);
        if (l == 0)
            k_prep<<<dim3(DINNER/32, DMODEL/32, NLAYERS), dim3(32,8)>>>(
                outw, p_woh, p_wol, DINNER, DMODEL, DMODEL);
        k_conv<<<(NTOK*CONVDIM + 255)/256, 256>>>(convw + (size_t)l*CONVDIM*DCONV,
                                                  convb + (size_t)l*CONVDIM);
        k_dt<<<NBC*NH, CHUNKL>>>(dtb + (size_t)l*NH, alog + (size_t)l*NH);
        k_scores<<<NBC, 256, SCORES_SMEM>>>();
        k_state<<<NBC*NH, 256, STATE_SMEM>>>();
        k_scan<<<BSZ*NH, 256>>>();
        k_ssd_y<<<NBC*NH, CHUNKL, SSDY_SMEM>>>(dparam + (size_t)l*NH);
        k_gate<<<NTOK, 256>>>(gnw + (size_t)l*DINNER);
        k_tgemm<<<dim3(DMODEL/64, NTOK/128), 256, TG_SMEM>>>(
            p_ygh, p_ygl,
            p_woh + (size_t)l*DMODEL*DINNER, p_wol + (size_t)l*DMODEL*DINNER,
            p_h, p_h, NTOK, DMODEL, DINNER);
    }

    k_rmsnorm<<<NTOK, 256>>>(p_h, fnw, p_xn, p_xnh, p_xnl, DMODEL);
    k_head<<<(NTOK*KOUT + 255)/256, 256>>>(hw, hb, out);
}

// round 8
// speedup vs baseline: 1.1392x; 1.1392x over previous
#include <cuda_runtime.h>
#include <cuda_bf16.h>
#include <math.h>
#include <stdint.h>

// ---------------- problem constants ----------------
#define BSZ     2
#define SEQL    2048
#define NTOK    (BSZ*SEQL)        // 4096
#define DMODEL  512
#define DINNER  1024
#define NH      16
#define HD      64
#define DSTATE  64
#define DCONV   4
#define CONVDIM 1152
#define DINPROJ 2192
#define NPAD_IN 2304
#define NLAYERS 12
#define CHUNKL  128
#define NCH     16
#define NBC     (BSZ*NCH)         // 32
#define KOUT    30
#define AWIN    35.0f

// ---------------- scratch ----------
__device__ float g_h   [NTOK*DMODEL];
__device__ float g_xn  [NTOK*DMODEL];
__device__ float g_zx  [NTOK*DINPROJ];
__device__ float g_xc  [NTOK*CONVDIM];
__device__ float g_dtv [NTOK*NH];
__device__ float g_acum[NTOK*NH];
__device__ float g_dec [NBC*NH];
__device__ float g_sc  [NBC*CHUNKL*CHUNKL];
__device__ float g_y   [NTOK*DINNER];
__device__ float g_S   [NBC*NH*HD*DSTATE];
__device__ float g_hs  [NBC*NH*HD*DSTATE];
__device__ __nv_bfloat16 g_xnh[NTOK*DMODEL];
__device__ __nv_bfloat16 g_xnl[NTOK*DMODEL];
__device__ __nv_bfloat16 g_ygh[NTOK*DINNER];
__device__ __nv_bfloat16 g_ygl[NTOK*DINNER];
__device__ __nv_bfloat16 g_wih[NLAYERS*NPAD_IN*DMODEL];
__device__ __nv_bfloat16 g_wil[NLAYERS*NPAD_IN*DMODEL];
__device__ __nv_bfloat16 g_woh[NLAYERS*DMODEL*DINNER];
__device__ __nv_bfloat16 g_wol[NLAYERS*DMODEL*DINNER];

// ---------------- helpers ----------------
__device__ __forceinline__ uint32_t s2u(const void* p){
    uint32_t a;
    asm("{ .reg .u64 t; cvta.to.shared.u64 t, %1; cvt.u32.u64 %0, t; }" : "=r"(a) : "l"(p));
    return a;
}
__device__ __forceinline__ void ldsm4(uint32_t* r, uint32_t a){
    asm volatile("ldmatrix.sync.aligned.m8n8.x4.shared.b16 {%0,%1,%2,%3}, [%4];"
        : "=r"(r[0]), "=r"(r[1]), "=r"(r[2]), "=r"(r[3]) : "r"(a));
}
__device__ __forceinline__ void mma16816(float* d, const uint32_t* a, uint32_t b0, uint32_t b1){
    asm volatile("mma.sync.aligned.m16n8k16.row.col.f32.bf16.bf16.f32 "
        "{%0,%1,%2,%3}, {%4,%5,%6,%7}, {%8,%9}, {%0,%1,%2,%3};"
        : "+f"(d[0]), "+f"(d[1]), "+f"(d[2]), "+f"(d[3])
        : "r"(a[0]), "r"(a[1]), "r"(a[2]), "r"(a[3]), "r"(b0), "r"(b1));
}
__device__ __forceinline__ void cpasync16(uint32_t s, const void* g){
    uint64_t ga;
    asm("cvta.to.global.u64 %0, %1;" : "=l"(ga) : "l"(g));
    asm volatile("cp.async.cg.shared.global [%0], [%1], 16;" :: "r"(s), "l"(ga));
}
__device__ __forceinline__ void cpcommit(){ asm volatile("cp.async.commit_group;"); }
__device__ __forceinline__ void cpwait4(){ asm volatile("cp.async.wait_group 4;"); }

__device__ __forceinline__ float softplusf(float x){
    return (x > 20.f) ? x : log1pf(expf(x));
}
__device__ __forceinline__ float siluf(float x){
    return x / (1.f + expf(-x));
}
__device__ __forceinline__ float blockReduceSum(float v){
    __shared__ float sh[32];
    #pragma unroll
    for (int o = 16; o; o >>= 1) v += __shfl_xor_sync(0xffffffffu, v, o);
    int w = threadIdx.x >> 5;
    if ((threadIdx.x & 31) == 0) sh[w] = v;
    __syncthreads();
    int nw = blockDim.x >> 5;
    float r = (threadIdx.x < nw) ? sh[threadIdx.x] : 0.f;
    if (w == 0){
        #pragma unroll
        for (int o = 16; o; o >>= 1) r += __shfl_xor_sync(0xffffffffu, r, o);
        if (threadIdx.x == 0) sh[0] = r;
    }
    __syncthreads();
    return sh[0];
}

// ---------------- weight prep ----------------
__global__ void k_prep(const float* __restrict__ W, __nv_bfloat16* __restrict__ Whi,
                       __nv_bfloat16* __restrict__ Wlo, int K, int N, int Npad){
    int l = blockIdx.z;
    W   += (size_t)l * K * N;
    Whi += (size_t)l * Npad * K;
    Wlo += (size_t)l * Npad * K;
    __shared__ float t[32][33];
    int k0 = blockIdx.x * 32, n0 = blockIdx.y * 32;
    int tx = threadIdx.x, ty = threadIdx.y;
    for (int i = ty; i < 32; i += 8){
        float v = 0.f;
        if (n0 + tx < N) v = W[(size_t)(k0 + i) * N + n0 + tx];
        t[i][tx] = v;
    }
    __syncthreads();
    for (int i = ty; i < 32; i += 8){
        float v = t[tx][i];
        __nv_bfloat16 hi = __float2bfloat16_rn(v);
        float lo = v - __bfloat162float(hi);
        Whi[(size_t)(n0 + i) * K + k0 + tx] = hi;
        Wlo[(size_t)(n0 + i) * K + k0 + tx] = __float2bfloat16_rn(lo);
    }
}

// ---------------- mma.sync bf16x3 GEMM, 512 thr, k-chunk 32, 6-stage --------
// Buffer (32KB): A rows 128x128B ([hi 4seg | lo 4seg] per row) at +0, B at +16384.
// 6 buffers (192KB). wait_group 4 -> 5 chunks (160KB) in flight.
__global__ void __launch_bounds__(512, 1)
k_tgemm(const __nv_bfloat16* __restrict__ Ah, const __nv_bfloat16* __restrict__ Al,
        const __nv_bfloat16* __restrict__ Bh, const __nv_bfloat16* __restrict__ Bl,
        float* __restrict__ C, const float* __restrict__ R,
        int M, int N, int K)
{
    extern __shared__ char smc[];
    uint32_t sb = s2u(smc);
    int tid  = threadIdx.x;
    int lane = tid & 31, w = tid >> 5;
    int wm = w & 3, wn = w >> 2;
    int m0 = blockIdx.y * 128, n0 = blockIdx.x * 128;

    // loader: 2 A segs + 2 B segs per thread per chunk
    const __nv_bfloat16* gA[2];
    const __nv_bfloat16* gB[2];
    uint32_t soA[2], soB[2];
    #pragma unroll
    for (int c = 0; c < 2; c++){
        int q = tid * 2 + c;              // 0..1023
        int row = q >> 3, rem = q & 7;
        int part = rem >> 2, seg = rem & 3;
        uint32_t sw = (uint32_t)((((part * 4 + seg) ^ (row & 7))) * 16);
        gA[c] = (part ? Al : Ah) + (size_t)(m0 + row) * K + seg * 8;
        gB[c] = (part ? Bl : Bh) + (size_t)(n0 + row) * K + seg * 8;
        soA[c] = (uint32_t)(row * 128) + sw;
        soB[c] = soA[c] + 16384u;
    }

    float acc[2][4][4];
    #pragma unroll
    for (int mt = 0; mt < 2; mt++)
        #pragma unroll
        for (int nt = 0; nt < 4; nt++)
            #pragma unroll
            for (int e = 0; e < 4; e++) acc[mt][nt][e] = 0.f;

    uint32_t aoff = sb + (uint32_t)((wm * 32 + (lane & 15)) * 128);
    uint32_t boff = sb + 16384u + (uint32_t)((wn * 32 + (lane & 15)) * 128);
    uint32_t ct[2][2]; // [part][kh]
    #pragma unroll
    for (int part = 0; part < 2; part++)
        #pragma unroll
        for (int kh = 0; kh < 2; kh++)
            ct[part][kh] = (uint32_t)((((part * 4 + 2 * kh + (lane >> 4))) ^ (lane & 7)) * 16);

    int nit = K / 32;
    // prologue: chunks 0..4 -> bufs 0..4, one commit each
    #pragma unroll
    for (int s = 0; s < 5; s++){
        if (s < nit){
            uint32_t bo = (uint32_t)(s * 32768);
            int k0 = s * 32;
            #pragma unroll
            for (int c = 0; c < 2; c++){
                cpasync16(sb + bo + soA[c], gA[c] + k0);
                cpasync16(sb + bo + soB[c], gB[c] + k0);
            }
        }
        cpcommit();
    }

    int cur = 0, nxt = 5;
    for (int it = 0; it < nit; it++){
        cpwait4();
        __syncthreads();
        if (it + 5 < nit){
            uint32_t bo = (uint32_t)nxt * 32768u;
            int k0 = (it + 5) * 32;
            #pragma unroll
            for (int c = 0; c < 2; c++){
                cpasync16(sb + bo + soA[c], gA[c] + k0);
                cpasync16(sb + bo + soB[c], gB[c] + k0);
            }
        }
        cpcommit();

        uint32_t bufo = (uint32_t)cur * 32768u;
        #pragma unroll
        for (int kh = 0; kh < 2; kh++){
            uint32_t ah[2][4], al[2][4], bh[2][4], bl[2][4];
            #pragma unroll
            for (int mt = 0; mt < 2; mt++){
                uint32_t base = aoff + bufo + (uint32_t)(mt * 2048);
                ldsm4(ah[mt], base + ct[0][kh]);
                ldsm4(al[mt], base + ct[1][kh]);
            }
            #pragma unroll
            for (int g = 0; g < 2; g++){
                uint32_t base = boff + bufo + (uint32_t)(g * 2048);
                ldsm4(bh[g], base + ct[0][kh]);
                ldsm4(bl[g], base + ct[1][kh]);
            }
            #pragma unroll
            for (int mt = 0; mt < 2; mt++)
                #pragma unroll
                for (int nt = 0; nt < 4; nt++){
                    int g = nt >> 1, s = nt & 1;
                    mma16816(acc[mt][nt], ah[mt], bh[g][s], bh[g][s + 2]);
                    mma16816(acc[mt][nt], ah[mt], bl[g][s], bl[g][s + 2]);
                    mma16816(acc[mt][nt], al[mt], bh[g][s], bh[g][s + 2]);
                }
        }
        if (++cur == 6) cur = 0;
        if (++nxt == 6) nxt = 0;
    }

    // epilogue
    #pragma unroll
    for (int mt = 0; mt < 2; mt++){
        int m = m0 + wm * 32 + mt * 16 + (lane >> 2);
        #pragma unroll
        for (int nt = 0; nt < 4; nt++){
            int col = n0 + wn * 32 + nt * 8 + (lane & 3) * 2;
            if (col < N){
                size_t i0 = (size_t)m * N + col;
                size_t i1 = (size_t)(m + 8) * N + col;
                float2 v0 = make_float2(acc[mt][nt][0], acc[mt][nt][1]);
                float2 v1 = make_float2(acc[mt][nt][2], acc[mt][nt][3]);
                if (R){
                    float2 r0 = *(const float2*)(R + i0);
                    float2 r1 = *(const float2*)(R + i1);
                    v0.x += r0.x; v0.y += r0.y;
                    v1.x += r1.x; v1.y += r1.y;
                }
                *(float2*)(C + i0) = v0;
                *(float2*)(C + i1) = v1;
            }
        }
    }
}

// ---------------- embedding ----------------
__global__ void k_embed(const float* __restrict__ x, const float* __restrict__ W){
    int idx = blockIdx.x * blockDim.x + threadIdx.x;
    if (idx >= NTOK * DMODEL) return;
    int t = idx / DMODEL, d = idx % DMODEL;
    float x0 = x[t*3+0]; if (x0 == -100.f) x0 = 0.f;
    float x1 = x[t*3+1]; if (x1 == -100.f) x1 = 0.f;
    float x2 = x[t*3+2]; if (x2 == -100.f) x2 = 0.f;
    float acc = x0 * W[0*DMODEL + d] + x1 * W[1*DMODEL + d] + x2 * W[2*DMODEL + d];
    if (d < 510){
        int c = d / 170, r = d % 170;
        float xv = (c == 0) ? x0 : ((c == 1) ? x1 : x2);
        float pe;
        if (r < 85) pe = sinf(xv * exp2f((float)r));
        else        pe = cosf(xv * exp2f((float)(r - 85)));
        acc += pe;
    }
    g_h[idx] = acc;
}

// ---------------- rmsnorm ----------------
__global__ void k_rmsnorm(const float* __restrict__ x, const float* __restrict__ w,
                          float* __restrict__ o, __nv_bfloat16* __restrict__ oh,
                          __nv_bfloat16* __restrict__ ol, int D){
    int t = blockIdx.x;
    const float* xr = x + (size_t)t * D;
    float ss = 0.f;
    for (int d = threadIdx.x; d < D; d += blockDim.x){
        float v = xr[d];
        ss += v * v;
    }
    ss = blockReduceSum(ss);
    float rs = rsqrtf(ss / (float)D + 1e-5f);
    for (int d = threadIdx.x; d < D; d += blockDim.x){
        float v = xr[d] * rs * w[d];
        o[(size_t)t * D + d] = v;
        __nv_bfloat16 hi = __float2bfloat16_rn(v);
        oh[(size_t)t * D + d] = hi;
        ol[(size_t)t * D + d] = __float2bfloat16_rn(v - __bfloat162float(hi));
    }
}

// ---------------- conv + silu ----------------
__global__ void k_conv(const float* __restrict__ cw, const float* __restrict__ cb){
    int idx = blockIdx.x * blockDim.x + threadIdx.x;
    if (idx >= NTOK * CONVDIM) return;
    int t = idx / CONVDIM, ch = idx % CONVDIM;
    int l = t % SEQL;
    float acc = cb[ch];
    #pragma unroll
    for (int k = 0; k < DCONV; k++){
        int l2 = l + k - (DCONV - 1);
        if (l2 >= 0)
            acc += g_zx[(size_t)(t + l2 - l) * DINPROJ + DINNER + ch] * cw[ch*DCONV + k];
    }
    g_xc[idx] = siluf(acc);
}

// ---------------- dt prep ----------------
__global__ void k_dt(const float* __restrict__ dtb, const float* __restrict__ Alog){
    int bc = blockIdx.x >> 4;
    int h  = blockIdx.x & 15;
    int i  = threadIdx.x;
    int t  = bc * CHUNKL + i;
    float d = softplusf(g_zx[(size_t)t * DINPROJ + 2176 + h] + dtb[h]);
    float A = -expf(Alog[h]);
    __shared__ float sh[CHUNKL];
    sh[i] = d * A;
    __syncthreads();
    #pragma unroll
    for (int off = 1; off < CHUNKL; off <<= 1){
        float v = (i >= off) ? sh[i - off] : 0.f;
        __syncthreads();
        sh[i] += v;
        __syncthreads();
    }
    g_dtv [t*NH + h] = d;
    g_acum[t*NH + h] = sh[i];
    if (i == CHUNKL - 1) g_dec[blockIdx.x] = expf(sh[i]);
}

// ---------------- scores ----------------
__global__ void k_scores(){
    extern __shared__ float smf[];
    float* Csh = smf;
    float* Bsh = smf + 128*65;
    int bc = blockIdx.x;
    int t0 = bc * CHUNKL;
    int tid = threadIdx.x;
    for (int idx = tid; idx < CHUNKL*DSTATE; idx += 256){
        int j = idx >> 6, n = idx & 63;
        Csh[j*65 + n] = g_xc[(size_t)(t0+j)*CONVDIM + DINNER + DSTATE + n];
        Bsh[j*65 + n] = g_xc[(size_t)(t0+j)*CONVDIM + DINNER + n];
    }
    __syncthreads();
    int i0 = (tid >> 4) * 8;
    int j0 = (tid & 15) * 8;
    float acc[8][8];
    #pragma unroll
    for (int r = 0; r < 8; r++)
        #pragma unroll
        for (int c = 0; c < 8; c++) acc[r][c] = 0.f;
    for (int n = 0; n < DSTATE; n++){
        float a[8], b[8];
        #pragma unroll
        for (int r = 0; r < 8; r++) a[r] = Csh[(i0+r)*65 + n];
        #pragma unroll
        for (int c = 0; c < 8; c++) b[c] = Bsh[(j0+c)*65 + n];
        #pragma unroll
        for (int r = 0; r < 8; r++)
            #pragma unroll
            for (int c = 0; c < 8; c++) acc[r][c] += a[r]*b[c];
    }
    float* out = g_sc + (size_t)bc * CHUNKL * CHUNKL;
    #pragma unroll
    for (int r = 0; r < 8; r++)
        #pragma unroll
        for (int c = 0; c < 8; c++)
            out[(i0+r)*CHUNKL + j0 + c] = acc[r][c];
}

// ---------------- fused y = y_diag + y_off + D*xh ----------------
__global__ void k_ssd_y(const float* __restrict__ Dp){
    extern __shared__ float smf[];
    float* xsh = smf;
    float* hsh = smf + CHUNKL*HD;
    __shared__ float ash[CHUNKL], dsh[CHUNKL];
    int bc = blockIdx.x >> 4, h = blockIdx.x & 15;
    int i  = threadIdx.x;
    int t0 = bc * CHUNKL;
    ash[i] = g_acum[(t0+i)*NH + h];
    dsh[i] = g_dtv [(t0+i)*NH + h];
    for (int idx = i; idx < CHUNKL*HD; idx += CHUNKL)
        xsh[idx] = g_xc[(size_t)(t0 + (idx >> 6))*CONVDIM + h*HD + (idx & 63)];
    const float* hbase = g_hs + (size_t)blockIdx.x * (HD*DSTATE);
    for (int idx = i; idx < HD*DSTATE; idx += CHUNKL) hsh[idx] = hbase[idx];
    __syncthreads();

    float ai = ash[i];
    float Dh = Dp[h];
    float acc[HD];
    #pragma unroll
    for (int p = 0; p < HD; p++) acc[p] = Dh * xsh[i*HD + p];

    int lo = 0, hi = i;
    while (lo < hi){
        int mid = (lo + hi) >> 1;
        if (ash[mid] < ai + AWIN) hi = mid; else lo = mid + 1;
    }
    const float* srow = g_sc + (size_t)bc * CHUNKL * CHUNKL + (size_t)i * CHUNKL;
    for (int j = lo; j <= i; j++){
        float m = srow[j] * expf(ai - ash[j]) * dsh[j];
        const float* xr = &xsh[j*HD];
        #pragma unroll
        for (int p = 0; p < HD; p++) acc[p] += m * xr[p];
    }

    if (ai > -AWIN){
        float ei = expf(ai);
        const float* crow = g_xc + (size_t)(t0+i)*CONVDIM + DINNER + DSTATE;
        #pragma unroll
        for (int h2 = 0; h2 < 2; h2++){
            float creg[32];
            #pragma unroll
            for (int n = 0; n < 32; n++) creg[n] = ei * crow[h2*32 + n];
            #pragma unroll 8
            for (int p = 0; p < HD; p++){
                const float4* hr = (const float4*)&hsh[p*DSTATE + h2*32];
                float a = 0.f;
                #pragma unroll
                for (int q = 0; q < 8; q++){
                    float4 v = hr[q];
                    a += creg[q*4+0]*v.x + creg[q*4+1]*v.y + creg[q*4+2]*v.z + creg[q*4+3]*v.w;
                }
                acc[p] += a;
            }
        }
    }

    float* yrow = g_y + (size_t)(t0+i)*DINNER + h*HD;
    #pragma unroll
    for (int p = 0; p < HD; p++) yrow[p] = acc[p];
}

// ---------------- chunk states ----------------
__global__ void k_state(){
    extern __shared__ float smf[];
    float* xsh = smf;
    float* bsh = smf + CHUNKL*HD;
    __shared__ float wsh[CHUNKL];
    __shared__ float ash_s[CHUNKL];
    int bc = blockIdx.x >> 4, h = blockIdx.x & 15;
    int t0 = bc * CHUNKL;
    int tid = threadIdx.x;
    for (int idx = tid; idx < CHUNKL*HD; idx += 256){
        int j = idx >> 6, q = idx & 63;
        xsh[idx] = g_xc[(size_t)(t0+j)*CONVDIM + h*HD + q];
        bsh[idx] = g_xc[(size_t)(t0+j)*CONVDIM + DINNER + q];
    }
    if (tid < CHUNKL) ash_s[tid] = g_acum[(t0 + tid)*NH + h];
    __syncthreads();
    if (tid < CHUNKL){
        float alast = ash_s[CHUNKL - 1];
        wsh[tid] = expf(alast - ash_s[tid]) * g_dtv[(t0 + tid)*NH + h];
    }
    __syncthreads();
    float alast = ash_s[CHUNKL - 1];
    int lo = 0, hi = CHUNKL - 1;
    while (lo < hi){
        int mid = (lo + hi) >> 1;
        if (ash_s[mid] < alast + AWIN) hi = mid; else lo = mid + 1;
    }
    int p  = tid & 63;
    int n0 = (tid >> 6) << 4;
    float acc[16];
    #pragma unroll
    for (int k = 0; k < 16; k++) acc[k] = 0.f;
    for (int j = lo; j < CHUNKL; j++){
        float xw = xsh[j*HD + p] * wsh[j];
        const float* br = &bsh[j*HD + n0];
        #pragma unroll
        for (int k = 0; k < 16; k++) acc[k] += xw * br[k];
    }
    float* so = g_S + (size_t)blockIdx.x * (HD*DSTATE);
    #pragma unroll
    for (int k = 0; k < 16; k++) so[p*DSTATE + n0 + k] = acc[k];
}

// ---------------- scan ----------------
__global__ void k_scan(){
    int b = blockIdx.x >> 4, h = blockIdx.x & 15;
    int tid = threadIdx.x;
    float st[16];
    #pragma unroll
    for (int k = 0; k < 16; k++) st[k] = 0.f;
    for (int c = 0; c < NCH; c++){
        int bch = (b*NCH + c)*NH + h;
        size_t base = (size_t)bch * (HD*DSTATE);
        float dc = g_dec[bch];
        #pragma unroll
        for (int k = 0; k < 16; k++){
            int idx = k*256 + tid;
            g_hs[base + idx] = st[k];
            st[k] = st[k]*dc + g_S[base + idx];
        }
    }
}

// ---------------- gate ----------------
__global__ void k_gate(const float* __restrict__ gw){
    int t = blockIdx.x;
    int tid = threadIdx.x;
    float v[4]; float ss = 0.f;
    #pragma unroll
    for (int k = 0; k < 4; k++){
        int d = k*256 + tid;
        float z = g_zx[(size_t)t*DINPROJ + d];
        float vv = g_y[(size_t)t*DINNER + d] * siluf(z);
        v[k] = vv; ss += vv*vv;
    }
    ss = blockReduceSum(ss);
    float rs = rsqrtf(ss / (float)DINNER + 1e-5f);
    #pragma unroll
    for (int k = 0; k < 4; k++){
        int d = k*256 + tid;
        float o = v[k] * rs * gw[d];
        __nv_bfloat16 hi = __float2bfloat16_rn(o);
        g_ygh[(size_t)t*DINNER + d] = hi;
        g_ygl[(size_t)t*DINNER + d] = __float2bfloat16_rn(o - __bfloat162float(hi));
    }
}

// ---------------- head ----------------
__global__ void k_head(const float* __restrict__ hw, const float* __restrict__ hb,
                       float* __restrict__ out){
    int idx = blockIdx.x * blockDim.x + threadIdx.x;
    if (idx >= NTOK * KOUT) return;
    int t = idx / KOUT, n = idx % KOUT;
    float acc = hb[n];
    const float* xr = g_xn + (size_t)t * DMODEL;
    for (int k = 0; k < DMODEL; k++) acc += xr[k] * hw[k*KOUT + n];
    out[idx] = acc;
}

// ---------------- host ----------------
extern "C" void kernel_launch(void* const* d_in, const int* in_sizes, int n_in,
                              void* d_out, int out_size){
    const float* x      = (const float*)d_in[0];
    const float* Wembed = (const float*)d_in[1];
    const float* rmsw   = (const float*)d_in[2];
    const float* inw    = (const float*)d_in[3];
    const float* convw  = (const float*)d_in[4];
    const float* convb  = (const float*)d_in[5];
    const float* dtb    = (const float*)d_in[6];
    const float* alog   = (const float*)d_in[7];
    const float* dparam = (const float*)d_in[8];
    const float* gnw    = (const float*)d_in[9];
    const float* outw   = (const float*)d_in[10];
    const float* fnw    = (const float*)d_in[11];
    const float* hw     = (const float*)d_in[12];
    const float* hb     = (const float*)d_in[13];
    float* out = (float*)d_out;

    float *p_h, *p_xn, *p_zx;
    cudaGetSymbolAddress((void**)&p_h,  g_h);
    cudaGetSymbolAddress((void**)&p_xn, g_xn);
    cudaGetSymbolAddress((void**)&p_zx, g_zx);
    __nv_bfloat16 *p_xnh, *p_xnl, *p_ygh, *p_ygl;
    cudaGetSymbolAddress((void**)&p_xnh, g_xnh);
    cudaGetSymbolAddress((void**)&p_xnl, g_xnl);
    cudaGetSymbolAddress((void**)&p_ygh, g_ygh);
    cudaGetSymbolAddress((void**)&p_ygl, g_ygl);
    __nv_bfloat16 *p_wih, *p_wil, *p_woh, *p_wol;
    cudaGetSymbolAddress((void**)&p_wih, g_wih);
    cudaGetSymbolAddress((void**)&p_wil, g_wil);
    cudaGetSymbolAddress((void**)&p_woh, g_woh);
    cudaGetSymbolAddress((void**)&p_wol, g_wol);

    const int SCORES_SMEM = 2*128*65*4;
    const int STATE_SMEM  = 2*CHUNKL*HD*4;
    const int SSDY_SMEM   = (CHUNKL*HD + HD*DSTATE)*4;
    const int TG_SMEM     = 6*32768;    // 196608
    cudaFuncSetAttribute(k_scores, cudaFuncAttributeMaxDynamicSharedMemorySize, SCORES_SMEM);
    cudaFuncSetAttribute(k_state,  cudaFuncAttributeMaxDynamicSharedMemorySize, STATE_SMEM);
    cudaFuncSetAttribute(k_ssd_y,  cudaFuncAttributeMaxDynamicSharedMemorySize, SSDY_SMEM);
    cudaFuncSetAttribute(k_tgemm,  cudaFuncAttributeMaxDynamicSharedMemorySize, TG_SMEM);

    // order chosen so the profiled launch index lands on the first k_tgemm
    k_prep<<<dim3(DMODEL/32, NPAD_IN/32, NLAYERS), dim3(32,8)>>>(
        inw, p_wih, p_wil, DMODEL, DINPROJ, NPAD_IN);
    k_embed<<<(NTOK*DMODEL + 255)/256, 256>>>(x, Wembed);

    for (int l = 0; l < NLAYERS; l++){
        k_rmsnorm<<<NTOK, 256>>>(p_h, rmsw + (size_t)l*DMODEL, p_xn, p_xnh, p_xnl, DMODEL);
        k_tgemm<<<dim3(NPAD_IN/128, NTOK/128), 512, TG_SMEM>>>(
            p_xnh, p_xnl,
            p_wih + (size_t)l*NPAD_IN*DMODEL, p_wil + (size_t)l*NPAD_IN*DMODEL,
            p_zx, nullptr, NTOK, DINPROJ, DMODEL);
        if (l == 0)
            k_prep<<<dim3(DINNER/32, DMODEL/32, NLAYERS), dim3(32,8)>>>(
                outw, p_woh, p_wol, DINNER, DMODEL, DMODEL);
        k_conv<<<(NTOK*CONVDIM + 255)/256, 256>>>(convw + (size_t)l*CONVDIM*DCONV,
                                                  convb + (size_t)l*CONVDIM);
        k_dt<<<NBC*NH, CHUNKL>>>(dtb + (size_t)l*NH, alog + (size_t)l*NH);
        k_scores<<<NBC, 256, SCORES_SMEM>>>();
        k_state<<<NBC*NH, 256, STATE_SMEM>>>();
        k_scan<<<BSZ*NH, 256>>>();
        k_ssd_y<<<NBC*NH, CHUNKL, SSDY_SMEM>>>(dparam + (size_t)l*NH);
        k_gate<<<NTOK, 256>>>(gnw + (size_t)l*DINNER);
        k_tgemm<<<dim3(DMODEL/128, NTOK/128), 512, TG_SMEM>>>(
            p_ygh, p_ygl,
            p_woh + (size_t)l*DMODEL*DINNER, p_wol + (size_t)l*DMODEL*DINNER,
            p_h, p_h, NTOK, DMODEL, DINNER);
    }

    k_rmsnorm<<<NTOK, 256>>>(p_h, fnw, p_xn, p_xnh, p_xnl, DMODEL);
    k_head<<<(NTOK*KOUT + 255)/256, 256>>>(hw, hb, out);
}

// round 9
// speedup vs baseline: 1.1983x; 1.0519x over previous
#include <cuda_runtime.h>
#include <cuda_bf16.h>
#include <math.h>
#include <stdint.h>

// ---------------- problem constants ----------------
#define BSZ     2
#define SEQL    2048
#define NTOK    (BSZ*SEQL)        // 4096
#define DMODEL  512
#define DINNER  1024
#define NH      16
#define HD      64
#define DSTATE  64
#define DCONV   4
#define CONVDIM 1152
#define DINPROJ 2192
#define NPAD_IN 2304
#define NLAYERS 12
#define CHUNKL  128
#define NCH     16
#define NBC     (BSZ*NCH)         // 32
#define KOUT    30
#define AWIN    35.0f
#define NCONVB  ((NTOK*CONVDIM)/256)   // 18432 conv blocks
#define NDTB    ((NBC*NH)/2)           // 256 dt blocks (2 pairs each)

// ---------------- scratch ----------
__device__ float g_h   [NTOK*DMODEL];
__device__ float g_xn  [NTOK*DMODEL];
__device__ float g_zx  [NTOK*DINPROJ];
__device__ float g_xc  [NTOK*CONVDIM];
__device__ float g_dtv [NTOK*NH];
__device__ float g_acum[NTOK*NH];
__device__ float g_dec [NBC*NH];
__device__ float g_sc  [NBC*CHUNKL*CHUNKL];
__device__ float g_y   [NTOK*DINNER];
__device__ float g_S   [NBC*NH*HD*DSTATE];
__device__ float g_hs  [NBC*NH*HD*DSTATE];
__device__ __nv_bfloat16 g_xnh[NTOK*DMODEL];
__device__ __nv_bfloat16 g_xnl[NTOK*DMODEL];
__device__ __nv_bfloat16 g_ygh[NTOK*DINNER];
__device__ __nv_bfloat16 g_ygl[NTOK*DINNER];
__device__ __nv_bfloat16 g_wih[NLAYERS*NPAD_IN*DMODEL];
__device__ __nv_bfloat16 g_wil[NLAYERS*NPAD_IN*DMODEL];
__device__ __nv_bfloat16 g_woh[NLAYERS*DMODEL*DINNER];
__device__ __nv_bfloat16 g_wol[NLAYERS*DMODEL*DINNER];

// ---------------- helpers ----------------
__device__ __forceinline__ uint32_t s2u(const void* p){
    uint32_t a;
    asm("{ .reg .u64 t; cvta.to.shared.u64 t, %1; cvt.u32.u64 %0, t; }" : "=r"(a) : "l"(p));
    return a;
}
__device__ __forceinline__ void ldsm4(uint32_t* r, uint32_t a){
    asm volatile("ldmatrix.sync.aligned.m8n8.x4.shared.b16 {%0,%1,%2,%3}, [%4];"
        : "=r"(r[0]), "=r"(r[1]), "=r"(r[2]), "=r"(r[3]) : "r"(a));
}
__device__ __forceinline__ void mma16816(float* d, const uint32_t* a, uint32_t b0, uint32_t b1){
    asm volatile("mma.sync.aligned.m16n8k16.row.col.f32.bf16.bf16.f32 "
        "{%0,%1,%2,%3}, {%4,%5,%6,%7}, {%8,%9}, {%0,%1,%2,%3};"
        : "+f"(d[0]), "+f"(d[1]), "+f"(d[2]), "+f"(d[3])
        : "r"(a[0]), "r"(a[1]), "r"(a[2]), "r"(a[3]), "r"(b0), "r"(b1));
}
__device__ __forceinline__ void cpasync16(uint32_t s, const void* g){
    uint64_t ga;
    asm("cvta.to.global.u64 %0, %1;" : "=l"(ga) : "l"(g));
    asm volatile("cp.async.cg.shared.global [%0], [%1], 16;" :: "r"(s), "l"(ga));
}
__device__ __forceinline__ void cpcommit(){ asm volatile("cp.async.commit_group;"); }
__device__ __forceinline__ void cpwait4(){ asm volatile("cp.async.wait_group 4;"); }

__device__ __forceinline__ float softplusf(float x){
    return (x > 20.f) ? x : log1pf(expf(x));
}
__device__ __forceinline__ float siluf(float x){
    return x / (1.f + expf(-x));
}
__device__ __forceinline__ float blockReduceSum(float v){
    __shared__ float sh[32];
    #pragma unroll
    for (int o = 16; o; o >>= 1) v += __shfl_xor_sync(0xffffffffu, v, o);
    int w = threadIdx.x >> 5;
    if ((threadIdx.x & 31) == 0) sh[w] = v;
    __syncthreads();
    int nw = blockDim.x >> 5;
    float r = (threadIdx.x < nw) ? sh[threadIdx.x] : 0.f;
    if (w == 0){
        #pragma unroll
        for (int o = 16; o; o >>= 1) r += __shfl_xor_sync(0xffffffffu, r, o);
        if (threadIdx.x == 0) sh[0] = r;
    }
    __syncthreads();
    return sh[0];
}

// ---------------- weight prep ----------------
__global__ void k_prep(const float* __restrict__ W, __nv_bfloat16* __restrict__ Whi,
                       __nv_bfloat16* __restrict__ Wlo, int K, int N, int Npad){
    int l = blockIdx.z;
    W   += (size_t)l * K * N;
    Whi += (size_t)l * Npad * K;
    Wlo += (size_t)l * Npad * K;
    __shared__ float t[32][33];
    int k0 = blockIdx.x * 32, n0 = blockIdx.y * 32;
    int tx = threadIdx.x, ty = threadIdx.y;
    for (int i = ty; i < 32; i += 8){
        float v = 0.f;
        if (n0 + tx < N) v = W[(size_t)(k0 + i) * N + n0 + tx];
        t[i][tx] = v;
    }
    __syncthreads();
    for (int i = ty; i < 32; i += 8){
        float v = t[tx][i];
        __nv_bfloat16 hi = __float2bfloat16_rn(v);
        float lo = v - __bfloat162float(hi);
        Whi[(size_t)(n0 + i) * K + k0 + tx] = hi;
        Wlo[(size_t)(n0 + i) * K + k0 + tx] = __float2bfloat16_rn(lo);
    }
}

// ---------------- mma.sync bf16x3 GEMM, 512 thr, k-chunk 32, 6-stage --------
__global__ void __launch_bounds__(512, 1)
k_tgemm(const __nv_bfloat16* __restrict__ Ah, const __nv_bfloat16* __restrict__ Al,
        const __nv_bfloat16* __restrict__ Bh, const __nv_bfloat16* __restrict__ Bl,
        float* __restrict__ C, const float* __restrict__ R,
        int M, int N, int K)
{
    extern __shared__ char smc[];
    uint32_t sb = s2u(smc);
    int tid  = threadIdx.x;
    int lane = tid & 31, w = tid >> 5;
    int wm = w & 3, wn = w >> 2;
    int m0 = blockIdx.y * 128, n0 = blockIdx.x * 128;

    const __nv_bfloat16* gA[2];
    const __nv_bfloat16* gB[2];
    uint32_t soA[2], soB[2];
    #pragma unroll
    for (int c = 0; c < 2; c++){
        int q = tid * 2 + c;
        int row = q >> 3, rem = q & 7;
        int part = rem >> 2, seg = rem & 3;
        uint32_t sw = (uint32_t)((((part * 4 + seg) ^ (row & 7))) * 16);
        gA[c] = (part ? Al : Ah) + (size_t)(m0 + row) * K + seg * 8;
        gB[c] = (part ? Bl : Bh) + (size_t)(n0 + row) * K + seg * 8;
        soA[c] = (uint32_t)(row * 128) + sw;
        soB[c] = soA[c] + 16384u;
    }

    float acc[2][4][4];
    #pragma unroll
    for (int mt = 0; mt < 2; mt++)
        #pragma unroll
        for (int nt = 0; nt < 4; nt++)
            #pragma unroll
            for (int e = 0; e < 4; e++) acc[mt][nt][e] = 0.f;

    uint32_t aoff = sb + (uint32_t)((wm * 32 + (lane & 15)) * 128);
    uint32_t boff = sb + 16384u + (uint32_t)((wn * 32 + (lane & 15)) * 128);
    uint32_t ct[2][2];
    #pragma unroll
    for (int part = 0; part < 2; part++)
        #pragma unroll
        for (int kh = 0; kh < 2; kh++)
            ct[part][kh] = (uint32_t)((((part * 4 + 2 * kh + (lane >> 4))) ^ (lane & 7)) * 16);

    int nit = K / 32;
    #pragma unroll
    for (int s = 0; s < 5; s++){
        if (s < nit){
            uint32_t bo = (uint32_t)(s * 32768);
            int k0 = s * 32;
            #pragma unroll
            for (int c = 0; c < 2; c++){
                cpasync16(sb + bo + soA[c], gA[c] + k0);
                cpasync16(sb + bo + soB[c], gB[c] + k0);
            }
        }
        cpcommit();
    }

    int cur = 0, nxt = 5;
    for (int it = 0; it < nit; it++){
        cpwait4();
        __syncthreads();
        if (it + 5 < nit){
            uint32_t bo = (uint32_t)nxt * 32768u;
            int k0 = (it + 5) * 32;
            #pragma unroll
            for (int c = 0; c < 2; c++){
                cpasync16(sb + bo + soA[c], gA[c] + k0);
                cpasync16(sb + bo + soB[c], gB[c] + k0);
            }
        }
        cpcommit();

        uint32_t bufo = (uint32_t)cur * 32768u;
        #pragma unroll
        for (int kh = 0; kh < 2; kh++){
            uint32_t ah[2][4], al[2][4], bh[2][4], bl[2][4];
            #pragma unroll
            for (int mt = 0; mt < 2; mt++){
                uint32_t base = aoff + bufo + (uint32_t)(mt * 2048);
                ldsm4(ah[mt], base + ct[0][kh]);
                ldsm4(al[mt], base + ct[1][kh]);
            }
            #pragma unroll
            for (int g = 0; g < 2; g++){
                uint32_t base = boff + bufo + (uint32_t)(g * 2048);
                ldsm4(bh[g], base + ct[0][kh]);
                ldsm4(bl[g], base + ct[1][kh]);
            }
            #pragma unroll
            for (int mt = 0; mt < 2; mt++)
                #pragma unroll
                for (int nt = 0; nt < 4; nt++){
                    int g = nt >> 1, s = nt & 1;
                    mma16816(acc[mt][nt], ah[mt], bh[g][s], bh[g][s + 2]);
                    mma16816(acc[mt][nt], ah[mt], bl[g][s], bl[g][s + 2]);
                    mma16816(acc[mt][nt], al[mt], bh[g][s], bh[g][s + 2]);
                }
        }
        if (++cur == 6) cur = 0;
        if (++nxt == 6) nxt = 0;
    }

    #pragma unroll
    for (int mt = 0; mt < 2; mt++){
        int m = m0 + wm * 32 + mt * 16 + (lane >> 2);
        #pragma unroll
        for (int nt = 0; nt < 4; nt++){
            int col = n0 + wn * 32 + nt * 8 + (lane & 3) * 2;
            if (col < N){
                size_t i0 = (size_t)m * N + col;
                size_t i1 = (size_t)(m + 8) * N + col;
                float2 v0 = make_float2(acc[mt][nt][0], acc[mt][nt][1]);
                float2 v1 = make_float2(acc[mt][nt][2], acc[mt][nt][3]);
                if (R){
                    float2 r0 = *(const float2*)(R + i0);
                    float2 r1 = *(const float2*)(R + i1);
                    v0.x += r0.x; v0.y += r0.y;
                    v1.x += r1.x; v1.y += r1.y;
                }
                *(float2*)(C + i0) = v0;
                *(float2*)(C + i1) = v1;
            }
        }
    }
}

// ---------------- embedding ----------------
__global__ void k_embed(const float* __restrict__ x, const float* __restrict__ W){
    int idx = blockIdx.x * blockDim.x + threadIdx.x;
    if (idx >= NTOK * DMODEL) return;
    int t = idx / DMODEL, d = idx % DMODEL;
    float x0 = x[t*3+0]; if (x0 == -100.f) x0 = 0.f;
    float x1 = x[t*3+1]; if (x1 == -100.f) x1 = 0.f;
    float x2 = x[t*3+2]; if (x2 == -100.f) x2 = 0.f;
    float acc = x0 * W[0*DMODEL + d] + x1 * W[1*DMODEL + d] + x2 * W[2*DMODEL + d];
    if (d < 510){
        int c = d / 170, r = d % 170;
        float xv = (c == 0) ? x0 : ((c == 1) ? x1 : x2);
        float pe;
        if (r < 85) pe = sinf(xv * exp2f((float)r));
        else        pe = cosf(xv * exp2f((float)(r - 85)));
        acc += pe;
    }
    g_h[idx] = acc;
}

// ---------------- rmsnorm (fp32 out optional) ----------------
__global__ void k_rmsnorm(const float* __restrict__ x, const float* __restrict__ w,
                          float* __restrict__ o, __nv_bfloat16* __restrict__ oh,
                          __nv_bfloat16* __restrict__ ol, int D){
    int t = blockIdx.x;
    const float* xr = x + (size_t)t * D;
    float ss = 0.f;
    for (int d = threadIdx.x; d < D; d += blockDim.x){
        float v = xr[d];
        ss += v * v;
    }
    ss = blockReduceSum(ss);
    float rs = rsqrtf(ss / (float)D + 1e-5f);
    for (int d = threadIdx.x; d < D; d += blockDim.x){
        float v = xr[d] * rs * w[d];
        if (o) o[(size_t)t * D + d] = v;
        __nv_bfloat16 hi = __float2bfloat16_rn(v);
        oh[(size_t)t * D + d] = hi;
        ol[(size_t)t * D + d] = __float2bfloat16_rn(v - __bfloat162float(hi));
    }
}

// ---------------- fused conv+silu and dt-cumsum ----------------
// blocks [0, NCONVB): conv. blocks [NCONVB, NCONVB+NDTB): dt, 2 (bc,h) pairs per block.
__global__ void k_convdt(const float* __restrict__ cw, const float* __restrict__ cb,
                         const float* __restrict__ dtb, const float* __restrict__ Alog){
    if (blockIdx.x < NCONVB){
        int idx = blockIdx.x * 256 + threadIdx.x;
        int t = idx / CONVDIM, ch = idx % CONVDIM;
        int l = t % SEQL;
        float acc = cb[ch];
        #pragma unroll
        for (int k = 0; k < DCONV; k++){
            int l2 = l + k - (DCONV - 1);
            if (l2 >= 0)
                acc += g_zx[(size_t)(t + l2 - l) * DINPROJ + DINNER + ch] * cw[ch*DCONV + k];
        }
        g_xc[idx] = siluf(acc);
    } else {
        __shared__ float sh[2][CHUNKL];
        int pr   = threadIdx.x >> 7;       // 0 or 1
        int i    = threadIdx.x & 127;
        int flat = (blockIdx.x - NCONVB) * 2 + pr;   // 0..511 = bc*16+h
        int bc = flat >> 4, h = flat & 15;
        int t  = bc * CHUNKL + i;
        float d = softplusf(g_zx[(size_t)t * DINPROJ + 2176 + h] + dtb[h]);
        float A = -expf(Alog[h]);
        sh[pr][i] = d * A;
        __syncthreads();
        #pragma unroll
        for (int off = 1; off < CHUNKL; off <<= 1){
            float v = (i >= off) ? sh[pr][i - off] : 0.f;
            __syncthreads();
            sh[pr][i] += v;
            __syncthreads();
        }
        g_dtv [t*NH + h] = d;
        g_acum[t*NH + h] = sh[pr][i];
        if (i == CHUNKL - 1) g_dec[flat] = expf(sh[pr][i]);
    }
}

// ---------------- scores ----------------
__global__ void k_scores(){
    extern __shared__ float smf[];
    float* Csh = smf;
    float* Bsh = smf + 128*65;
    int bc = blockIdx.x;
    int t0 = bc * CHUNKL;
    int tid = threadIdx.x;
    for (int idx = tid; idx < CHUNKL*DSTATE; idx += 256){
        int j = idx >> 6, n = idx & 63;
        Csh[j*65 + n] = g_xc[(size_t)(t0+j)*CONVDIM + DINNER + DSTATE + n];
        Bsh[j*65 + n] = g_xc[(size_t)(t0+j)*CONVDIM + DINNER + n];
    }
    __syncthreads();
    int i0 = (tid >> 4) * 8;
    int j0 = (tid & 15) * 8;
    float acc[8][8];
    #pragma unroll
    for (int r = 0; r < 8; r++)
        #pragma unroll
        for (int c = 0; c < 8; c++) acc[r][c] = 0.f;
    for (int n = 0; n < DSTATE; n++){
        float a[8], b[8];
        #pragma unroll
        for (int r = 0; r < 8; r++) a[r] = Csh[(i0+r)*65 + n];
        #pragma unroll
        for (int c = 0; c < 8; c++) b[c] = Bsh[(j0+c)*65 + n];
        #pragma unroll
        for (int r = 0; r < 8; r++)
            #pragma unroll
            for (int c = 0; c < 8; c++) acc[r][c] += a[r]*b[c];
    }
    float* out = g_sc + (size_t)bc * CHUNKL * CHUNKL;
    #pragma unroll
    for (int r = 0; r < 8; r++)
        #pragma unroll
        for (int c = 0; c < 8; c++)
            out[(i0+r)*CHUNKL + j0 + c] = acc[r][c];
}

// ---------------- fused y = y_diag + y_off + D*xh ----------------
__global__ void k_ssd_y(const float* __restrict__ Dp){
    extern __shared__ float smf[];
    float* xsh = smf;
    float* hsh = smf + CHUNKL*HD;
    __shared__ float ash[CHUNKL], dsh[CHUNKL];
    int bc = blockIdx.x >> 4, h = blockIdx.x & 15;
    int i  = threadIdx.x;
    int t0 = bc * CHUNKL;
    ash[i] = g_acum[(t0+i)*NH + h];
    dsh[i] = g_dtv [(t0+i)*NH + h];
    for (int idx = i; idx < CHUNKL*HD; idx += CHUNKL)
        xsh[idx] = g_xc[(size_t)(t0 + (idx >> 6))*CONVDIM + h*HD + (idx & 63)];
    const float* hbase = g_hs + (size_t)blockIdx.x * (HD*DSTATE);
    for (int idx = i; idx < HD*DSTATE; idx += CHUNKL) hsh[idx] = hbase[idx];
    __syncthreads();

    float ai = ash[i];
    float Dh = Dp[h];
    float acc[HD];
    #pragma unroll
    for (int p = 0; p < HD; p++) acc[p] = Dh * xsh[i*HD + p];

    int lo = 0, hi = i;
    while (lo < hi){
        int mid = (lo + hi) >> 1;
        if (ash[mid] < ai + AWIN) hi = mid; else lo = mid + 1;
    }
    const float* srow = g_sc + (size_t)bc * CHUNKL * CHUNKL + (size_t)i * CHUNKL;
    for (int j = lo; j <= i; j++){
        float m = srow[j] * expf(ai - ash[j]) * dsh[j];
        const float* xr = &xsh[j*HD];
        #pragma unroll
        for (int p = 0; p < HD; p++) acc[p] += m * xr[p];
    }

    if (ai > -AWIN){
        float ei = expf(ai);
        const float* crow = g_xc + (size_t)(t0+i)*CONVDIM + DINNER + DSTATE;
        #pragma unroll
        for (int h2 = 0; h2 < 2; h2++){
            float creg[32];
            #pragma unroll
            for (int n = 0; n < 32; n++) creg[n] = ei * crow[h2*32 + n];
            #pragma unroll 8
            for (int p = 0; p < HD; p++){
                const float4* hr = (const float4*)&hsh[p*DSTATE + h2*32];
                float a = 0.f;
                #pragma unroll
                for (int q = 0; q < 8; q++){
                    float4 v = hr[q];
                    a += creg[q*4+0]*v.x + creg[q*4+1]*v.y + creg[q*4+2]*v.z + creg[q*4+3]*v.w;
                }
                acc[p] += a;
            }
        }
    }

    float* yrow = g_y + (size_t)(t0+i)*DINNER + h*HD;
    #pragma unroll
    for (int p = 0; p < HD; p++) yrow[p] = acc[p];
}

// ---------------- chunk states ----------------
__global__ void k_state(){
    extern __shared__ float smf[];
    float* xsh = smf;
    float* bsh = smf + CHUNKL*HD;
    __shared__ float wsh[CHUNKL];
    __shared__ float ash_s[CHUNKL];
    int bc = blockIdx.x >> 4, h = blockIdx.x & 15;
    int t0 = bc * CHUNKL;
    int tid = threadIdx.x;
    for (int idx = tid; idx < CHUNKL*HD; idx += 256){
        int j = idx >> 6, q = idx & 63;
        xsh[idx] = g_xc[(size_t)(t0+j)*CONVDIM + h*HD + q];
        bsh[idx] = g_xc[(size_t)(t0+j)*CONVDIM + DINNER + q];
    }
    if (tid < CHUNKL) ash_s[tid] = g_acum[(t0 + tid)*NH + h];
    __syncthreads();
    if (tid < CHUNKL){
        float alast = ash_s[CHUNKL - 1];
        wsh[tid] = expf(alast - ash_s[tid]) * g_dtv[(t0 + tid)*NH + h];
    }
    __syncthreads();
    float alast = ash_s[CHUNKL - 1];
    int lo = 0, hi = CHUNKL - 1;
    while (lo < hi){
        int mid = (lo + hi) >> 1;
        if (ash_s[mid] < alast + AWIN) hi = mid; else lo = mid + 1;
    }
    int p  = tid & 63;
    int n0 = (tid >> 6) << 4;
    float acc[16];
    #pragma unroll
    for (int k = 0; k < 16; k++) acc[k] = 0.f;
    for (int j = lo; j < CHUNKL; j++){
        float xw = xsh[j*HD + p] * wsh[j];
        const float* br = &bsh[j*HD + n0];
        #pragma unroll
        for (int k = 0; k < 16; k++) acc[k] += xw * br[k];
    }
    float* so = g_S + (size_t)blockIdx.x * (HD*DSTATE);
    #pragma unroll
    for (int k = 0; k < 16; k++) so[p*DSTATE + n0 + k] = acc[k];
}

// ---------------- scan (parallel: 512 blocks) ----------------
__global__ void k_scan(){
    int bid = blockIdx.x;               // 0..511
    int bh  = bid >> 4;                 // (b,h) 0..31
    int grp = bid & 15;
    int b = bh >> 4, h = bh & 15;
    int idx = grp * 256 + threadIdx.x;  // 0..4095
    float st = 0.f;
    #pragma unroll 4
    for (int c = 0; c < NCH; c++){
        int bch = (b*NCH + c)*NH + h;
        size_t base = (size_t)bch * (HD*DSTATE);
        float dc = g_dec[bch];
        g_hs[base + idx] = st;
        st = st*dc + g_S[base + idx];
    }
}

// ---------------- gate ----------------
__global__ void k_gate(const float* __restrict__ gw){
    int t = blockIdx.x;
    int tid = threadIdx.x;
    float v[4]; float ss = 0.f;
    #pragma unroll
    for (int k = 0; k < 4; k++){
        int d = k*256 + tid;
        float z = g_zx[(size_t)t*DINPROJ + d];
        float vv = g_y[(size_t)t*DINNER + d] * siluf(z);
        v[k] = vv; ss += vv*vv;
    }
    ss = blockReduceSum(ss);
    float rs = rsqrtf(ss / (float)DINNER + 1e-5f);
    #pragma unroll
    for (int k = 0; k < 4; k++){
        int d = k*256 + tid;
        float o = v[k] * rs * gw[d];
        __nv_bfloat16 hi = __float2bfloat16_rn(o);
        g_ygh[(size_t)t*DINNER + d] = hi;
        g_ygl[(size_t)t*DINNER + d] = __float2bfloat16_rn(o - __bfloat162float(hi));
    }
}

// ---------------- head ----------------
__global__ void k_head(const float* __restrict__ hw, const float* __restrict__ hb,
                       float* __restrict__ out){
    int idx = blockIdx.x * blockDim.x + threadIdx.x;
    if (idx >= NTOK * KOUT) return;
    int t = idx / KOUT, n = idx % KOUT;
    float acc = hb[n];
    const float* xr = g_xn + (size_t)t * DMODEL;
    for (int k = 0; k < DMODEL; k++) acc += xr[k] * hw[k*KOUT + n];
    out[idx] = acc;
}

// ---------------- host ----------------
extern "C" void kernel_launch(void* const* d_in, const int* in_sizes, int n_in,
                              void* d_out, int out_size){
    const float* x      = (const float*)d_in[0];
    const float* Wembed = (const float*)d_in[1];
    const float* rmsw   = (const float*)d_in[2];
    const float* inw    = (const float*)d_in[3];
    const float* convw  = (const float*)d_in[4];
    const float* convb  = (const float*)d_in[5];
    const float* dtb    = (const float*)d_in[6];
    const float* alog   = (const float*)d_in[7];
    const float* dparam = (const float*)d_in[8];
    const float* gnw    = (const float*)d_in[9];
    const float* outw   = (const float*)d_in[10];
    const float* fnw    = (const float*)d_in[11];
    const float* hw     = (const float*)d_in[12];
    const float* hb     = (const float*)d_in[13];
    float* out = (float*)d_out;

    float *p_h, *p_xn, *p_zx;
    cudaGetSymbolAddress((void**)&p_h,  g_h);
    cudaGetSymbolAddress((void**)&p_xn, g_xn);
    cudaGetSymbolAddress((void**)&p_zx, g_zx);
    __nv_bfloat16 *p_xnh, *p_xnl, *p_ygh, *p_ygl;
    cudaGetSymbolAddress((void**)&p_xnh, g_xnh);
    cudaGetSymbolAddress((void**)&p_xnl, g_xnl);
    cudaGetSymbolAddress((void**)&p_ygh, g_ygh);
    cudaGetSymbolAddress((void**)&p_ygl, g_ygl);
    __nv_bfloat16 *p_wih, *p_wil, *p_woh, *p_wol;
    cudaGetSymbolAddress((void**)&p_wih, g_wih);
    cudaGetSymbolAddress((void**)&p_wil, g_wil);
    cudaGetSymbolAddress((void**)&p_woh, g_woh);
    cudaGetSymbolAddress((void**)&p_wol, g_wol);

    const int SCORES_SMEM = 2*128*65*4;
    const int STATE_SMEM  = 2*CHUNKL*HD*4;
    const int SSDY_SMEM   = (CHUNKL*HD + HD*DSTATE)*4;
    const int TG_SMEM     = 6*32768;
    cudaFuncSetAttribute(k_scores, cudaFuncAttributeMaxDynamicSharedMemorySize, SCORES_SMEM);
    cudaFuncSetAttribute(k_state,  cudaFuncAttributeMaxDynamicSharedMemorySize, STATE_SMEM);
    cudaFuncSetAttribute(k_ssd_y,  cudaFuncAttributeMaxDynamicSharedMemorySize, SSDY_SMEM);
    cudaFuncSetAttribute(k_tgemm,  cudaFuncAttributeMaxDynamicSharedMemorySize, TG_SMEM);

    k_prep<<<dim3(DMODEL/32, NPAD_IN/32, NLAYERS), dim3(32,8)>>>(
        inw, p_wih, p_wil, DMODEL, DINPROJ, NPAD_IN);
    k_embed<<<(NTOK*DMODEL + 255)/256, 256>>>(x, Wembed);

    for (int l = 0; l < NLAYERS; l++){
        k_rmsnorm<<<NTOK, 256>>>(p_h, rmsw + (size_t)l*DMODEL, nullptr, p_xnh, p_xnl, DMODEL);
        k_tgemm<<<dim3(NPAD_IN/128, NTOK/128), 512, TG_SMEM>>>(
            p_xnh, p_xnl,
            p_wih + (size_t)l*NPAD_IN*DMODEL, p_wil + (size_t)l*NPAD_IN*DMODEL,
            p_zx, nullptr, NTOK, DINPROJ, DMODEL);
        if (l == 0)
            k_prep<<<dim3(DINNER/32, DMODEL/32, NLAYERS), dim3(32,8)>>>(
                outw, p_woh, p_wol, DINNER, DMODEL, DMODEL);
        k_convdt<<<NCONVB + NDTB, 256>>>(convw + (size_t)l*CONVDIM*DCONV,
                                         convb + (size_t)l*CONVDIM,
                                         dtb + (size_t)l*NH, alog + (size_t)l*NH);
        k_scores<<<NBC, 256, SCORES_SMEM>>>();
        k_state<<<NBC*NH, 256, STATE_SMEM>>>();
        k_scan<<<BSZ*NH*16, 256>>>();
        k_ssd_y<<<NBC*NH, CHUNKL, SSDY_SMEM>>>(dparam + (size_t)l*NH);
        k_gate<<<NTOK, 256>>>(gnw + (size_t)l*DINNER);
        k_tgemm<<<dim3(DMODEL/128, NTOK/128), 512, TG_SMEM>>>(
            p_ygh, p_ygl,
            p_woh + (size_t)l*DMODEL*DINNER, p_wol + (size_t)l*DMODEL*DINNER,
            p_h, p_h, NTOK, DMODEL, DINNER);
    }

    k_rmsnorm<<<NTOK, 256>>>(p_h, fnw, p_xn, p_xnh, p_xnl, DMODEL);
    k_head<<<(NTOK*KOUT + 255)/256, 256>>>(hw, hb, out);
}

// round 10
// speedup vs baseline: 1.2721x; 1.0616x over previous
#include <cuda_runtime.h>
#include <cuda_bf16.h>
#include <math.h>
#include <stdint.h>

// ---------------- problem constants ----------------
#define BSZ     2
#define SEQL    2048
#define NTOK    (BSZ*SEQL)        // 4096
#define DMODEL  512
#define DINNER  1024
#define NH      16
#define HD      64
#define DSTATE  64
#define DCONV   4
#define CONVDIM 1152
#define DINPROJ 2192
#define NPAD_IN 2304
#define NLAYERS 12
#define CHUNKL  128
#define NCH     16
#define NBC     (BSZ*NCH)         // 32
#define KOUT    30
#define AWIN    35.0f
#define NCONVB  ((NTOK*CONVDIM)/256)
#define NDTB    ((NBC*NH)/2)

// ---------------- scratch ----------
__device__ float g_h   [NTOK*DMODEL];
__device__ float g_xn  [NTOK*DMODEL];
__device__ float g_zx  [NTOK*DINPROJ];
__device__ float g_xc  [NTOK*CONVDIM];
__device__ float g_dtv [NTOK*NH];
__device__ float g_acum[NTOK*NH];
__device__ float g_dec [NBC*NH];
__device__ float g_sc  [NBC*CHUNKL*CHUNKL];
__device__ float g_y   [NTOK*DINNER];
__device__ float g_S   [NBC*NH*HD*DSTATE];
__device__ float g_hs  [NBC*NH*HD*DSTATE];
// tiled+swizzled bf16 hi/lo operands: blocks of 8192 bf16 (16KB), layout identical to GEMM smem
__device__ __align__(128) __nv_bfloat16 g_ain [(NTOK/128)*(DMODEL/32)*8192];
__device__ __align__(128) __nv_bfloat16 g_aout[(NTOK/128)*(DINNER/32)*8192];
__device__ __align__(128) __nv_bfloat16 g_win [NLAYERS*(NPAD_IN/128)*(DMODEL/32)*8192];
__device__ __align__(128) __nv_bfloat16 g_wout[NLAYERS*(DMODEL/128)*(DINNER/32)*8192];

// ---------------- helpers ----------------
__device__ __forceinline__ uint32_t s2u(const void* p){
    uint32_t a;
    asm("{ .reg .u64 t; cvta.to.shared.u64 t, %1; cvt.u32.u64 %0, t; }" : "=r"(a) : "l"(p));
    return a;
}
__device__ __forceinline__ void ldsm4(uint32_t* r, uint32_t a){
    asm volatile("ldmatrix.sync.aligned.m8n8.x4.shared.b16 {%0,%1,%2,%3}, [%4];"
        : "=r"(r[0]), "=r"(r[1]), "=r"(r[2]), "=r"(r[3]) : "r"(a));
}
__device__ __forceinline__ void mma16816(float* d, const uint32_t* a, uint32_t b0, uint32_t b1){
    asm volatile("mma.sync.aligned.m16n8k16.row.col.f32.bf16.bf16.f32 "
        "{%0,%1,%2,%3}, {%4,%5,%6,%7}, {%8,%9}, {%0,%1,%2,%3};"
        : "+f"(d[0]), "+f"(d[1]), "+f"(d[2]), "+f"(d[3])
        : "r"(a[0]), "r"(a[1]), "r"(a[2]), "r"(a[3]), "r"(b0), "r"(b1));
}
__device__ __forceinline__ void mbar_init(uint32_t m, uint32_t cnt){
    asm volatile("mbarrier.init.shared.b64 [%0], %1;" :: "r"(m), "r"(cnt) : "memory");
}
__device__ __forceinline__ void mbar_expect(uint32_t m, uint32_t bytes){
    asm volatile("mbarrier.arrive.expect_tx.shared.b64 _, [%0], %1;" :: "r"(m), "r"(bytes) : "memory");
}
__device__ __forceinline__ void mbar_wait(uint32_t m, uint32_t phase){
    asm volatile(
        "{\n\t.reg .pred P;\n\t"
        "WL_%=:\n\t"
        "mbarrier.try_wait.parity.acquire.cta.shared::cta.b64 P, [%0], %1, 0x989680;\n\t"
        "@P bra.uni WD_%=;\n\t"
        "bra.uni WL_%=;\n\t"
        "WD_%=:\n\t}"
        :: "r"(m), "r"(phase) : "memory");
}
__device__ __forceinline__ void bulkcp16k(uint32_t sdst, const void* gsrc, uint32_t mbar){
    uint64_t ga;
    asm("cvta.to.global.u64 %0, %1;" : "=l"(ga) : "l"(gsrc));
    asm volatile("cp.async.bulk.shared::cluster.global.mbarrier::complete_tx::bytes [%0], [%1], %2, [%3];"
        :: "r"(sdst), "l"(ga), "r"(16384u), "r"(mbar) : "memory");
}
__device__ __forceinline__ void fence_async(){
    asm volatile("fence.proxy.async.shared::cta;" ::: "memory");
}

__device__ __forceinline__ float softplusf(float x){
    return (x > 20.f) ? x : log1pf(expf(x));
}
__device__ __forceinline__ float siluf(float x){
    return x / (1.f + expf(-x));
}
__device__ __forceinline__ float blockReduceSum(float v){
    __shared__ float sh[32];
    #pragma unroll
    for (int o = 16; o; o >>= 1) v += __shfl_xor_sync(0xffffffffu, v, o);
    int w = threadIdx.x >> 5;
    if ((threadIdx.x & 31) == 0) sh[w] = v;
    __syncthreads();
    int nw = blockDim.x >> 5;
    float r = (threadIdx.x < nw) ? sh[threadIdx.x] : 0.f;
    if (w == 0){
        #pragma unroll
        for (int o = 16; o; o >>= 1) r += __shfl_xor_sync(0xffffffffu, r, o);
        if (threadIdx.x == 0) sh[0] = r;
    }
    __syncthreads();
    return sh[0];
}

// element index inside the tiled layout: tile block 8192 elems, row r(0..127),
// k-chunk column c(0..31), part 0=hi/1=lo. Matches GEMM smem swizzle exactly.
__device__ __forceinline__ size_t tidx(int tile, int nkc, int kc, int r, int c, int part){
    int s = c >> 3, e = c & 7;
    return (((size_t)tile * nkc + kc) << 13) + (size_t)(r * 64) +
           (size_t)((((part * 4 + s) ^ (r & 7))) << 3) + e;
}

// ---------------- weight prep: transpose + split + tile ----------------
__global__ void k_prep(const float* __restrict__ W, __nv_bfloat16* __restrict__ Wt,
                       int K, int N, int Npad){
    int l = blockIdx.z;
    W  += (size_t)l * K * N;
    Wt += (size_t)l * (Npad >> 7) * (K >> 5) * 8192;
    __shared__ float t[32][33];
    int k0 = blockIdx.x * 32, n0 = blockIdx.y * 32;
    int tx = threadIdx.x, ty = threadIdx.y;
    int nkc = K >> 5;
    for (int i = ty; i < 32; i += 8){
        float v = 0.f;
        if (n0 + tx < N) v = W[(size_t)(k0 + i) * N + n0 + tx];
        t[i][tx] = v;
    }
    __syncthreads();
    for (int i = ty; i < 32; i += 8){
        float v = t[tx][i];                 // W[k0+tx][n0+i]
        __nv_bfloat16 hi = __float2bfloat16_rn(v);
        float lo = v - __bfloat162float(hi);
        int n = n0 + i, k = k0 + tx;
        int tile = n >> 7, r = n & 127, kc = k >> 5, c = k & 31;
        Wt[tidx(tile, nkc, kc, r, c, 0)] = hi;
        Wt[tidx(tile, nkc, kc, r, c, 1)] = __float2bfloat16_rn(lo);
    }
}

// ---------------- GEMM: bulk-copy pipeline, 512 thr, k-chunk 32, 6 stages ---
// At/Bt: tiled blocks (16KB) in gmem. smem stage (32KB): A at +0, B at +16384.
__global__ void __launch_bounds__(512, 1)
k_tgemm(const __nv_bfloat16* __restrict__ At, const __nv_bfloat16* __restrict__ Bt,
        float* __restrict__ C, const float* __restrict__ R,
        int M, int N, int K)
{
    extern __shared__ char smc[];
    __shared__ __align__(8) uint64_t mbarr[6];
    uint32_t sb  = s2u(smc);
    uint32_t mb0 = s2u(mbarr);
    int tid  = threadIdx.x;
    int lane = tid & 31, w = tid >> 5;
    int wm = w & 3, wn = w >> 2;
    int m0 = blockIdx.y * 128, n0 = blockIdx.x * 128;
    int nkc = K >> 5;
    const __nv_bfloat16* gA = At + (((size_t)blockIdx.y * nkc) << 13);
    const __nv_bfloat16* gB = Bt + (((size_t)blockIdx.x * nkc) << 13);

    if (tid == 0){
        #pragma unroll
        for (int s = 0; s < 6; s++) mbar_init(mb0 + s * 8, 1);
    }
    __syncthreads();
    if (tid == 0){
        #pragma unroll
        for (int s = 0; s < 5; s++){
            if (s < nkc){
                mbar_expect(mb0 + s * 8, 32768u);
                bulkcp16k(sb + s * 32768u,          gA + ((size_t)s << 13), mb0 + s * 8);
                bulkcp16k(sb + s * 32768u + 16384u, gB + ((size_t)s << 13), mb0 + s * 8);
            }
        }
    }

    float acc[2][4][4];
    #pragma unroll
    for (int mt = 0; mt < 2; mt++)
        #pragma unroll
        for (int nt = 0; nt < 4; nt++)
            #pragma unroll
            for (int e = 0; e < 4; e++) acc[mt][nt][e] = 0.f;

    uint32_t aoff = sb + (uint32_t)((wm * 32 + (lane & 15)) * 128);
    uint32_t boff = sb + 16384u + (uint32_t)((wn * 32 + (lane & 15)) * 128);
    uint32_t ct[2][2];
    #pragma unroll
    for (int part = 0; part < 2; part++)
        #pragma unroll
        for (int kh = 0; kh < 2; kh++)
            ct[part][kh] = (uint32_t)((((part * 4 + 2 * kh + (lane >> 4))) ^ (lane & 7)) * 16);

    int cur = 0, nxt = 5;
    uint32_t phase = 0;
    for (int it = 0; it < nkc; it++){
        mbar_wait(mb0 + (uint32_t)cur * 8, phase);
        __syncthreads();
        if (tid == 0 && it + 5 < nkc){
            fence_async();
            mbar_expect(mb0 + (uint32_t)nxt * 8, 32768u);
            bulkcp16k(sb + (uint32_t)nxt * 32768u,          gA + ((size_t)(it + 5) << 13), mb0 + (uint32_t)nxt * 8);
            bulkcp16k(sb + (uint32_t)nxt * 32768u + 16384u, gB + ((size_t)(it + 5) << 13), mb0 + (uint32_t)nxt * 8);
        }

        uint32_t bufo = (uint32_t)cur * 32768u;
        #pragma unroll
        for (int kh = 0; kh < 2; kh++){
            uint32_t ah[2][4], al[2][4], bh[2][4], bl[2][4];
            #pragma unroll
            for (int mt = 0; mt < 2; mt++){
                uint32_t base = aoff + bufo + (uint32_t)(mt * 2048);
                ldsm4(ah[mt], base + ct[0][kh]);
                ldsm4(al[mt], base + ct[1][kh]);
            }
            #pragma unroll
            for (int g = 0; g < 2; g++){
                uint32_t base = boff + bufo + (uint32_t)(g * 2048);
                ldsm4(bh[g], base + ct[0][kh]);
                ldsm4(bl[g], base + ct[1][kh]);
            }
            #pragma unroll
            for (int mt = 0; mt < 2; mt++)
                #pragma unroll
                for (int nt = 0; nt < 4; nt++){
                    int g = nt >> 1, s = nt & 1;
                    mma16816(acc[mt][nt], ah[mt], bh[g][s], bh[g][s + 2]);
                    mma16816(acc[mt][nt], ah[mt], bl[g][s], bl[g][s + 2]);
                    mma16816(acc[mt][nt], al[mt], bh[g][s], bh[g][s + 2]);
                }
        }
        if (++cur == 6){ cur = 0; phase ^= 1; }
        if (++nxt == 6) nxt = 0;
    }

    #pragma unroll
    for (int mt = 0; mt < 2; mt++){
        int m = m0 + wm * 32 + mt * 16 + (lane >> 2);
        #pragma unroll
        for (int nt = 0; nt < 4; nt++){
            int col = n0 + wn * 32 + nt * 8 + (lane & 3) * 2;
            if (col < N){
                size_t i0 = (size_t)m * N + col;
                size_t i1 = (size_t)(m + 8) * N + col;
                float2 v0 = make_float2(acc[mt][nt][0], acc[mt][nt][1]);
                float2 v1 = make_float2(acc[mt][nt][2], acc[mt][nt][3]);
                if (R){
                    float2 r0 = *(const float2*)(R + i0);
                    float2 r1 = *(const float2*)(R + i1);
                    v0.x += r0.x; v0.y += r0.y;
                    v1.x += r1.x; v1.y += r1.y;
                }
                *(float2*)(C + i0) = v0;
                *(float2*)(C + i1) = v1;
            }
        }
    }
}

// ---------------- embedding ----------------
__global__ void k_embed(const float* __restrict__ x, const float* __restrict__ W){
    int idx = blockIdx.x * blockDim.x + threadIdx.x;
    if (idx >= NTOK * DMODEL) return;
    int t = idx / DMODEL, d = idx % DMODEL;
    float x0 = x[t*3+0]; if (x0 == -100.f) x0 = 0.f;
    float x1 = x[t*3+1]; if (x1 == -100.f) x1 = 0.f;
    float x2 = x[t*3+2]; if (x2 == -100.f) x2 = 0.f;
    float acc = x0 * W[0*DMODEL + d] + x1 * W[1*DMODEL + d] + x2 * W[2*DMODEL + d];
    if (d < 510){
        int c = d / 170, r = d % 170;
        float xv = (c == 0) ? x0 : ((c == 1) ? x1 : x2);
        float pe;
        if (r < 85) pe = sinf(xv * exp2f((float)r));
        else        pe = cosf(xv * exp2f((float)(r - 85)));
        acc += pe;
    }
    g_h[idx] = acc;
}

// ---------------- rmsnorm: optional fp32 out + tiled bf16 hi/lo out ---------
__global__ void k_rmsnorm(const float* __restrict__ x, const float* __restrict__ w,
                          float* __restrict__ o, __nv_bfloat16* __restrict__ At, int D){
    int t = blockIdx.x;
    const float* xr = x + (size_t)t * D;
    float ss = 0.f;
    for (int d = threadIdx.x; d < D; d += blockDim.x){
        float v = xr[d];
        ss += v * v;
    }
    ss = blockReduceSum(ss);
    float rs = rsqrtf(ss / (float)D + 1e-5f);
    int tile = t >> 7, r = t & 127, nkc = D >> 5;
    for (int d = threadIdx.x; d < D; d += blockDim.x){
        float v = xr[d] * rs * w[d];
        if (o) o[(size_t)t * D + d] = v;
        __nv_bfloat16 hi = __float2bfloat16_rn(v);
        int kc = d >> 5, c = d & 31;
        At[tidx(tile, nkc, kc, r, c, 0)] = hi;
        At[tidx(tile, nkc, kc, r, c, 1)] = __float2bfloat16_rn(v - __bfloat162float(hi));
    }
}

// ---------------- fused conv+silu and dt-cumsum ----------------
__global__ void k_convdt(const float* __restrict__ cw, const float* __restrict__ cb,
                         const float* __restrict__ dtb, const float* __restrict__ Alog){
    if (blockIdx.x < NCONVB){
        int idx = blockIdx.x * 256 + threadIdx.x;
        int t = idx / CONVDIM, ch = idx % CONVDIM;
        int l = t % SEQL;
        float acc = cb[ch];
        #pragma unroll
        for (int k = 0; k < DCONV; k++){
            int l2 = l + k - (DCONV - 1);
            if (l2 >= 0)
                acc += g_zx[(size_t)(t + l2 - l) * DINPROJ + DINNER + ch] * cw[ch*DCONV + k];
        }
        g_xc[idx] = siluf(acc);
    } else {
        __shared__ float sh[2][CHUNKL];
        int pr   = threadIdx.x >> 7;
        int i    = threadIdx.x & 127;
        int flat = (blockIdx.x - NCONVB) * 2 + pr;
        int bc = flat >> 4, h = flat & 15;
        int t  = bc * CHUNKL + i;
        float d = softplusf(g_zx[(size_t)t * DINPROJ + 2176 + h] + dtb[h]);
        float A = -expf(Alog[h]);
        sh[pr][i] = d * A;
        __syncthreads();
        #pragma unroll
        for (int off = 1; off < CHUNKL; off <<= 1){
            float v = (i >= off) ? sh[pr][i - off] : 0.f;
            __syncthreads();
            sh[pr][i] += v;
            __syncthreads();
        }
        g_dtv [t*NH + h] = d;
        g_acum[t*NH + h] = sh[pr][i];
        if (i == CHUNKL - 1) g_dec[flat] = expf(sh[pr][i]);
    }
}

// ---------------- scores ----------------
__global__ void k_scores(){
    extern __shared__ float smf[];
    float* Csh = smf;
    float* Bsh = smf + 128*65;
    int bc = blockIdx.x;
    int t0 = bc * CHUNKL;
    int tid = threadIdx.x;
    for (int idx = tid; idx < CHUNKL*DSTATE; idx += 256){
        int j = idx >> 6, n = idx & 63;
        Csh[j*65 + n] = g_xc[(size_t)(t0+j)*CONVDIM + DINNER + DSTATE + n];
        Bsh[j*65 + n] = g_xc[(size_t)(t0+j)*CONVDIM + DINNER + n];
    }
    __syncthreads();
    int i0 = (tid >> 4) * 8;
    int j0 = (tid & 15) * 8;
    float acc[8][8];
    #pragma unroll
    for (int r = 0; r < 8; r++)
        #pragma unroll
        for (int c = 0; c < 8; c++) acc[r][c] = 0.f;
    for (int n = 0; n < DSTATE; n++){
        float a[8], b[8];
        #pragma unroll
        for (int r = 0; r < 8; r++) a[r] = Csh[(i0+r)*65 + n];
        #pragma unroll
        for (int c = 0; c < 8; c++) b[c] = Bsh[(j0+c)*65 + n];
        #pragma unroll
        for (int r = 0; r < 8; r++)
            #pragma unroll
            for (int c = 0; c < 8; c++) acc[r][c] += a[r]*b[c];
    }
    float* out = g_sc + (size_t)bc * CHUNKL * CHUNKL;
    #pragma unroll
    for (int r = 0; r < 8; r++)
        #pragma unroll
        for (int c = 0; c < 8; c++)
            out[(i0+r)*CHUNKL + j0 + c] = acc[r][c];
}

// ---------------- fused y = y_diag + y_off + D*xh ----------------
__global__ void k_ssd_y(const float* __restrict__ Dp){
    extern __shared__ float smf[];
    float* xsh = smf;
    float* hsh = smf + CHUNKL*HD;
    __shared__ float ash[CHUNKL], dsh[CHUNKL];
    int bc = blockIdx.x >> 4, h = blockIdx.x & 15;
    int i  = threadIdx.x;
    int t0 = bc * CHUNKL;
    ash[i] = g_acum[(t0+i)*NH + h];
    dsh[i] = g_dtv [(t0+i)*NH + h];
    for (int idx = i; idx < CHUNKL*HD; idx += CHUNKL)
        xsh[idx] = g_xc[(size_t)(t0 + (idx >> 6))*CONVDIM + h*HD + (idx & 63)];
    const float* hbase = g_hs + (size_t)blockIdx.x * (HD*DSTATE);
    for (int idx = i; idx < HD*DSTATE; idx += CHUNKL) hsh[idx] = hbase[idx];
    __syncthreads();

    float ai = ash[i];
    float Dh = Dp[h];
    float acc[HD];
    #pragma unroll
    for (int p = 0; p < HD; p++) acc[p] = Dh * xsh[i*HD + p];

    int lo = 0, hi = i;
    while (lo < hi){
        int mid = (lo + hi) >> 1;
        if (ash[mid] < ai + AWIN) hi = mid; else lo = mid + 1;
    }
    const float* srow = g_sc + (size_t)bc * CHUNKL * CHUNKL + (size_t)i * CHUNKL;
    for (int j = lo; j <= i; j++){
        float m = srow[j] * expf(ai - ash[j]) * dsh[j];
        const float* xr = &xsh[j*HD];
        #pragma unroll
        for (int p = 0; p < HD; p++) acc[p] += m * xr[p];
    }

    if (ai > -AWIN){
        float ei = expf(ai);
        const float* crow = g_xc + (size_t)(t0+i)*CONVDIM + DINNER + DSTATE;
        #pragma unroll
        for (int h2 = 0; h2 < 2; h2++){
            float creg[32];
            #pragma unroll
            for (int n = 0; n < 32; n++) creg[n] = ei * crow[h2*32 + n];
            #pragma unroll 8
            for (int p = 0; p < HD; p++){
                const float4* hr = (const float4*)&hsh[p*DSTATE + h2*32];
                float a = 0.f;
                #pragma unroll
                for (int q = 0; q < 8; q++){
                    float4 v = hr[q];
                    a += creg[q*4+0]*v.x + creg[q*4+1]*v.y + creg[q*4+2]*v.z + creg[q*4+3]*v.w;
                }
                acc[p] += a;
            }
        }
    }

    float* yrow = g_y + (size_t)(t0+i)*DINNER + h*HD;
    #pragma unroll
    for (int p = 0; p < HD; p++) yrow[p] = acc[p];
}

// ---------------- chunk states ----------------
__global__ void k_state(){
    extern __shared__ float smf[];
    float* xsh = smf;
    float* bsh = smf + CHUNKL*HD;
    __shared__ float wsh[CHUNKL];
    __shared__ float ash_s[CHUNKL];
    int bc = blockIdx.x >> 4, h = blockIdx.x & 15;
    int t0 = bc * CHUNKL;
    int tid = threadIdx.x;
    for (int idx = tid; idx < CHUNKL*HD; idx += 256){
        int j = idx >> 6, q = idx & 63;
        xsh[idx] = g_xc[(size_t)(t0+j)*CONVDIM + h*HD + q];
        bsh[idx] = g_xc[(size_t)(t0+j)*CONVDIM + DINNER + q];
    }
    if (tid < CHUNKL) ash_s[tid] = g_acum[(t0 + tid)*NH + h];
    __syncthreads();
    if (tid < CHUNKL){
        float alast = ash_s[CHUNKL - 1];
        wsh[tid] = expf(alast - ash_s[tid]) * g_dtv[(t0 + tid)*NH + h];
    }
    __syncthreads();
    float alast = ash_s[CHUNKL - 1];
    int lo = 0, hi = CHUNKL - 1;
    while (lo < hi){
        int mid = (lo + hi) >> 1;
        if (ash_s[mid] < alast + AWIN) hi = mid; else lo = mid + 1;
    }
    int p  = tid & 63;
    int n0 = (tid >> 6) << 4;
    float acc[16];
    #pragma unroll
    for (int k = 0; k < 16; k++) acc[k] = 0.f;
    for (int j = lo; j < CHUNKL; j++){
        float xw = xsh[j*HD + p] * wsh[j];
        const float* br = &bsh[j*HD + n0];
        #pragma unroll
        for (int k = 0; k < 16; k++) acc[k] += xw * br[k];
    }
    float* so = g_S + (size_t)blockIdx.x * (HD*DSTATE);
    #pragma unroll
    for (int k = 0; k < 16; k++) so[p*DSTATE + n0 + k] = acc[k];
}

// ---------------- scan (parallel: 512 blocks) ----------------
__global__ void k_scan(){
    int bid = blockIdx.x;
    int bh  = bid >> 4;
    int grp = bid & 15;
    int b = bh >> 4, h = bh & 15;
    int idx = grp * 256 + threadIdx.x;
    float st = 0.f;
    #pragma unroll 4
    for (int c = 0; c < NCH; c++){
        int bch = (b*NCH + c)*NH + h;
        size_t base = (size_t)bch * (HD*DSTATE);
        float dc = g_dec[bch];
        g_hs[base + idx] = st;
        st = st*dc + g_S[base + idx];
    }
}

// ---------------- gate: rmsnorm(y*silu(z))*gw -> tiled bf16 hi/lo -----------
__global__ void k_gate(const float* __restrict__ gw, __nv_bfloat16* __restrict__ At){
    int t = blockIdx.x;
    int tid = threadIdx.x;
    float v[4]; float ss = 0.f;
    #pragma unroll
    for (int k = 0; k < 4; k++){
        int d = k*256 + tid;
        float z = g_zx[(size_t)t*DINPROJ + d];
        float vv = g_y[(size_t)t*DINNER + d] * siluf(z);
        v[k] = vv; ss += vv*vv;
    }
    ss = blockReduceSum(ss);
    float rs = rsqrtf(ss / (float)DINNER + 1e-5f);
    int tile = t >> 7, r = t & 127;
    #pragma unroll
    for (int k = 0; k < 4; k++){
        int d = k*256 + tid;
        float o = v[k] * rs * gw[d];
        __nv_bfloat16 hi = __float2bfloat16_rn(o);
        int kc = d >> 5, c = d & 31;
        At[tidx(tile, DINNER >> 5, kc, r, c, 0)] = hi;
        At[tidx(tile, DINNER >> 5, kc, r, c, 1)] = __float2bfloat16_rn(o - __bfloat162float(hi));
    }
}

// ---------------- head ----------------
__global__ void k_head(const float* __restrict__ hw, const float* __restrict__ hb,
                       float* __restrict__ out){
    int idx = blockIdx.x * blockDim.x + threadIdx.x;
    if (idx >= NTOK * KOUT) return;
    int t = idx / KOUT, n = idx % KOUT;
    float acc = hb[n];
    const float* xr = g_xn + (size_t)t * DMODEL;
    for (int k = 0; k < DMODEL; k++) acc += xr[k] * hw[k*KOUT + n];
    out[idx] = acc;
}

// ---------------- host ----------------
extern "C" void kernel_launch(void* const* d_in, const int* in_sizes, int n_in,
                              void* d_out, int out_size){
    const float* x      = (const float*)d_in[0];
    const float* Wembed = (const float*)d_in[1];
    const float* rmsw   = (const float*)d_in[2];
    const float* inw    = (const float*)d_in[3];
    const float* convw  = (const float*)d_in[4];
    const float* convb  = (const float*)d_in[5];
    const float* dtb    = (const float*)d_in[6];
    const float* alog   = (const float*)d_in[7];
    const float* dparam = (const float*)d_in[8];
    const float* gnw    = (const float*)d_in[9];
    const float* outw   = (const float*)d_in[10];
    const float* fnw    = (const float*)d_in[11];
    const float* hw     = (const float*)d_in[12];
    const float* hb     = (const float*)d_in[13];
    float* out = (float*)d_out;

    float *p_h, *p_xn, *p_zx;
    cudaGetSymbolAddress((void**)&p_h,  g_h);
    cudaGetSymbolAddress((void**)&p_xn, g_xn);
    cudaGetSymbolAddress((void**)&p_zx, g_zx);
    __nv_bfloat16 *p_ain, *p_aout, *p_win, *p_wout;
    cudaGetSymbolAddress((void**)&p_ain,  g_ain);
    cudaGetSymbolAddress((void**)&p_aout, g_aout);
    cudaGetSymbolAddress((void**)&p_win,  g_win);
    cudaGetSymbolAddress((void**)&p_wout, g_wout);

    const int SCORES_SMEM = 2*128*65*4;
    const int STATE_SMEM  = 2*CHUNKL*HD*4;
    const int SSDY_SMEM   = (CHUNKL*HD + HD*DSTATE)*4;
    const int TG_SMEM     = 6*32768;
    cudaFuncSetAttribute(k_scores, cudaFuncAttributeMaxDynamicSharedMemorySize, SCORES_SMEM);
    cudaFuncSetAttribute(k_state,  cudaFuncAttributeMaxDynamicSharedMemorySize, STATE_SMEM);
    cudaFuncSetAttribute(k_ssd_y,  cudaFuncAttributeMaxDynamicSharedMemorySize, SSDY_SMEM);
    cudaFuncSetAttribute(k_tgemm,  cudaFuncAttributeMaxDynamicSharedMemorySize, TG_SMEM);

    const size_t WIN_L  = (size_t)(NPAD_IN/128)*(DMODEL/32)*8192;
    const size_t WOUT_L = (size_t)(DMODEL/128)*(DINNER/32)*8192;

    k_prep<<<dim3(DMODEL/32, NPAD_IN/32, NLAYERS), dim3(32,8)>>>(
        inw, p_win, DMODEL, DINPROJ, NPAD_IN);
    k_embed<<<(NTOK*DMODEL + 255)/256, 256>>>(x, Wembed);

    for (int l = 0; l < NLAYERS; l++){
        k_rmsnorm<<<NTOK, 256>>>(p_h, rmsw + (size_t)l*DMODEL, nullptr, p_ain, DMODEL);
        k_tgemm<<<dim3(NPAD_IN/128, NTOK/128), 512, TG_SMEM>>>(
            p_ain, p_win + (size_t)l*WIN_L, p_zx, nullptr, NTOK, DINPROJ, DMODEL);
        if (l == 0)
            k_prep<<<dim3(DINNER/32, DMODEL/32, NLAYERS), dim3(32,8)>>>(
                outw, p_wout, DINNER, DMODEL, DMODEL);
        k_convdt<<<NCONVB + NDTB, 256>>>(convw + (size_t)l*CONVDIM*DCONV,
                                         convb + (size_t)l*CONVDIM,
                                         dtb + (size_t)l*NH, alog + (size_t)l*NH);
        k_scores<<<NBC, 256, SCORES_SMEM>>>();
        k_state<<<NBC*NH, 256, STATE_SMEM>>>();
        k_scan<<<BSZ*NH*16, 256>>>();
        k_ssd_y<<<NBC*NH, CHUNKL, SSDY_SMEM>>>(dparam + (size_t)l*NH);
        k_gate<<<NTOK, 256>>>(gnw + (size_t)l*DINNER, p_aout);
        k_tgemm<<<dim3(DMODEL/128, NTOK/128), 512, TG_SMEM>>>(
            p_aout, p_wout + (size_t)l*WOUT_L, p_h, p_h, NTOK, DMODEL, DINNER);
    }

    k_rmsnorm<<<NTOK, 256>>>(p_h, fnw, p_xn, p_ain, DMODEL);
    k_head<<<(NTOK*KOUT + 255)/256, 256>>>(hw, hb, out);
}

// round 11
// speedup vs baseline: 1.3247x; 1.0413x over previous
#include <cuda_runtime.h>
#include <cuda_bf16.h>
#include <math.h>
#include <stdint.h>

// ---------------- problem constants ----------------
#define BSZ     2
#define SEQL    2048
#define NTOK    (BSZ*SEQL)        // 4096
#define DMODEL  512
#define DINNER  1024
#define NH      16
#define HD      64
#define DSTATE  64
#define DCONV   4
#define CONVDIM 1152
#define DINPROJ 2192
#define NPAD_IN 2304
#define NLAYERS 12
#define CHUNKL  128
#define NCH     16
#define NBC     (BSZ*NCH)         // 32
#define KOUT    30
#define AWIN    35.0f
#define NCONVB  ((NTOK*CONVDIM)/256)
#define NDTB    ((NBC*NH)/2)

// ---------------- scratch ----------
__device__ float g_h   [NTOK*DMODEL];
__device__ float g_xn  [NTOK*DMODEL];
__device__ float g_zx  [NTOK*DINPROJ];
__device__ float g_xc  [NTOK*CONVDIM];
__device__ float g_dtv [NTOK*NH];
__device__ float g_acum[NTOK*NH];
__device__ float g_dec [NBC*NH];
__device__ float g_sc  [NBC*CHUNKL*CHUNKL];
__device__ float g_y   [NTOK*DINNER];
__device__ float g_S   [NBC*NH*HD*DSTATE];
__device__ float g_hs  [NBC*NH*HD*DSTATE];
// tiled+swizzled bf16 hi/lo operands: blocks of 8192 bf16 (16KB), layout identical to GEMM smem
__device__ __align__(128) __nv_bfloat16 g_ain [(NTOK/128)*(DMODEL/32)*8192];
__device__ __align__(128) __nv_bfloat16 g_aout[(NTOK/128)*(DINNER/32)*8192];
__device__ __align__(128) __nv_bfloat16 g_win [NLAYERS*(NPAD_IN/128)*(DMODEL/32)*8192];
__device__ __align__(128) __nv_bfloat16 g_wout[NLAYERS*(DMODEL/128)*(DINNER/32)*8192];

// ---------------- helpers ----------------
__device__ __forceinline__ uint32_t s2u(const void* p){
    uint32_t a;
    asm("{ .reg .u64 t; cvta.to.shared.u64 t, %1; cvt.u32.u64 %0, t; }" : "=r"(a) : "l"(p));
    return a;
}
__device__ __forceinline__ void ldsm4(uint32_t* r, uint32_t a){
    asm volatile("ldmatrix.sync.aligned.m8n8.x4.shared.b16 {%0,%1,%2,%3}, [%4];"
        : "=r"(r[0]), "=r"(r[1]), "=r"(r[2]), "=r"(r[3]) : "r"(a));
}
__device__ __forceinline__ void mma16816(float* d, const uint32_t* a, uint32_t b0, uint32_t b1){
    asm volatile("mma.sync.aligned.m16n8k16.row.col.f32.bf16.bf16.f32 "
        "{%0,%1,%2,%3}, {%4,%5,%6,%7}, {%8,%9}, {%0,%1,%2,%3};"
        : "+f"(d[0]), "+f"(d[1]), "+f"(d[2]), "+f"(d[3])
        : "r"(a[0]), "r"(a[1]), "r"(a[2]), "r"(a[3]), "r"(b0), "r"(b1));
}
__device__ __forceinline__ void mbar_init(uint32_t m, uint32_t cnt){
    asm volatile("mbarrier.init.shared.b64 [%0], %1;" :: "r"(m), "r"(cnt) : "memory");
}
__device__ __forceinline__ void mbar_expect(uint32_t m, uint32_t bytes){
    asm volatile("mbarrier.arrive.expect_tx.shared.b64 _, [%0], %1;" :: "r"(m), "r"(bytes) : "memory");
}
__device__ __forceinline__ void mbar_wait(uint32_t m, uint32_t phase){
    asm volatile(
        "{\n\t.reg .pred P;\n\t"
        "WL_%=:\n\t"
        "mbarrier.try_wait.parity.acquire.cta.shared::cta.b64 P, [%0], %1, 0x989680;\n\t"
        "@P bra.uni WD_%=;\n\t"
        "bra.uni WL_%=;\n\t"
        "WD_%=:\n\t}"
        :: "r"(m), "r"(phase) : "memory");
}
__device__ __forceinline__ void bulkcp32k(uint32_t sdst, const void* gsrc, uint32_t mbar){
    uint64_t ga;
    asm("cvta.to.global.u64 %0, %1;" : "=l"(ga) : "l"(gsrc));
    asm volatile("cp.async.bulk.shared::cluster.global.mbarrier::complete_tx::bytes [%0], [%1], %2, [%3];"
        :: "r"(sdst), "l"(ga), "r"(32768u), "r"(mbar) : "memory");
}
__device__ __forceinline__ void fence_async(){
    asm volatile("fence.proxy.async.shared::cta;" ::: "memory");
}

__device__ __forceinline__ float softplusf(float x){
    return (x > 20.f) ? x : log1pf(expf(x));
}
__device__ __forceinline__ float siluf(float x){
    return x / (1.f + expf(-x));
}
__device__ __forceinline__ float blockReduceSum(float v){
    __shared__ float sh[32];
    #pragma unroll
    for (int o = 16; o; o >>= 1) v += __shfl_xor_sync(0xffffffffu, v, o);
    int w = threadIdx.x >> 5;
    if ((threadIdx.x & 31) == 0) sh[w] = v;
    __syncthreads();
    int nw = blockDim.x >> 5;
    float r = (threadIdx.x < nw) ? sh[threadIdx.x] : 0.f;
    if (w == 0){
        #pragma unroll
        for (int o = 16; o; o >>= 1) r += __shfl_xor_sync(0xffffffffu, r, o);
        if (threadIdx.x == 0) sh[0] = r;
    }
    __syncthreads();
    return sh[0];
}

// tiled layout index (block 8192 elems = 128 rows x 64 cols bf16, swizzled)
__device__ __forceinline__ size_t tidx(int tile, int nkc, int kc, int r, int c, int part){
    int s = c >> 3, e = c & 7;
    return (((size_t)tile * nkc + kc) << 13) + (size_t)(r * 64) +
           (size_t)((((part * 4 + s) ^ (r & 7))) << 3) + e;
}

// ---------------- weight prep: transpose + split + tile ----------------
__global__ void k_prep(const float* __restrict__ W, __nv_bfloat16* __restrict__ Wt,
                       int K, int N, int Npad){
    int l = blockIdx.z;
    W  += (size_t)l * K * N;
    Wt += (size_t)l * (Npad >> 7) * (K >> 5) * 8192;
    __shared__ float t[32][33];
    int k0 = blockIdx.x * 32, n0 = blockIdx.y * 32;
    int tx = threadIdx.x, ty = threadIdx.y;
    int nkc = K >> 5;
    for (int i = ty; i < 32; i += 8){
        float v = 0.f;
        if (n0 + tx < N) v = W[(size_t)(k0 + i) * N + n0 + tx];
        t[i][tx] = v;
    }
    __syncthreads();
    for (int i = ty; i < 32; i += 8){
        float v = t[tx][i];
        __nv_bfloat16 hi = __float2bfloat16_rn(v);
        float lo = v - __bfloat162float(hi);
        int n = n0 + i, k = k0 + tx;
        int tile = n >> 7, r = n & 127, kc = k >> 5, c = k & 31;
        Wt[tidx(tile, nkc, kc, r, c, 0)] = hi;
        Wt[tidx(tile, nkc, kc, r, c, 1)] = __float2bfloat16_rn(lo);
    }
}

// ---------------- GEMM: bulk-copy, 512 thr, k-chunk 64, 3 stages x 64KB -----
// Stage: A blocks(2x16KB) at +0, B blocks at +32768. Stage stride 65536.
__global__ void __launch_bounds__(512, 1)
k_tgemm(const __nv_bfloat16* __restrict__ At, const __nv_bfloat16* __restrict__ Bt,
        float* __restrict__ C, const float* __restrict__ R,
        int M, int N, int K)
{
    extern __shared__ char smc[];
    __shared__ __align__(8) uint64_t mbarr[3];
    uint32_t sb  = s2u(smc);
    uint32_t mb0 = s2u(mbarr);
    int tid  = threadIdx.x;
    int lane = tid & 31, w = tid >> 5;
    int wm = w & 3, wn = w >> 2;
    int m0 = blockIdx.y * 128, n0 = blockIdx.x * 128;
    int nkc  = K >> 5;
    int nit  = K >> 6;
    const __nv_bfloat16* gA = At + (((size_t)blockIdx.y * nkc) << 13);
    const __nv_bfloat16* gB = Bt + (((size_t)blockIdx.x * nkc) << 13);

    if (tid == 0){
        #pragma unroll
        for (int s = 0; s < 3; s++) mbar_init(mb0 + s * 8, 1);
    }
    __syncthreads();
    if (tid == 0){
        #pragma unroll
        for (int s = 0; s < 2; s++){
            if (s < nit){
                mbar_expect(mb0 + s * 8, 65536u);
                bulkcp32k(sb + s * 65536u,          gA + ((size_t)(s * 2) << 13), mb0 + s * 8);
                bulkcp32k(sb + s * 65536u + 32768u, gB + ((size_t)(s * 2) << 13), mb0 + s * 8);
            }
        }
    }

    float acc[2][4][4];
    #pragma unroll
    for (int mt = 0; mt < 2; mt++)
        #pragma unroll
        for (int nt = 0; nt < 4; nt++)
            #pragma unroll
            for (int e = 0; e < 4; e++) acc[mt][nt][e] = 0.f;

    uint32_t aoff = sb + (uint32_t)((wm * 32 + (lane & 15)) * 128);
    uint32_t boff = sb + 32768u + (uint32_t)((wn * 32 + (lane & 15)) * 128);
    uint32_t ct[2][2];   // [part][kh-local]
    #pragma unroll
    for (int part = 0; part < 2; part++)
        #pragma unroll
        for (int kh = 0; kh < 2; kh++)
            ct[part][kh] = (uint32_t)((((part * 4 + 2 * kh + (lane >> 4))) ^ (lane & 7)) * 16);

    int cur = 0, nxt = 2;
    uint32_t phase = 0;
    for (int it = 0; it < nit; it++){
        mbar_wait(mb0 + (uint32_t)cur * 8, phase);
        __syncthreads();
        if (tid == 0 && it + 2 < nit){
            fence_async();
            mbar_expect(mb0 + (uint32_t)nxt * 8, 65536u);
            bulkcp32k(sb + (uint32_t)nxt * 65536u,          gA + ((size_t)((it + 2) * 2) << 13), mb0 + (uint32_t)nxt * 8);
            bulkcp32k(sb + (uint32_t)nxt * 65536u + 32768u, gB + ((size_t)((it + 2) * 2) << 13), mb0 + (uint32_t)nxt * 8);
        }

        uint32_t bufo = (uint32_t)cur * 65536u;
        #pragma unroll
        for (int kh = 0; kh < 4; kh++){
            uint32_t blko = (uint32_t)((kh >> 1) * 16384);
            int khl = kh & 1;
            uint32_t ah[2][4], al[2][4], bh[2][4], bl[2][4];
            #pragma unroll
            for (int mt = 0; mt < 2; mt++){
                uint32_t base = aoff + bufo + blko + (uint32_t)(mt * 2048);
                ldsm4(ah[mt], base + ct[0][khl]);
                ldsm4(al[mt], base + ct[1][khl]);
            }
            #pragma unroll
            for (int g = 0; g < 2; g++){
                uint32_t base = boff + bufo + blko + (uint32_t)(g * 2048);
                ldsm4(bh[g], base + ct[0][khl]);
                ldsm4(bl[g], base + ct[1][khl]);
            }
            #pragma unroll
            for (int mt = 0; mt < 2; mt++)
                #pragma unroll
                for (int nt = 0; nt < 4; nt++){
                    int g = nt >> 1, s = nt & 1;
                    mma16816(acc[mt][nt], ah[mt], bh[g][s], bh[g][s + 2]);
                    mma16816(acc[mt][nt], ah[mt], bl[g][s], bl[g][s + 2]);
                    mma16816(acc[mt][nt], al[mt], bh[g][s], bh[g][s + 2]);
                }
        }
        if (++cur == 3){ cur = 0; phase ^= 1; }
        if (++nxt == 3) nxt = 0;
    }

    #pragma unroll
    for (int mt = 0; mt < 2; mt++){
        int m = m0 + wm * 32 + mt * 16 + (lane >> 2);
        #pragma unroll
        for (int nt = 0; nt < 4; nt++){
            int col = n0 + wn * 32 + nt * 8 + (lane & 3) * 2;
            if (col < N){
                size_t i0 = (size_t)m * N + col;
                size_t i1 = (size_t)(m + 8) * N + col;
                float2 v0 = make_float2(acc[mt][nt][0], acc[mt][nt][1]);
                float2 v1 = make_float2(acc[mt][nt][2], acc[mt][nt][3]);
                if (R){
                    float2 r0 = *(const float2*)(R + i0);
                    float2 r1 = *(const float2*)(R + i1);
                    v0.x += r0.x; v0.y += r0.y;
                    v1.x += r1.x; v1.y += r1.y;
                }
                *(float2*)(C + i0) = v0;
                *(float2*)(C + i1) = v1;
            }
        }
    }
}

// ---------------- embedding ----------------
__global__ void k_embed(const float* __restrict__ x, const float* __restrict__ W){
    int idx = blockIdx.x * blockDim.x + threadIdx.x;
    if (idx >= NTOK * DMODEL) return;
    int t = idx / DMODEL, d = idx % DMODEL;
    float x0 = x[t*3+0]; if (x0 == -100.f) x0 = 0.f;
    float x1 = x[t*3+1]; if (x1 == -100.f) x1 = 0.f;
    float x2 = x[t*3+2]; if (x2 == -100.f) x2 = 0.f;
    float acc = x0 * W[0*DMODEL + d] + x1 * W[1*DMODEL + d] + x2 * W[2*DMODEL + d];
    if (d < 510){
        int c = d / 170, r = d % 170;
        float xv = (c == 0) ? x0 : ((c == 1) ? x1 : x2);
        float pe;
        if (r < 85) pe = sinf(xv * exp2f((float)r));
        else        pe = cosf(xv * exp2f((float)(r - 85)));
        acc += pe;
    }
    g_h[idx] = acc;
}

// ---------------- rmsnorm: optional fp32 out + tiled bf16 hi/lo out ---------
__global__ void k_rmsnorm(const float* __restrict__ x, const float* __restrict__ w,
                          float* __restrict__ o, __nv_bfloat16* __restrict__ At, int D){
    int t = blockIdx.x;
    const float* xr = x + (size_t)t * D;
    float ss = 0.f;
    for (int d = threadIdx.x; d < D; d += blockDim.x){
        float v = xr[d];
        ss += v * v;
    }
    ss = blockReduceSum(ss);
    float rs = rsqrtf(ss / (float)D + 1e-5f);
    int tile = t >> 7, r = t & 127, nkc = D >> 5;
    for (int d = threadIdx.x; d < D; d += blockDim.x){
        float v = xr[d] * rs * w[d];
        if (o) o[(size_t)t * D + d] = v;
        __nv_bfloat16 hi = __float2bfloat16_rn(v);
        int kc = d >> 5, c = d & 31;
        At[tidx(tile, nkc, kc, r, c, 0)] = hi;
        At[tidx(tile, nkc, kc, r, c, 1)] = __float2bfloat16_rn(v - __bfloat162float(hi));
    }
}

// ---------------- fused conv+silu and dt-cumsum ----------------
__global__ void k_convdt(const float* __restrict__ cw, const float* __restrict__ cb,
                         const float* __restrict__ dtb, const float* __restrict__ Alog){
    if (blockIdx.x < NCONVB){
        int idx = blockIdx.x * 256 + threadIdx.x;
        int t = idx / CONVDIM, ch = idx % CONVDIM;
        int l = t % SEQL;
        float acc = cb[ch];
        #pragma unroll
        for (int k = 0; k < DCONV; k++){
            int l2 = l + k - (DCONV - 1);
            if (l2 >= 0)
                acc += g_zx[(size_t)(t + l2 - l) * DINPROJ + DINNER + ch] * cw[ch*DCONV + k];
        }
        g_xc[idx] = siluf(acc);
    } else {
        __shared__ float sh[2][CHUNKL];
        int pr   = threadIdx.x >> 7;
        int i    = threadIdx.x & 127;
        int flat = (blockIdx.x - NCONVB) * 2 + pr;
        int bc = flat >> 4, h = flat & 15;
        int t  = bc * CHUNKL + i;
        float d = softplusf(g_zx[(size_t)t * DINPROJ + 2176 + h] + dtb[h]);
        float A = -expf(Alog[h]);
        sh[pr][i] = d * A;
        __syncthreads();
        #pragma unroll
        for (int off = 1; off < CHUNKL; off <<= 1){
            float v = (i >= off) ? sh[pr][i - off] : 0.f;
            __syncthreads();
            sh[pr][i] += v;
            __syncthreads();
        }
        g_dtv [t*NH + h] = d;
        g_acum[t*NH + h] = sh[pr][i];
        if (i == CHUNKL - 1) g_dec[flat] = expf(sh[pr][i]);
    }
}

// ---------------- scores: causal i-tiles, grid NBC*4 ----------------
// block (bc, q): computes scores rows [q*32, q*32+32) x cols [0, q*32+32)
__global__ void k_scores(){
    extern __shared__ float smf[];
    float* Csh = smf;             // [32][65]
    float* Bsh = smf + 32*65;     // [128][65]
    int bc = blockIdx.x >> 2, q = blockIdx.x & 3;
    int i0 = q * 32, jmax = i0 + 32;
    int t0 = bc * CHUNKL;
    int tid = threadIdx.x;
    for (int idx = tid; idx < 32*DSTATE; idx += 256){
        int i = idx >> 6, n = idx & 63;
        Csh[i*65 + n] = g_xc[(size_t)(t0+i0+i)*CONVDIM + DINNER + DSTATE + n];
    }
    for (int idx = tid; idx < jmax*DSTATE; idx += 256){
        int j = idx >> 6, n = idx & 63;
        Bsh[j*65 + n] = g_xc[(size_t)(t0+j)*CONVDIM + DINNER + n];
    }
    __syncthreads();
    int ti = (tid >> 4) * 2;
    int tj = (tid & 15) * 8;
    if (tj >= jmax) return;
    float acc[2][8];
    #pragma unroll
    for (int r = 0; r < 2; r++)
        #pragma unroll
        for (int c = 0; c < 8; c++) acc[r][c] = 0.f;
    for (int n = 0; n < DSTATE; n++){
        float a0 = Csh[(ti+0)*65 + n];
        float a1 = Csh[(ti+1)*65 + n];
        float b[8];
        #pragma unroll
        for (int c = 0; c < 8; c++) b[c] = Bsh[(tj+c)*65 + n];
        #pragma unroll
        for (int c = 0; c < 8; c++){ acc[0][c] += a0*b[c]; acc[1][c] += a1*b[c]; }
    }
    float* out = g_sc + (size_t)bc * CHUNKL * CHUNKL;
    #pragma unroll
    for (int r = 0; r < 2; r++)
        #pragma unroll
        for (int c = 0; c < 8; c++)
            out[(i0+ti+r)*CHUNKL + tj + c] = acc[r][c];
}

// ---------------- fused y = y_diag + y_off + D*xh ----------------
__global__ void k_ssd_y(const float* __restrict__ Dp){
    extern __shared__ float smf[];
    float* xsh = smf;
    float* hsh = smf + CHUNKL*HD;
    __shared__ float ash[CHUNKL], dsh[CHUNKL];
    int bc = blockIdx.x >> 4, h = blockIdx.x & 15;
    int i  = threadIdx.x;
    int t0 = bc * CHUNKL;
    ash[i] = g_acum[(t0+i)*NH + h];
    dsh[i] = g_dtv [(t0+i)*NH + h];
    for (int idx = i; idx < CHUNKL*HD; idx += CHUNKL)
        xsh[idx] = g_xc[(size_t)(t0 + (idx >> 6))*CONVDIM + h*HD + (idx & 63)];
    const float* hbase = g_hs + (size_t)blockIdx.x * (HD*DSTATE);
    for (int idx = i; idx < HD*DSTATE; idx += CHUNKL) hsh[idx] = hbase[idx];
    __syncthreads();

    float ai = ash[i];
    float Dh = Dp[h];
    float acc[HD];
    #pragma unroll
    for (int p = 0; p < HD; p++) acc[p] = Dh * xsh[i*HD + p];

    int lo = 0, hi = i;
    while (lo < hi){
        int mid = (lo + hi) >> 1;
        if (ash[mid] < ai + AWIN) hi = mid; else lo = mid + 1;
    }
    const float* srow = g_sc + (size_t)bc * CHUNKL * CHUNKL + (size_t)i * CHUNKL;
    for (int j = lo; j <= i; j++){
        float m = srow[j] * expf(ai - ash[j]) * dsh[j];
        const float* xr = &xsh[j*HD];
        #pragma unroll
        for (int p = 0; p < HD; p++) acc[p] += m * xr[p];
    }

    if (ai > -AWIN){
        float ei = expf(ai);
        const float* crow = g_xc + (size_t)(t0+i)*CONVDIM + DINNER + DSTATE;
        #pragma unroll
        for (int h2 = 0; h2 < 2; h2++){
            float creg[32];
            #pragma unroll
            for (int n = 0; n < 32; n++) creg[n] = ei * crow[h2*32 + n];
            #pragma unroll 8
            for (int p = 0; p < HD; p++){
                const float4* hr = (const float4*)&hsh[p*DSTATE + h2*32];
                float a = 0.f;
                #pragma unroll
                for (int q = 0; q < 8; q++){
                    float4 v = hr[q];
                    a += creg[q*4+0]*v.x + creg[q*4+1]*v.y + creg[q*4+2]*v.z + creg[q*4+3]*v.w;
                }
                acc[p] += a;
            }
        }
    }

    float* yrow = g_y + (size_t)(t0+i)*DINNER + h*HD;
    #pragma unroll
    for (int p = 0; p < HD; p++) yrow[p] = acc[p];
}

// ---------------- chunk states ----------------
__global__ void k_state(){
    extern __shared__ float smf[];
    float* xsh = smf;
    float* bsh = smf + CHUNKL*HD;
    __shared__ float wsh[CHUNKL];
    __shared__ float ash_s[CHUNKL];
    int bc = blockIdx.x >> 4, h = blockIdx.x & 15;
    int t0 = bc * CHUNKL;
    int tid = threadIdx.x;
    for (int idx = tid; idx < CHUNKL*HD; idx += 256){
        int j = idx >> 6, q = idx & 63;
        xsh[idx] = g_xc[(size_t)(t0+j)*CONVDIM + h*HD + q];
        bsh[idx] = g_xc[(size_t)(t0+j)*CONVDIM + DINNER + q];
    }
    if (tid < CHUNKL) ash_s[tid] = g_acum[(t0 + tid)*NH + h];
    __syncthreads();
    if (tid < CHUNKL){
        float alast = ash_s[CHUNKL - 1];
        wsh[tid] = expf(alast - ash_s[tid]) * g_dtv[(t0 + tid)*NH + h];
    }
    __syncthreads();
    float alast = ash_s[CHUNKL - 1];
    int lo = 0, hi = CHUNKL - 1;
    while (lo < hi){
        int mid = (lo + hi) >> 1;
        if (ash_s[mid] < alast + AWIN) hi = mid; else lo = mid + 1;
    }
    int p  = tid & 63;
    int n0 = (tid >> 6) << 4;
    float acc[16];
    #pragma unroll
    for (int k = 0; k < 16; k++) acc[k] = 0.f;
    for (int j = lo; j < CHUNKL; j++){
        float xw = xsh[j*HD + p] * wsh[j];
        const float* br = &bsh[j*HD + n0];
        #pragma unroll
        for (int k = 0; k < 16; k++) acc[k] += xw * br[k];
    }
    float* so = g_S + (size_t)blockIdx.x * (HD*DSTATE);
    #pragma unroll
    for (int k = 0; k < 16; k++) so[p*DSTATE + n0 + k] = acc[k];
}

// ---------------- scan (parallel: 512 blocks) ----------------
__global__ void k_scan(){
    int bid = blockIdx.x;
    int bh  = bid >> 4;
    int grp = bid & 15;
    int b = bh >> 4, h = bh & 15;
    int idx = grp * 256 + threadIdx.x;
    float st = 0.f;
    #pragma unroll 4
    for (int c = 0; c < NCH; c++){
        int bch = (b*NCH + c)*NH + h;
        size_t base = (size_t)bch * (HD*DSTATE);
        float dc = g_dec[bch];
        g_hs[base + idx] = st;
        st = st*dc + g_S[base + idx];
    }
}

// ---------------- gate: rmsnorm(y*silu(z))*gw -> tiled bf16 hi/lo -----------
__global__ void k_gate(const float* __restrict__ gw, __nv_bfloat16* __restrict__ At){
    int t = blockIdx.x;
    int tid = threadIdx.x;
    float v[4]; float ss = 0.f;
    #pragma unroll
    for (int k = 0; k < 4; k++){
        int d = k*256 + tid;
        float z = g_zx[(size_t)t*DINPROJ + d];
        float vv = g_y[(size_t)t*DINNER + d] * siluf(z);
        v[k] = vv; ss += vv*vv;
    }
    ss = blockReduceSum(ss);
    float rs = rsqrtf(ss / (float)DINNER + 1e-5f);
    int tile = t >> 7, r = t & 127;
    #pragma unroll
    for (int k = 0; k < 4; k++){
        int d = k*256 + tid;
        float o = v[k] * rs * gw[d];
        __nv_bfloat16 hi = __float2bfloat16_rn(o);
        int kc = d >> 5, c = d & 31;
        At[tidx(tile, DINNER >> 5, kc, r, c, 0)] = hi;
        At[tidx(tile, DINNER >> 5, kc, r, c, 1)] = __float2bfloat16_rn(o - __bfloat162float(hi));
    }
}

// ---------------- head ----------------
__global__ void k_head(const float* __restrict__ hw, const float* __restrict__ hb,
                       float* __restrict__ out){
    int idx = blockIdx.x * blockDim.x + threadIdx.x;
    if (idx >= NTOK * KOUT) return;
    int t = idx / KOUT, n = idx % KOUT;
    float acc = hb[n];
    const float* xr = g_xn + (size_t)t * DMODEL;
    for (int k = 0; k < DMODEL; k++) acc += xr[k] * hw[k*KOUT + n];
    out[idx] = acc;
}

// ---------------- host ----------------
extern "C" void kernel_launch(void* const* d_in, const int* in_sizes, int n_in,
                              void* d_out, int out_size){
    const float* x      = (const float*)d_in[0];
    const float* Wembed = (const float*)d_in[1];
    const float* rmsw   = (const float*)d_in[2];
    const float* inw    = (const float*)d_in[3];
    const float* convw  = (const float*)d_in[4];
    const float* convb  = (const float*)d_in[5];
    const float* dtb    = (const float*)d_in[6];
    const float* alog   = (const float*)d_in[7];
    const float* dparam = (const float*)d_in[8];
    const float* gnw    = (const float*)d_in[9];
    const float* outw   = (const float*)d_in[10];
    const float* fnw    = (const float*)d_in[11];
    const float* hw     = (const float*)d_in[12];
    const float* hb     = (const float*)d_in[13];
    float* out = (float*)d_out;

    float *p_h, *p_xn, *p_zx;
    cudaGetSymbolAddress((void**)&p_h,  g_h);
    cudaGetSymbolAddress((void**)&p_xn, g_xn);
    cudaGetSymbolAddress((void**)&p_zx, g_zx);
    __nv_bfloat16 *p_ain, *p_aout, *p_win, *p_wout;
    cudaGetSymbolAddress((void**)&p_ain,  g_ain);
    cudaGetSymbolAddress((void**)&p_aout, g_aout);
    cudaGetSymbolAddress((void**)&p_win,  g_win);
    cudaGetSymbolAddress((void**)&p_wout, g_wout);

    const int SC2_SMEM  = (32*65 + 128*65)*4;   // 41600
    const int STATE_SMEM = 2*CHUNKL*HD*4;
    const int SSDY_SMEM  = (CHUNKL*HD + HD*DSTATE)*4;
    const int TG_SMEM    = 3*65536;             // 196608
    cudaFuncSetAttribute(k_scores, cudaFuncAttributeMaxDynamicSharedMemorySize, SC2_SMEM);
    cudaFuncSetAttribute(k_state,  cudaFuncAttributeMaxDynamicSharedMemorySize, STATE_SMEM);
    cudaFuncSetAttribute(k_ssd_y,  cudaFuncAttributeMaxDynamicSharedMemorySize, SSDY_SMEM);
    cudaFuncSetAttribute(k_tgemm,  cudaFuncAttributeMaxDynamicSharedMemorySize, TG_SMEM);

    const size_t WIN_L  = (size_t)(NPAD_IN/128)*(DMODEL/32)*8192;
    const size_t WOUT_L = (size_t)(DMODEL/128)*(DINNER/32)*8192;

    k_prep<<<dim3(DMODEL/32, NPAD_IN/32, NLAYERS), dim3(32,8)>>>(
        inw, p_win, DMODEL, DINPROJ, NPAD_IN);
    k_embed<<<(NTOK*DMODEL + 255)/256, 256>>>(x, Wembed);

    for (int l = 0; l < NLAYERS; l++){
        k_rmsnorm<<<NTOK, 256>>>(p_h, rmsw + (size_t)l*DMODEL, nullptr, p_ain, DMODEL);
        k_tgemm<<<dim3(NPAD_IN/128, NTOK/128), 512, TG_SMEM>>>(
            p_ain, p_win + (size_t)l*WIN_L, p_zx, nullptr, NTOK, DINPROJ, DMODEL);
        if (l == 0)
            k_prep<<<dim3(DINNER/32, DMODEL/32, NLAYERS), dim3(32,8)>>>(
                outw, p_wout, DINNER, DMODEL, DMODEL);
        k_convdt<<<NCONVB + NDTB, 256>>>(convw + (size_t)l*CONVDIM*DCONV,
                                         convb + (size_t)l*CONVDIM,
                                         dtb + (size_t)l*NH, alog + (size_t)l*NH);
        k_scores<<<NBC*4, 256, SC2_SMEM>>>();
        k_state<<<NBC*NH, 256, STATE_SMEM>>>();
        k_scan<<<BSZ*NH*16, 256>>>();
        k_ssd_y<<<NBC*NH, CHUNKL, SSDY_SMEM>>>(dparam + (size_t)l*NH);
        k_gate<<<NTOK, 256>>>(gnw + (size_t)l*DINNER, p_aout);
        k_tgemm<<<dim3(DMODEL/128, NTOK/128), 512, TG_SMEM>>>(
            p_aout, p_wout + (size_t)l*WOUT_L, p_h, p_h, NTOK, DMODEL, DINNER);
    }

    k_rmsnorm<<<NTOK, 256>>>(p_h, fnw, p_xn, p_ain, DMODEL);
    k_head<<<(NTOK*KOUT + 255)/256, 256>>>(hw, hb, out);
}

// round 12
// speedup vs baseline: 1.3741x; 1.0373x over previous
#include <cuda_runtime.h>
#include <cuda_bf16.h>
#include <math.h>
#include <stdint.h>

// ---------------- problem constants ----------------
#define BSZ     2
#define SEQL    2048
#define NTOK    (BSZ*SEQL)        // 4096
#define DMODEL  512
#define DINNER  1024
#define NH      16
#define HD      64
#define DSTATE  64
#define DCONV   4
#define CONVDIM 1152
#define DINPROJ 2192
#define NPAD_IN 2304
#define NLAYERS 12
#define CHUNKL  128
#define NCH     16
#define NBC     (BSZ*NCH)         // 32
#define KOUT    30
#define AWIN    35.0f
#define NCONVB  ((NTOK*CONVDIM)/256)
#define NDTB    ((NBC*NH)/2)

// ---------------- scratch ----------
__device__ float g_h   [NTOK*DMODEL];
__device__ float g_xn  [NTOK*DMODEL];
__device__ float g_zx  [NTOK*DINPROJ];
__device__ float g_xc  [NTOK*CONVDIM];
__device__ float g_dtv [NTOK*NH];
__device__ float g_acum[NTOK*NH];
__device__ float g_dec [NBC*NH];
__device__ float g_sc  [NBC*CHUNKL*CHUNKL];
__device__ float g_y   [NTOK*DINNER];
__device__ float g_S   [NBC*NH*HD*DSTATE];
__device__ float g_hs  [NBC*NH*HD*DSTATE];
// tiled+swizzled bf16 hi/lo operands (16KB blocks, byte-identical to GEMM smem)
__device__ __align__(128) __nv_bfloat16 g_ain [(NTOK/128)*(DMODEL/32)*8192];
__device__ __align__(128) __nv_bfloat16 g_aout[(NTOK/128)*(DINNER/32)*8192];
__device__ __align__(128) __nv_bfloat16 g_win [NLAYERS*(NPAD_IN/128)*(DMODEL/32)*8192];
__device__ __align__(128) __nv_bfloat16 g_wout[NLAYERS*(DMODEL/128)*(DINNER/32)*8192];

// ---------------- helpers ----------------
__device__ __forceinline__ uint32_t s2u(const void* p){
    uint32_t a;
    asm("{ .reg .u64 t; cvta.to.shared.u64 t, %1; cvt.u32.u64 %0, t; }" : "=r"(a) : "l"(p));
    return a;
}
__device__ __forceinline__ void ldsm4(uint32_t* r, uint32_t a){
    asm volatile("ldmatrix.sync.aligned.m8n8.x4.shared.b16 {%0,%1,%2,%3}, [%4];"
        : "=r"(r[0]), "=r"(r[1]), "=r"(r[2]), "=r"(r[3]) : "r"(a));
}
__device__ __forceinline__ void mma16816(float* d, const uint32_t* a, uint32_t b0, uint32_t b1){
    asm volatile("mma.sync.aligned.m16n8k16.row.col.f32.bf16.bf16.f32 "
        "{%0,%1,%2,%3}, {%4,%5,%6,%7}, {%8,%9}, {%0,%1,%2,%3};"
        : "+f"(d[0]), "+f"(d[1]), "+f"(d[2]), "+f"(d[3])
        : "r"(a[0]), "r"(a[1]), "r"(a[2]), "r"(a[3]), "r"(b0), "r"(b1));
}
__device__ __forceinline__ void mbar_init(uint32_t m, uint32_t cnt){
    asm volatile("mbarrier.init.shared.b64 [%0], %1;" :: "r"(m), "r"(cnt) : "memory");
}
__device__ __forceinline__ void mbar_expect(uint32_t m, uint32_t bytes){
    asm volatile("mbarrier.arrive.expect_tx.shared.b64 _, [%0], %1;" :: "r"(m), "r"(bytes) : "memory");
}
__device__ __forceinline__ void mbar_wait(uint32_t m, uint32_t phase){
    asm volatile(
        "{\n\t.reg .pred P;\n\t"
        "WL_%=:\n\t"
        "mbarrier.try_wait.parity.acquire.cta.shared::cta.b64 P, [%0], %1, 0x989680;\n\t"
        "@P bra.uni WD_%=;\n\t"
        "bra.uni WL_%=;\n\t"
        "WD_%=:\n\t}"
        :: "r"(m), "r"(phase) : "memory");
}
__device__ __forceinline__ void bulkcp32k(uint32_t sdst, const void* gsrc, uint32_t mbar){
    uint64_t ga;
    asm("cvta.to.global.u64 %0, %1;" : "=l"(ga) : "l"(gsrc));
    asm volatile("cp.async.bulk.shared::cluster.global.mbarrier::complete_tx::bytes [%0], [%1], %2, [%3];"
        :: "r"(sdst), "l"(ga), "r"(32768u), "r"(mbar) : "memory");
}
__device__ __forceinline__ void fence_async(){
    asm volatile("fence.proxy.async.shared::cta;" ::: "memory");
}

__device__ __forceinline__ float softplusf(float x){
    return (x > 20.f) ? x : log1pf(expf(x));
}
__device__ __forceinline__ float siluf(float x){
    return x / (1.f + expf(-x));
}
__device__ __forceinline__ float blockReduceSum(float v){
    __shared__ float sh[32];
    #pragma unroll
    for (int o = 16; o; o >>= 1) v += __shfl_xor_sync(0xffffffffu, v, o);
    int w = threadIdx.x >> 5;
    if ((threadIdx.x & 31) == 0) sh[w] = v;
    __syncthreads();
    int nw = blockDim.x >> 5;
    float r = (threadIdx.x < nw) ? sh[threadIdx.x] : 0.f;
    if (w == 0){
        #pragma unroll
        for (int o = 16; o; o >>= 1) r += __shfl_xor_sync(0xffffffffu, r, o);
        if (threadIdx.x == 0) sh[0] = r;
    }
    __syncthreads();
    return sh[0];
}

// tiled layout index (block 8192 elems = 128 rows x 64 cols bf16, swizzled)
__device__ __forceinline__ size_t tidx(int tile, int nkc, int kc, int r, int c, int part){
    int s = c >> 3, e = c & 7;
    return (((size_t)tile * nkc + kc) << 13) + (size_t)(r * 64) +
           (size_t)((((part * 4 + s) ^ (r & 7))) << 3) + e;
}
// pack 4 floats to 4 bf16 (uint2)
__device__ __forceinline__ uint2 pack4bf(float a, float b, float c, float d){
    __nv_bfloat162 p0 = __floats2bfloat162_rn(a, b);
    __nv_bfloat162 p1 = __floats2bfloat162_rn(c, d);
    return make_uint2(*(uint32_t*)&p0, *(uint32_t*)&p1);
}

// ---------------- weight prep ----------------
__global__ void k_prep(const float* __restrict__ W, __nv_bfloat16* __restrict__ Wt,
                       int K, int N, int Npad){
    int l = blockIdx.z;
    W  += (size_t)l * K * N;
    Wt += (size_t)l * (Npad >> 7) * (K >> 5) * 8192;
    __shared__ float t[32][33];
    int k0 = blockIdx.x * 32, n0 = blockIdx.y * 32;
    int tx = threadIdx.x, ty = threadIdx.y;
    int nkc = K >> 5;
    for (int i = ty; i < 32; i += 8){
        float v = 0.f;
        if (n0 + tx < N) v = W[(size_t)(k0 + i) * N + n0 + tx];
        t[i][tx] = v;
    }
    __syncthreads();
    for (int i = ty; i < 32; i += 8){
        float v = t[tx][i];
        __nv_bfloat16 hi = __float2bfloat16_rn(v);
        float lo = v - __bfloat162float(hi);
        int n = n0 + i, k = k0 + tx;
        int tile = n >> 7, r = n & 127, kc = k >> 5, c = k & 31;
        Wt[tidx(tile, nkc, kc, r, c, 0)] = hi;
        Wt[tidx(tile, nkc, kc, r, c, 1)] = __float2bfloat16_rn(lo);
    }
}

// ---------------- GEMM (unchanged from R11) ----------------
__global__ void __launch_bounds__(512, 1)
k_tgemm(const __nv_bfloat16* __restrict__ At, const __nv_bfloat16* __restrict__ Bt,
        float* __restrict__ C, const float* __restrict__ R,
        int M, int N, int K)
{
    extern __shared__ char smc[];
    __shared__ __align__(8) uint64_t mbarr[3];
    uint32_t sb  = s2u(smc);
    uint32_t mb0 = s2u(mbarr);
    int tid  = threadIdx.x;
    int lane = tid & 31, w = tid >> 5;
    int wm = w & 3, wn = w >> 2;
    int m0 = blockIdx.y * 128, n0 = blockIdx.x * 128;
    int nkc  = K >> 5;
    int nit  = K >> 6;
    const __nv_bfloat16* gA = At + (((size_t)blockIdx.y * nkc) << 13);
    const __nv_bfloat16* gB = Bt + (((size_t)blockIdx.x * nkc) << 13);

    if (tid == 0){
        #pragma unroll
        for (int s = 0; s < 3; s++) mbar_init(mb0 + s * 8, 1);
    }
    __syncthreads();
    if (tid == 0){
        #pragma unroll
        for (int s = 0; s < 2; s++){
            if (s < nit){
                mbar_expect(mb0 + s * 8, 65536u);
                bulkcp32k(sb + s * 65536u,          gA + ((size_t)(s * 2) << 13), mb0 + s * 8);
                bulkcp32k(sb + s * 65536u + 32768u, gB + ((size_t)(s * 2) << 13), mb0 + s * 8);
            }
        }
    }

    float acc[2][4][4];
    #pragma unroll
    for (int mt = 0; mt < 2; mt++)
        #pragma unroll
        for (int nt = 0; nt < 4; nt++)
            #pragma unroll
            for (int e = 0; e < 4; e++) acc[mt][nt][e] = 0.f;

    uint32_t aoff = sb + (uint32_t)((wm * 32 + (lane & 15)) * 128);
    uint32_t boff = sb + 32768u + (uint32_t)((wn * 32 + (lane & 15)) * 128);
    uint32_t ct[2][2];
    #pragma unroll
    for (int part = 0; part < 2; part++)
        #pragma unroll
        for (int kh = 0; kh < 2; kh++)
            ct[part][kh] = (uint32_t)((((part * 4 + 2 * kh + (lane >> 4))) ^ (lane & 7)) * 16);

    int cur = 0, nxt = 2;
    uint32_t phase = 0;
    for (int it = 0; it < nit; it++){
        mbar_wait(mb0 + (uint32_t)cur * 8, phase);
        __syncthreads();
        if (tid == 0 && it + 2 < nit){
            fence_async();
            mbar_expect(mb0 + (uint32_t)nxt * 8, 65536u);
            bulkcp32k(sb + (uint32_t)nxt * 65536u,          gA + ((size_t)((it + 2) * 2) << 13), mb0 + (uint32_t)nxt * 8);
            bulkcp32k(sb + (uint32_t)nxt * 65536u + 32768u, gB + ((size_t)((it + 2) * 2) << 13), mb0 + (uint32_t)nxt * 8);
        }

        uint32_t bufo = (uint32_t)cur * 65536u;
        #pragma unroll
        for (int kh = 0; kh < 4; kh++){
            uint32_t blko = (uint32_t)((kh >> 1) * 16384);
            int khl = kh & 1;
            uint32_t ah[2][4], al[2][4], bh[2][4], bl[2][4];
            #pragma unroll
            for (int mt = 0; mt < 2; mt++){
                uint32_t base = aoff + bufo + blko + (uint32_t)(mt * 2048);
                ldsm4(ah[mt], base + ct[0][khl]);
                ldsm4(al[mt], base + ct[1][khl]);
            }
            #pragma unroll
            for (int g = 0; g < 2; g++){
                uint32_t base = boff + bufo + blko + (uint32_t)(g * 2048);
                ldsm4(bh[g], base + ct[0][khl]);
                ldsm4(bl[g], base + ct[1][khl]);
            }
            #pragma unroll
            for (int mt = 0; mt < 2; mt++)
                #pragma unroll
                for (int nt = 0; nt < 4; nt++){
                    int g = nt >> 1, s = nt & 1;
                    mma16816(acc[mt][nt], ah[mt], bh[g][s], bh[g][s + 2]);
                    mma16816(acc[mt][nt], ah[mt], bl[g][s], bl[g][s + 2]);
                    mma16816(acc[mt][nt], al[mt], bh[g][s], bh[g][s + 2]);
                }
        }
        if (++cur == 3){ cur = 0; phase ^= 1; }
        if (++nxt == 3) nxt = 0;
    }

    #pragma unroll
    for (int mt = 0; mt < 2; mt++){
        int m = m0 + wm * 32 + mt * 16 + (lane >> 2);
        #pragma unroll
        for (int nt = 0; nt < 4; nt++){
            int col = n0 + wn * 32 + nt * 8 + (lane & 3) * 2;
            if (col < N){
                size_t i0 = (size_t)m * N + col;
                size_t i1 = (size_t)(m + 8) * N + col;
                float2 v0 = make_float2(acc[mt][nt][0], acc[mt][nt][1]);
                float2 v1 = make_float2(acc[mt][nt][2], acc[mt][nt][3]);
                if (R){
                    float2 r0 = *(const float2*)(R + i0);
                    float2 r1 = *(const float2*)(R + i1);
                    v0.x += r0.x; v0.y += r0.y;
                    v1.x += r1.x; v1.y += r1.y;
                }
                *(float2*)(C + i0) = v0;
                *(float2*)(C + i1) = v1;
            }
        }
    }
}

// ---------------- embedding ----------------
__global__ void k_embed(const float* __restrict__ x, const float* __restrict__ W){
    int idx = blockIdx.x * blockDim.x + threadIdx.x;
    if (idx >= NTOK * DMODEL) return;
    int t = idx / DMODEL, d = idx % DMODEL;
    float x0 = x[t*3+0]; if (x0 == -100.f) x0 = 0.f;
    float x1 = x[t*3+1]; if (x1 == -100.f) x1 = 0.f;
    float x2 = x[t*3+2]; if (x2 == -100.f) x2 = 0.f;
    float acc = x0 * W[0*DMODEL + d] + x1 * W[1*DMODEL + d] + x2 * W[2*DMODEL + d];
    if (d < 510){
        int c = d / 170, r = d % 170;
        float xv = (c == 0) ? x0 : ((c == 1) ? x1 : x2);
        float pe;
        if (r < 85) pe = sinf(xv * exp2f((float)r));
        else        pe = cosf(xv * exp2f((float)(r - 85)));
        acc += pe;
    }
    g_h[idx] = acc;
}

// ---------------- rmsnorm: float4, optional fp32 out + tiled bf16 out -------
__global__ void k_rmsnorm(const float* __restrict__ x, const float* __restrict__ w,
                          float* __restrict__ o, __nv_bfloat16* __restrict__ At, int D){
    int t = blockIdx.x;
    const float* xr = x + (size_t)t * D;
    float ss = 0.f;
    for (int d4 = threadIdx.x * 4; d4 < D; d4 += blockDim.x * 4){
        float4 v = *(const float4*)(xr + d4);
        ss += v.x*v.x + v.y*v.y + v.z*v.z + v.w*v.w;
    }
    ss = blockReduceSum(ss);
    float rs = rsqrtf(ss / (float)D + 1e-5f);
    int tile = t >> 7, r = t & 127, nkc = D >> 5;
    for (int d4 = threadIdx.x * 4; d4 < D; d4 += blockDim.x * 4){
        float4 v  = *(const float4*)(xr + d4);
        float4 wv = *(const float4*)(w + d4);
        float a = v.x*rs*wv.x, b = v.y*rs*wv.y, c = v.z*rs*wv.z, e = v.w*rs*wv.w;
        if (o) *(float4*)(o + (size_t)t * D + d4) = make_float4(a,b,c,e);
        __nv_bfloat162 h0 = __floats2bfloat162_rn(a, b);
        __nv_bfloat162 h1 = __floats2bfloat162_rn(c, e);
        float2 f0 = __bfloat1622float2(h0), f1 = __bfloat1622float2(h1);
        int kc = d4 >> 5, cc = d4 & 31;
        *(uint2*)(At + tidx(tile, nkc, kc, r, cc, 0)) = make_uint2(*(uint32_t*)&h0, *(uint32_t*)&h1);
        *(uint2*)(At + tidx(tile, nkc, kc, r, cc, 1)) = pack4bf(a-f0.x, b-f0.y, c-f1.x, e-f1.y);
    }
}

// ---------------- fused conv+silu and dt-cumsum ----------------
__global__ void k_convdt(const float* __restrict__ cw, const float* __restrict__ cb,
                         const float* __restrict__ dtb, const float* __restrict__ Alog){
    if (blockIdx.x < NCONVB){
        int idx = blockIdx.x * 256 + threadIdx.x;
        int t = idx / CONVDIM, ch = idx % CONVDIM;
        int l = t % SEQL;
        float acc = cb[ch];
        #pragma unroll
        for (int k = 0; k < DCONV; k++){
            int l2 = l + k - (DCONV - 1);
            if (l2 >= 0)
                acc += g_zx[(size_t)(t + l2 - l) * DINPROJ + DINNER + ch] * cw[ch*DCONV + k];
        }
        g_xc[idx] = siluf(acc);
    } else {
        __shared__ float sh[2][CHUNKL];
        int pr   = threadIdx.x >> 7;
        int i    = threadIdx.x & 127;
        int flat = (blockIdx.x - NCONVB) * 2 + pr;
        int bc = flat >> 4, h = flat & 15;
        int t  = bc * CHUNKL + i;
        float d = softplusf(g_zx[(size_t)t * DINPROJ + 2176 + h] + dtb[h]);
        float A = -expf(Alog[h]);
        sh[pr][i] = d * A;
        __syncthreads();
        #pragma unroll
        for (int off = 1; off < CHUNKL; off <<= 1){
            float v = (i >= off) ? sh[pr][i - off] : 0.f;
            __syncthreads();
            sh[pr][i] += v;
            __syncthreads();
        }
        g_dtv [t*NH + h] = d;
        g_acum[t*NH + h] = sh[pr][i];
        if (i == CHUNKL - 1) g_dec[flat] = expf(sh[pr][i]);
    }
}

// ---------------- fused state + scores (one launch) ----------------
// blocks [0, NBC*NH): chunk states. blocks [NBC*NH, NBC*NH+NBC*4): causal scores.
__global__ void k_ssd1(){
    extern __shared__ float smf[];
    int tid = threadIdx.x;
    if (blockIdx.x < NBC*NH){
        float* xsh = smf;
        float* bsh = smf + CHUNKL*HD;
        __shared__ float wsh[CHUNKL];
        __shared__ float ash_s[CHUNKL];
        int bc = blockIdx.x >> 4, h = blockIdx.x & 15;
        int t0 = bc * CHUNKL;
        for (int idx = tid; idx < CHUNKL*HD; idx += 256){
            int j = idx >> 6, q = idx & 63;
            xsh[idx] = g_xc[(size_t)(t0+j)*CONVDIM + h*HD + q];
            bsh[idx] = g_xc[(size_t)(t0+j)*CONVDIM + DINNER + q];
        }
        if (tid < CHUNKL) ash_s[tid] = g_acum[(t0 + tid)*NH + h];
        __syncthreads();
        if (tid < CHUNKL){
            float alast = ash_s[CHUNKL - 1];
            wsh[tid] = __expf(alast - ash_s[tid]) * g_dtv[(t0 + tid)*NH + h];
        }
        __syncthreads();
        float alast = ash_s[CHUNKL - 1];
        int lo = 0, hi = CHUNKL - 1;
        while (lo < hi){
            int mid = (lo + hi) >> 1;
            if (ash_s[mid] < alast + AWIN) hi = mid; else lo = mid + 1;
        }
        int p  = tid & 63;
        int n0 = (tid >> 6) << 4;
        float acc[16];
        #pragma unroll
        for (int k = 0; k < 16; k++) acc[k] = 0.f;
        for (int j = lo; j < CHUNKL; j++){
            float xw = xsh[j*HD + p] * wsh[j];
            const float* br = &bsh[j*HD + n0];
            #pragma unroll
            for (int k = 0; k < 16; k++) acc[k] += xw * br[k];
        }
        float* so = g_S + (size_t)blockIdx.x * (HD*DSTATE);
        #pragma unroll
        for (int k = 0; k < 16; k++) so[p*DSTATE + n0 + k] = acc[k];
    } else {
        int bid = blockIdx.x - NBC*NH;
        float* Csh = smf;             // [32][65]
        float* Bsh = smf + 32*65;     // [128][65]
        int bc = bid >> 2, q = bid & 3;
        int i0 = q * 32, jmax = i0 + 32;
        int t0 = bc * CHUNKL;
        for (int idx = tid; idx < 32*DSTATE; idx += 256){
            int i = idx >> 6, n = idx & 63;
            Csh[i*65 + n] = g_xc[(size_t)(t0+i0+i)*CONVDIM + DINNER + DSTATE + n];
        }
        for (int idx = tid; idx < jmax*DSTATE; idx += 256){
            int j = idx >> 6, n = idx & 63;
            Bsh[j*65 + n] = g_xc[(size_t)(t0+j)*CONVDIM + DINNER + n];
        }
        __syncthreads();
        int ti = (tid >> 4) * 2;
        int tj = (tid & 15) * 8;
        if (tj >= jmax) return;
        float acc[2][8];
        #pragma unroll
        for (int r = 0; r < 2; r++)
            #pragma unroll
            for (int c = 0; c < 8; c++) acc[r][c] = 0.f;
        for (int n = 0; n < DSTATE; n++){
            float a0 = Csh[(ti+0)*65 + n];
            float a1 = Csh[(ti+1)*65 + n];
            float b[8];
            #pragma unroll
            for (int c = 0; c < 8; c++) b[c] = Bsh[(tj+c)*65 + n];
            #pragma unroll
            for (int c = 0; c < 8; c++){ acc[0][c] += a0*b[c]; acc[1][c] += a1*b[c]; }
        }
        float* out = g_sc + (size_t)bc * CHUNKL * CHUNKL;
        #pragma unroll
        for (int r = 0; r < 2; r++)
            #pragma unroll
            for (int c = 0; c < 8; c++)
                out[(i0+ti+r)*CHUNKL + tj + c] = acc[r][c];
    }
}

// ---------------- scan (parallel: 512 blocks) ----------------
__global__ void k_scan(){
    int bid = blockIdx.x;
    int bh  = bid >> 4;
    int grp = bid & 15;
    int b = bh >> 4, h = bh & 15;
    int idx = grp * 256 + threadIdx.x;
    float st = 0.f;
    #pragma unroll 4
    for (int c = 0; c < NCH; c++){
        int bch = (b*NCH + c)*NH + h;
        size_t base = (size_t)bch * (HD*DSTATE);
        float dc = g_dec[bch];
        g_hs[base + idx] = st;
        st = st*dc + g_S[base + idx];
    }
}

// ---------------- fused y = y_diag + y_off + D*xh, 256 threads --------------
// thread = (row i = tid&127, p-half ph = tid>>7). acc[32].
__global__ void k_ssd_y(const float* __restrict__ Dp){
    extern __shared__ float smf[];
    float* xsh = smf;                 // [128][64]
    float* hsh = smf + CHUNKL*HD;     // [64][64]
    __shared__ float ash[CHUNKL], dsh[CHUNKL];
    int bc = blockIdx.x >> 4, h = blockIdx.x & 15;
    int tid = threadIdx.x;
    int i  = tid & 127, ph = tid >> 7;
    int pb = ph * 32;
    int t0 = bc * CHUNKL;
    if (tid < CHUNKL){
        ash[tid] = g_acum[(t0+tid)*NH + h];
        dsh[tid] = g_dtv [(t0+tid)*NH + h];
    }
    for (int idx = tid; idx < CHUNKL*HD; idx += 256)
        xsh[idx] = g_xc[(size_t)(t0 + (idx >> 6))*CONVDIM + h*HD + (idx & 63)];
    const float* hbase = g_hs + (size_t)blockIdx.x * (HD*DSTATE);
    for (int idx = tid; idx < HD*DSTATE; idx += 256) hsh[idx] = hbase[idx];
    __syncthreads();

    float ai = ash[i];
    float Dh = Dp[h];
    float acc[32];
    #pragma unroll
    for (int p = 0; p < 32; p++) acc[p] = Dh * xsh[i*HD + pb + p];

    int lo = 0, hi = i;
    while (lo < hi){
        int mid = (lo + hi) >> 1;
        if (ash[mid] < ai + AWIN) hi = mid; else lo = mid + 1;
    }
    const float* srow = g_sc + (size_t)bc * CHUNKL * CHUNKL + (size_t)i * CHUNKL;
    for (int j = lo; j <= i; j++){
        float m = srow[j] * __expf(ai - ash[j]) * dsh[j];
        const float* xr = &xsh[j*HD + pb];
        #pragma unroll
        for (int p = 0; p < 32; p++) acc[p] += m * xr[p];
    }

    if (ai > -AWIN){
        float ei = __expf(ai);
        const float* crow = g_xc + (size_t)(t0+i)*CONVDIM + DINNER + DSTATE;
        #pragma unroll
        for (int h2 = 0; h2 < 2; h2++){
            float creg[32];
            #pragma unroll
            for (int n = 0; n < 32; n++) creg[n] = ei * crow[h2*32 + n];
            #pragma unroll 4
            for (int p = 0; p < 32; p++){
                const float4* hr = (const float4*)&hsh[(pb+p)*DSTATE + h2*32];
                float a = 0.f;
                #pragma unroll
                for (int q = 0; q < 8; q++){
                    float4 v = hr[q];
                    a += creg[q*4+0]*v.x + creg[q*4+1]*v.y + creg[q*4+2]*v.z + creg[q*4+3]*v.w;
                }
                acc[p] += a;
            }
        }
    }

    float* yrow = g_y + (size_t)(t0+i)*DINNER + h*HD + pb;
    #pragma unroll
    for (int p = 0; p < 32; p++) yrow[p] = acc[p];
}

// ---------------- gate: float4 loads, tiled bf16 hi/lo out ------------------
__global__ void k_gate(const float* __restrict__ gw, __nv_bfloat16* __restrict__ At){
    int t = blockIdx.x;
    int tid = threadIdx.x;
    int d4 = tid * 4;                    // 256 threads x 4 = 1024
    float4 zv = *(const float4*)(g_zx + (size_t)t*DINPROJ + d4);
    float4 yv = *(const float4*)(g_y  + (size_t)t*DINNER + d4);
    float v0 = yv.x * siluf(zv.x);
    float v1 = yv.y * siluf(zv.y);
    float v2 = yv.z * siluf(zv.z);
    float v3 = yv.w * siluf(zv.w);
    float ss = blockReduceSum(v0*v0 + v1*v1 + v2*v2 + v3*v3);
    float rs = rsqrtf(ss / (float)DINNER + 1e-5f);
    float4 wv = *(const float4*)(gw + d4);
    float a = v0*rs*wv.x, b = v1*rs*wv.y, c = v2*rs*wv.z, e = v3*rs*wv.w;
    __nv_bfloat162 h0 = __floats2bfloat162_rn(a, b);
    __nv_bfloat162 h1 = __floats2bfloat162_rn(c, e);
    float2 f0 = __bfloat1622float2(h0), f1 = __bfloat1622float2(h1);
    int tile = t >> 7, r = t & 127;
    int kc = d4 >> 5, cc = d4 & 31;
    *(uint2*)(At + tidx(tile, DINNER >> 5, kc, r, cc, 0)) = make_uint2(*(uint32_t*)&h0, *(uint32_t*)&h1);
    *(uint2*)(At + tidx(tile, DINNER >> 5, kc, r, cc, 1)) = pack4bf(a-f0.x, b-f0.y, c-f1.x, e-f1.y);
}

// ---------------- head ----------------
__global__ void k_head(const float* __restrict__ hw, const float* __restrict__ hb,
                       float* __restrict__ out){
    int idx = blockIdx.x * blockDim.x + threadIdx.x;
    if (idx >= NTOK * KOUT) return;
    int t = idx / KOUT, n = idx % KOUT;
    float acc = hb[n];
    const float* xr = g_xn + (size_t)t * DMODEL;
    for (int k = 0; k < DMODEL; k++) acc += xr[k] * hw[k*KOUT + n];
    out[idx] = acc;
}

// ---------------- host ----------------
extern "C" void kernel_launch(void* const* d_in, const int* in_sizes, int n_in,
                              void* d_out, int out_size){
    const float* x      = (const float*)d_in[0];
    const float* Wembed = (const float*)d_in[1];
    const float* rmsw   = (const float*)d_in[2];
    const float* inw    = (const float*)d_in[3];
    const float* convw  = (const float*)d_in[4];
    const float* convb  = (const float*)d_in[5];
    const float* dtb    = (const float*)d_in[6];
    const float* alog   = (const float*)d_in[7];
    const float* dparam = (const float*)d_in[8];
    const float* gnw    = (const float*)d_in[9];
    const float* outw   = (const float*)d_in[10];
    const float* fnw    = (const float*)d_in[11];
    const float* hw     = (const float*)d_in[12];
    const float* hb     = (const float*)d_in[13];
    float* out = (float*)d_out;

    float *p_h, *p_xn;
    cudaGetSymbolAddress((void**)&p_h,  g_h);
    cudaGetSymbolAddress((void**)&p_xn, g_xn);
    float *p_zx;
    cudaGetSymbolAddress((void**)&p_zx, g_zx);
    __nv_bfloat16 *p_ain, *p_aout, *p_win, *p_wout;
    cudaGetSymbolAddress((void**)&p_ain,  g_ain);
    cudaGetSymbolAddress((void**)&p_aout, g_aout);
    cudaGetSymbolAddress((void**)&p_win,  g_win);
    cudaGetSymbolAddress((void**)&p_wout, g_wout);

    const int SSD1_SMEM = 2*CHUNKL*HD*4;         // 65536 (max of state/scores needs)
    const int SSDY_SMEM = (CHUNKL*HD + HD*DSTATE)*4;
    const int TG_SMEM   = 3*65536;
    cudaFuncSetAttribute(k_ssd1,  cudaFuncAttributeMaxDynamicSharedMemorySize, SSD1_SMEM);
    cudaFuncSetAttribute(k_ssd_y, cudaFuncAttributeMaxDynamicSharedMemorySize, SSDY_SMEM);
    cudaFuncSetAttribute(k_tgemm, cudaFuncAttributeMaxDynamicSharedMemorySize, TG_SMEM);

    const size_t WIN_L  = (size_t)(NPAD_IN/128)*(DMODEL/32)*8192;
    const size_t WOUT_L = (size_t)(DMODEL/128)*(DINNER/32)*8192;

    k_prep<<<dim3(DMODEL/32, NPAD_IN/32, NLAYERS), dim3(32,8)>>>(
        inw, p_win, DMODEL, DINPROJ, NPAD_IN);
    k_embed<<<(NTOK*DMODEL + 255)/256, 256>>>(x, Wembed);

    for (int l = 0; l < NLAYERS; l++){
        k_rmsnorm<<<NTOK, 128>>>(p_h, rmsw + (size_t)l*DMODEL, nullptr, p_ain, DMODEL);
        k_tgemm<<<dim3(NPAD_IN/128, NTOK/128), 512, TG_SMEM>>>(
            p_ain, p_win + (size_t)l*WIN_L, p_zx, nullptr, NTOK, DINPROJ, DMODEL);
        if (l == 0)
            k_prep<<<dim3(DINNER/32, DMODEL/32, NLAYERS), dim3(32,8)>>>(
                outw, p_wout, DINNER, DMODEL, DMODEL);
        k_convdt<<<NCONVB + NDTB, 256>>>(convw + (size_t)l*CONVDIM*DCONV,
                                         convb + (size_t)l*CONVDIM,
                                         dtb + (size_t)l*NH, alog + (size_t)l*NH);
        k_ssd1<<<NBC*NH + NBC*4, 256, SSD1_SMEM>>>();
        k_scan<<<BSZ*NH*16, 256>>>();
        k_ssd_y<<<NBC*NH, 256, SSDY_SMEM>>>(dparam + (size_t)l*NH);
        k_gate<<<NTOK, 256>>>(gnw + (size_t)l*DINNER, p_aout);
        k_tgemm<<<dim3(DMODEL/128, NTOK/128), 512, TG_SMEM>>>(
            p_aout, p_wout + (size_t)l*WOUT_L, p_h, p_h, NTOK, DMODEL, DINNER);
    }

    k_rmsnorm<<<NTOK, 128>>>(p_h, fnw, p_xn, p_ain, DMODEL);
    k_head<<<(NTOK*KOUT + 255)/256, 256>>>(hw, hb, out);
}

// round 13
// speedup vs baseline: 1.5914x; 1.1582x over previous
#include <cuda_runtime.h>
#include <cuda_bf16.h>
#include <math.h>
#include <stdint.h>

// ---------------- problem constants ----------------
#define BSZ     2
#define SEQL    2048
#define NTOK    (BSZ*SEQL)        // 4096
#define DMODEL  512
#define DINNER  1024
#define NH      16
#define HD      64
#define DSTATE  64
#define DCONV   4
#define CONVDIM 1152
#define DINPROJ 2192
#define NPAD_IN 2304
#define NLAYERS 12
#define CHUNKL  128
#define NCH     16
#define NBC     (BSZ*NCH)         // 32
#define KOUT    30
#define AWIN    20.0f
#define NCONVB  ((NTOK/4*CONVDIM)/256)   // 4608 conv blocks (4 tokens/thread)
#define NDTB    ((NBC*NH)/2)

// ---------------- scratch ----------
__device__ float g_h   [NTOK*DMODEL];
__device__ float g_xn  [NTOK*DMODEL];
__device__ float g_zx  [NTOK*DINPROJ];
__device__ float g_xc  [NTOK*CONVDIM];
__device__ float g_dtv [NTOK*NH];
__device__ float g_acum[NTOK*NH];
__device__ float g_dec [NBC*NH];
__device__ float g_sc  [NBC*CHUNKL*CHUNKL];
__device__ float g_y   [NTOK*DINNER];
__device__ float g_S   [NBC*NH*HD*DSTATE];
__device__ float g_hs  [NBC*NH*HD*DSTATE];
// tiled+swizzled bf16 hi/lo operands (16KB blocks, byte-identical to GEMM smem)
__device__ __align__(128) __nv_bfloat16 g_ain [(NTOK/128)*(DMODEL/32)*8192];
__device__ __align__(128) __nv_bfloat16 g_aout[(NTOK/128)*(DINNER/32)*8192];
__device__ __align__(128) __nv_bfloat16 g_win [NLAYERS*(NPAD_IN/128)*(DMODEL/32)*8192];
__device__ __align__(128) __nv_bfloat16 g_wout[NLAYERS*(DMODEL/128)*(DINNER/32)*8192];

// ---------------- helpers ----------------
__device__ __forceinline__ uint32_t s2u(const void* p){
    uint32_t a;
    asm("{ .reg .u64 t; cvta.to.shared.u64 t, %1; cvt.u32.u64 %0, t; }" : "=r"(a) : "l"(p));
    return a;
}
__device__ __forceinline__ void ldsm4(uint32_t* r, uint32_t a){
    asm volatile("ldmatrix.sync.aligned.m8n8.x4.shared.b16 {%0,%1,%2,%3}, [%4];"
        : "=r"(r[0]), "=r"(r[1]), "=r"(r[2]), "=r"(r[3]) : "r"(a));
}
__device__ __forceinline__ void mma16816(float* d, const uint32_t* a, uint32_t b0, uint32_t b1){
    asm volatile("mma.sync.aligned.m16n8k16.row.col.f32.bf16.bf16.f32 "
        "{%0,%1,%2,%3}, {%4,%5,%6,%7}, {%8,%9}, {%0,%1,%2,%3};"
        : "+f"(d[0]), "+f"(d[1]), "+f"(d[2]), "+f"(d[3])
        : "r"(a[0]), "r"(a[1]), "r"(a[2]), "r"(a[3]), "r"(b0), "r"(b1));
}
__device__ __forceinline__ void mbar_init(uint32_t m, uint32_t cnt){
    asm volatile("mbarrier.init.shared.b64 [%0], %1;" :: "r"(m), "r"(cnt) : "memory");
}
__device__ __forceinline__ void mbar_expect(uint32_t m, uint32_t bytes){
    asm volatile("mbarrier.arrive.expect_tx.shared.b64 _, [%0], %1;" :: "r"(m), "r"(bytes) : "memory");
}
__device__ __forceinline__ void mbar_wait(uint32_t m, uint32_t phase){
    asm volatile(
        "{\n\t.reg .pred P;\n\t"
        "WL_%=:\n\t"
        "mbarrier.try_wait.parity.acquire.cta.shared::cta.b64 P, [%0], %1, 0x989680;\n\t"
        "@P bra.uni WD_%=;\n\t"
        "bra.uni WL_%=;\n\t"
        "WD_%=:\n\t}"
        :: "r"(m), "r"(phase) : "memory");
}
__device__ __forceinline__ void bulkcp32k(uint32_t sdst, const void* gsrc, uint32_t mbar){
    uint64_t ga;
    asm("cvta.to.global.u64 %0, %1;" : "=l"(ga) : "l"(gsrc));
    asm volatile("cp.async.bulk.shared::cluster.global.mbarrier::complete_tx::bytes [%0], [%1], %2, [%3];"
        :: "r"(sdst), "l"(ga), "r"(32768u), "r"(mbar) : "memory");
}
__device__ __forceinline__ void fence_async(){
    asm volatile("fence.proxy.async.shared::cta;" ::: "memory");
}

__device__ __forceinline__ float softplusf(float x){
    return (x > 20.f) ? x : log1pf(expf(x));
}
__device__ __forceinline__ float siluf(float x){
    return x / (1.f + expf(-x));
}
__device__ __forceinline__ float blockReduceSum(float v){
    __shared__ float sh[32];
    #pragma unroll
    for (int o = 16; o; o >>= 1) v += __shfl_xor_sync(0xffffffffu, v, o);
    int w = threadIdx.x >> 5;
    if ((threadIdx.x & 31) == 0) sh[w] = v;
    __syncthreads();
    int nw = blockDim.x >> 5;
    float r = (threadIdx.x < nw) ? sh[threadIdx.x] : 0.f;
    if (w == 0){
        #pragma unroll
        for (int o = 16; o; o >>= 1) r += __shfl_xor_sync(0xffffffffu, r, o);
        if (threadIdx.x == 0) sh[0] = r;
    }
    __syncthreads();
    return sh[0];
}

// tiled layout index (block 8192 elems = 128 rows x 64 cols bf16, swizzled)
__device__ __forceinline__ size_t tidx(int tile, int nkc, int kc, int r, int c, int part){
    int s = c >> 3, e = c & 7;
    return (((size_t)tile * nkc + kc) << 13) + (size_t)(r * 64) +
           (size_t)((((part * 4 + s) ^ (r & 7))) << 3) + e;
}
__device__ __forceinline__ uint2 pack4bf(float a, float b, float c, float d){
    __nv_bfloat162 p0 = __floats2bfloat162_rn(a, b);
    __nv_bfloat162 p1 = __floats2bfloat162_rn(c, d);
    return make_uint2(*(uint32_t*)&p0, *(uint32_t*)&p1);
}

// ---------------- weight prep ----------------
__global__ void k_prep(const float* __restrict__ W, __nv_bfloat16* __restrict__ Wt,
                       int K, int N, int Npad){
    int l = blockIdx.z;
    W  += (size_t)l * K * N;
    Wt += (size_t)l * (Npad >> 7) * (K >> 5) * 8192;
    __shared__ float t[32][33];
    int k0 = blockIdx.x * 32, n0 = blockIdx.y * 32;
    int tx = threadIdx.x, ty = threadIdx.y;
    int nkc = K >> 5;
    for (int i = ty; i < 32; i += 8){
        float v = 0.f;
        if (n0 + tx < N) v = W[(size_t)(k0 + i) * N + n0 + tx];
        t[i][tx] = v;
    }
    __syncthreads();
    for (int i = ty; i < 32; i += 8){
        float v = t[tx][i];
        __nv_bfloat16 hi = __float2bfloat16_rn(v);
        float lo = v - __bfloat162float(hi);
        int n = n0 + i, k = k0 + tx;
        int tile = n >> 7, r = n & 127, kc = k >> 5, c = k & 31;
        Wt[tidx(tile, nkc, kc, r, c, 0)] = hi;
        Wt[tidx(tile, nkc, kc, r, c, 1)] = __float2bfloat16_rn(lo);
    }
}

// ---------------- GEMM (unchanged) ----------------
__global__ void __launch_bounds__(512, 1)
k_tgemm(const __nv_bfloat16* __restrict__ At, const __nv_bfloat16* __restrict__ Bt,
        float* __restrict__ C, const float* __restrict__ R,
        int M, int N, int K)
{
    extern __shared__ char smc[];
    __shared__ __align__(8) uint64_t mbarr[3];
    uint32_t sb  = s2u(smc);
    uint32_t mb0 = s2u(mbarr);
    int tid  = threadIdx.x;
    int lane = tid & 31, w = tid >> 5;
    int wm = w & 3, wn = w >> 2;
    int m0 = blockIdx.y * 128, n0 = blockIdx.x * 128;
    int nkc  = K >> 5;
    int nit  = K >> 6;
    const __nv_bfloat16* gA = At + (((size_t)blockIdx.y * nkc) << 13);
    const __nv_bfloat16* gB = Bt + (((size_t)blockIdx.x * nkc) << 13);

    if (tid == 0){
        #pragma unroll
        for (int s = 0; s < 3; s++) mbar_init(mb0 + s * 8, 1);
    }
    __syncthreads();
    if (tid == 0){
        #pragma unroll
        for (int s = 0; s < 2; s++){
            if (s < nit){
                mbar_expect(mb0 + s * 8, 65536u);
                bulkcp32k(sb + s * 65536u,          gA + ((size_t)(s * 2) << 13), mb0 + s * 8);
                bulkcp32k(sb + s * 65536u + 32768u, gB + ((size_t)(s * 2) << 13), mb0 + s * 8);
            }
        }
    }

    float acc[2][4][4];
    #pragma unroll
    for (int mt = 0; mt < 2; mt++)
        #pragma unroll
        for (int nt = 0; nt < 4; nt++)
            #pragma unroll
            for (int e = 0; e < 4; e++) acc[mt][nt][e] = 0.f;

    uint32_t aoff = sb + (uint32_t)((wm * 32 + (lane & 15)) * 128);
    uint32_t boff = sb + 32768u + (uint32_t)((wn * 32 + (lane & 15)) * 128);
    uint32_t ct[2][2];
    #pragma unroll
    for (int part = 0; part < 2; part++)
        #pragma unroll
        for (int kh = 0; kh < 2; kh++)
            ct[part][kh] = (uint32_t)((((part * 4 + 2 * kh + (lane >> 4))) ^ (lane & 7)) * 16);

    int cur = 0, nxt = 2;
    uint32_t phase = 0;
    for (int it = 0; it < nit; it++){
        mbar_wait(mb0 + (uint32_t)cur * 8, phase);
        __syncthreads();
        if (tid == 0 && it + 2 < nit){
            fence_async();
            mbar_expect(mb0 + (uint32_t)nxt * 8, 65536u);
            bulkcp32k(sb + (uint32_t)nxt * 65536u,          gA + ((size_t)((it + 2) * 2) << 13), mb0 + (uint32_t)nxt * 8);
            bulkcp32k(sb + (uint32_t)nxt * 65536u + 32768u, gB + ((size_t)((it + 2) * 2) << 13), mb0 + (uint32_t)nxt * 8);
        }

        uint32_t bufo = (uint32_t)cur * 65536u;
        #pragma unroll
        for (int kh = 0; kh < 4; kh++){
            uint32_t blko = (uint32_t)((kh >> 1) * 16384);
            int khl = kh & 1;
            uint32_t ah[2][4], al[2][4], bh[2][4], bl[2][4];
            #pragma unroll
            for (int mt = 0; mt < 2; mt++){
                uint32_t base = aoff + bufo + blko + (uint32_t)(mt * 2048);
                ldsm4(ah[mt], base + ct[0][khl]);
                ldsm4(al[mt], base + ct[1][khl]);
            }
            #pragma unroll
            for (int g = 0; g < 2; g++){
                uint32_t base = boff + bufo + blko + (uint32_t)(g * 2048);
                ldsm4(bh[g], base + ct[0][khl]);
                ldsm4(bl[g], base + ct[1][khl]);
            }
            #pragma unroll
            for (int mt = 0; mt < 2; mt++)
                #pragma unroll
                for (int nt = 0; nt < 4; nt++){
                    int g = nt >> 1, s = nt & 1;
                    mma16816(acc[mt][nt], ah[mt], bh[g][s], bh[g][s + 2]);
                    mma16816(acc[mt][nt], ah[mt], bl[g][s], bl[g][s + 2]);
                    mma16816(acc[mt][nt], al[mt], bh[g][s], bh[g][s + 2]);
                }
        }
        if (++cur == 3){ cur = 0; phase ^= 1; }
        if (++nxt == 3) nxt = 0;
    }

    #pragma unroll
    for (int mt = 0; mt < 2; mt++){
        int m = m0 + wm * 32 + mt * 16 + (lane >> 2);
        #pragma unroll
        for (int nt = 0; nt < 4; nt++){
            int col = n0 + wn * 32 + nt * 8 + (lane & 3) * 2;
            if (col < N){
                size_t i0 = (size_t)m * N + col;
                size_t i1 = (size_t)(m + 8) * N + col;
                float2 v0 = make_float2(acc[mt][nt][0], acc[mt][nt][1]);
                float2 v1 = make_float2(acc[mt][nt][2], acc[mt][nt][3]);
                if (R){
                    float2 r0 = *(const float2*)(R + i0);
                    float2 r1 = *(const float2*)(R + i1);
                    v0.x += r0.x; v0.y += r0.y;
                    v1.x += r1.x; v1.y += r1.y;
                }
                *(float2*)(C + i0) = v0;
                *(float2*)(C + i1) = v1;
            }
        }
    }
}

// ---------------- embedding ----------------
__global__ void k_embed(const float* __restrict__ x, const float* __restrict__ W){
    int idx = blockIdx.x * blockDim.x + threadIdx.x;
    if (idx >= NTOK * DMODEL) return;
    int t = idx / DMODEL, d = idx % DMODEL;
    float x0 = x[t*3+0]; if (x0 == -100.f) x0 = 0.f;
    float x1 = x[t*3+1]; if (x1 == -100.f) x1 = 0.f;
    float x2 = x[t*3+2]; if (x2 == -100.f) x2 = 0.f;
    float acc = x0 * W[0*DMODEL + d] + x1 * W[1*DMODEL + d] + x2 * W[2*DMODEL + d];
    if (d < 510){
        int c = d / 170, r = d % 170;
        float xv = (c == 0) ? x0 : ((c == 1) ? x1 : x2);
        float pe;
        if (r < 85) pe = sinf(xv * exp2f((float)r));
        else        pe = cosf(xv * exp2f((float)(r - 85)));
        acc += pe;
    }
    g_h[idx] = acc;
}

// ---------------- rmsnorm: float4, optional fp32 out + tiled bf16 out -------
__global__ void k_rmsnorm(const float* __restrict__ x, const float* __restrict__ w,
                          float* __restrict__ o, __nv_bfloat16* __restrict__ At, int D){
    int t = blockIdx.x;
    const float* xr = x + (size_t)t * D;
    float ss = 0.f;
    for (int d4 = threadIdx.x * 4; d4 < D; d4 += blockDim.x * 4){
        float4 v = *(const float4*)(xr + d4);
        ss += v.x*v.x + v.y*v.y + v.z*v.z + v.w*v.w;
    }
    ss = blockReduceSum(ss);
    float rs = rsqrtf(ss / (float)D + 1e-5f);
    int tile = t >> 7, r = t & 127, nkc = D >> 5;
    for (int d4 = threadIdx.x * 4; d4 < D; d4 += blockDim.x * 4){
        float4 v  = *(const float4*)(xr + d4);
        float4 wv = *(const float4*)(w + d4);
        float a = v.x*rs*wv.x, b = v.y*rs*wv.y, c = v.z*rs*wv.z, e = v.w*rs*wv.w;
        if (o) *(float4*)(o + (size_t)t * D + d4) = make_float4(a,b,c,e);
        __nv_bfloat162 h0 = __floats2bfloat162_rn(a, b);
        __nv_bfloat162 h1 = __floats2bfloat162_rn(c, e);
        float2 f0 = __bfloat1622float2(h0), f1 = __bfloat1622float2(h1);
        int kc = d4 >> 5, cc = d4 & 31;
        *(uint2*)(At + tidx(tile, nkc, kc, r, cc, 0)) = make_uint2(*(uint32_t*)&h0, *(uint32_t*)&h1);
        *(uint2*)(At + tidx(tile, nkc, kc, r, cc, 1)) = pack4bf(a-f0.x, b-f0.y, c-f1.x, e-f1.y);
    }
}

// ---------------- fused conv(4 tokens/thread)+silu and dt-cumsum ------------
__global__ void k_convdt(const float* __restrict__ cw, const float* __restrict__ cb,
                         const float* __restrict__ dtb, const float* __restrict__ Alog){
    if (blockIdx.x < NCONVB){
        int idx = blockIdx.x * 256 + threadIdx.x;
        int ch = idx % CONVDIM;
        int t0 = (idx / CONVDIM) * 4;
        int l0 = t0 % SEQL;
        float w0 = cw[ch*DCONV+0], w1 = cw[ch*DCONV+1];
        float w2 = cw[ch*DCONV+2], w3 = cw[ch*DCONV+3];
        float bb = cb[ch];
        float xb[7];
        #pragma unroll
        for (int j = 0; j < 7; j++){
            int l = l0 - 3 + j;
            xb[j] = (l >= 0) ? g_zx[(size_t)(t0 - 3 + j) * DINPROJ + DINNER + ch] : 0.f;
        }
        #pragma unroll
        for (int m = 0; m < 4; m++){
            float acc = bb + xb[m]*w0 + xb[m+1]*w1 + xb[m+2]*w2 + xb[m+3]*w3;
            g_xc[(size_t)(t0 + m) * CONVDIM + ch] = siluf(acc);
        }
    } else {
        __shared__ float sh[2][CHUNKL];
        int pr   = threadIdx.x >> 7;
        int i    = threadIdx.x & 127;
        int flat = (blockIdx.x - NCONVB) * 2 + pr;
        int bc = flat >> 4, h = flat & 15;
        int t  = bc * CHUNKL + i;
        float d = softplusf(g_zx[(size_t)t * DINPROJ + 2176 + h] + dtb[h]);
        float A = -expf(Alog[h]);
        sh[pr][i] = d * A;
        __syncthreads();
        #pragma unroll
        for (int off = 1; off < CHUNKL; off <<= 1){
            float v = (i >= off) ? sh[pr][i - off] : 0.f;
            __syncthreads();
            sh[pr][i] += v;
            __syncthreads();
        }
        g_dtv [t*NH + h] = d;
        g_acum[t*NH + h] = sh[pr][i];
        if (i == CHUNKL - 1) g_dec[flat] = expf(sh[pr][i]);
    }
}

// ---------------- fused state + scores ----------------
__global__ void k_ssd1(){
    extern __shared__ float smf[];
    int tid = threadIdx.x;
    if (blockIdx.x < NBC*NH){
        float* xsh = smf;
        float* bsh = smf + CHUNKL*HD;
        __shared__ float wsh[CHUNKL];
        __shared__ float ash_s[CHUNKL];
        int bc = blockIdx.x >> 4, h = blockIdx.x & 15;
        int t0 = bc * CHUNKL;
        for (int idx = tid; idx < CHUNKL*HD; idx += 256){
            int j = idx >> 6, q = idx & 63;
            xsh[idx] = g_xc[(size_t)(t0+j)*CONVDIM + h*HD + q];
            bsh[idx] = g_xc[(size_t)(t0+j)*CONVDIM + DINNER + q];
        }
        if (tid < CHUNKL) ash_s[tid] = g_acum[(t0 + tid)*NH + h];
        __syncthreads();
        if (tid < CHUNKL){
            float alast = ash_s[CHUNKL - 1];
            wsh[tid] = __expf(alast - ash_s[tid]) * g_dtv[(t0 + tid)*NH + h];
        }
        __syncthreads();
        float alast = ash_s[CHUNKL - 1];
        int lo = 0, hi = CHUNKL - 1;
        while (lo < hi){
            int mid = (lo + hi) >> 1;
            if (ash_s[mid] < alast + AWIN) hi = mid; else lo = mid + 1;
        }
        int p  = tid & 63;
        int n0 = (tid >> 6) << 4;
        float acc[16];
        #pragma unroll
        for (int k = 0; k < 16; k++) acc[k] = 0.f;
        for (int j = lo; j < CHUNKL; j++){
            float xw = xsh[j*HD + p] * wsh[j];
            const float* br = &bsh[j*HD + n0];
            #pragma unroll
            for (int k = 0; k < 16; k++) acc[k] += xw * br[k];
        }
        float* so = g_S + (size_t)blockIdx.x * (HD*DSTATE);
        #pragma unroll
        for (int k = 0; k < 16; k++) so[p*DSTATE + n0 + k] = acc[k];
    } else {
        int bid = blockIdx.x - NBC*NH;
        float* Csh = smf;
        float* Bsh = smf + 32*65;
        int bc = bid >> 2, q = bid & 3;
        int i0 = q * 32, jmax = i0 + 32;
        int t0 = bc * CHUNKL;
        for (int idx = tid; idx < 32*DSTATE; idx += 256){
            int i = idx >> 6, n = idx & 63;
            Csh[i*65 + n] = g_xc[(size_t)(t0+i0+i)*CONVDIM + DINNER + DSTATE + n];
        }
        for (int idx = tid; idx < jmax*DSTATE; idx += 256){
            int j = idx >> 6, n = idx & 63;
            Bsh[j*65 + n] = g_xc[(size_t)(t0+j)*CONVDIM + DINNER + n];
        }
        __syncthreads();
        int ti = (tid >> 4) * 2;
        int tj = (tid & 15) * 8;
        if (tj >= jmax) return;
        float acc[2][8];
        #pragma unroll
        for (int r = 0; r < 2; r++)
            #pragma unroll
            for (int c = 0; c < 8; c++) acc[r][c] = 0.f;
        for (int n = 0; n < DSTATE; n++){
            float a0 = Csh[(ti+0)*65 + n];
            float a1 = Csh[(ti+1)*65 + n];
            float b[8];
            #pragma unroll
            for (int c = 0; c < 8; c++) b[c] = Bsh[(tj+c)*65 + n];
            #pragma unroll
            for (int c = 0; c < 8; c++){ acc[0][c] += a0*b[c]; acc[1][c] += a1*b[c]; }
        }
        float* out = g_sc + (size_t)bc * CHUNKL * CHUNKL;
        #pragma unroll
        for (int r = 0; r < 2; r++)
            #pragma unroll
            for (int c = 0; c < 8; c++)
                out[(i0+ti+r)*CHUNKL + tj + c] = acc[r][c];
    }
}

// ---------------- scan ----------------
__global__ void k_scan(){
    int bid = blockIdx.x;
    int bh  = bid >> 4;
    int grp = bid & 15;
    int b = bh >> 4, h = bh & 15;
    int idx = grp * 256 + threadIdx.x;
    float st = 0.f;
    #pragma unroll 4
    for (int c = 0; c < NCH; c++){
        int bch = (b*NCH + c)*NH + h;
        size_t base = (size_t)bch * (HD*DSTATE);
        float dc = g_dec[bch];
        g_hs[base + idx] = st;
        st = st*dc + g_S[base + idx];
    }
}

// ---------------- fused y, 256 threads ----------------
__global__ void k_ssd_y(const float* __restrict__ Dp){
    extern __shared__ float smf[];
    float* xsh = smf;
    float* hsh = smf + CHUNKL*HD;
    __shared__ float ash[CHUNKL], dsh[CHUNKL];
    int bc = blockIdx.x >> 4, h = blockIdx.x & 15;
    int tid = threadIdx.x;
    int i  = tid & 127, ph = tid >> 7;
    int pb = ph * 32;
    int t0 = bc * CHUNKL;
    if (tid < CHUNKL){
        ash[tid] = g_acum[(t0+tid)*NH + h];
        dsh[tid] = g_dtv [(t0+tid)*NH + h];
    }
    for (int idx = tid; idx < CHUNKL*HD; idx += 256)
        xsh[idx] = g_xc[(size_t)(t0 + (idx >> 6))*CONVDIM + h*HD + (idx & 63)];
    const float* hbase = g_hs + (size_t)blockIdx.x * (HD*DSTATE);
    for (int idx = tid; idx < HD*DSTATE; idx += 256) hsh[idx] = hbase[idx];
    __syncthreads();

    float ai = ash[i];
    float Dh = Dp[h];
    float acc[32];
    #pragma unroll
    for (int p = 0; p < 32; p++) acc[p] = Dh * xsh[i*HD + pb + p];

    int lo = 0, hi = i;
    while (lo < hi){
        int mid = (lo + hi) >> 1;
        if (ash[mid] < ai + AWIN) hi = mid; else lo = mid + 1;
    }
    const float* srow = g_sc + (size_t)bc * CHUNKL * CHUNKL + (size_t)i * CHUNKL;
    for (int j = lo; j <= i; j++){
        float m = srow[j] * __expf(ai - ash[j]) * dsh[j];
        const float* xr = &xsh[j*HD + pb];
        #pragma unroll
        for (int p = 0; p < 32; p++) acc[p] += m * xr[p];
    }

    if (ai > -AWIN){
        float ei = __expf(ai);
        const float* crow = g_xc + (size_t)(t0+i)*CONVDIM + DINNER + DSTATE;
        #pragma unroll
        for (int h2 = 0; h2 < 2; h2++){
            float creg[32];
            #pragma unroll
            for (int n = 0; n < 32; n++) creg[n] = ei * crow[h2*32 + n];
            #pragma unroll 4
            for (int p = 0; p < 32; p++){
                const float4* hr = (const float4*)&hsh[(pb+p)*DSTATE + h2*32];
                float a = 0.f;
                #pragma unroll
                for (int q = 0; q < 8; q++){
                    float4 v = hr[q];
                    a += creg[q*4+0]*v.x + creg[q*4+1]*v.y + creg[q*4+2]*v.z + creg[q*4+3]*v.w;
                }
                acc[p] += a;
            }
        }
    }

    float* yrow = g_y + (size_t)(t0+i)*DINNER + h*HD + pb;
    #pragma unroll
    for (int p = 0; p < 32; p++) yrow[p] = acc[p];
}

// ---------------- gate ----------------
__global__ void k_gate(const float* __restrict__ gw, __nv_bfloat16* __restrict__ At){
    int t = blockIdx.x;
    int tid = threadIdx.x;
    int d4 = tid * 4;
    float4 zv = *(const float4*)(g_zx + (size_t)t*DINPROJ + d4);
    float4 yv = *(const float4*)(g_y  + (size_t)t*DINNER + d4);
    float v0 = yv.x * siluf(zv.x);
    float v1 = yv.y * siluf(zv.y);
    float v2 = yv.z * siluf(zv.z);
    float v3 = yv.w * siluf(zv.w);
    float ss = blockReduceSum(v0*v0 + v1*v1 + v2*v2 + v3*v3);
    float rs = rsqrtf(ss / (float)DINNER + 1e-5f);
    float4 wv = *(const float4*)(gw + d4);
    float a = v0*rs*wv.x, b = v1*rs*wv.y, c = v2*rs*wv.z, e = v3*rs*wv.w;
    __nv_bfloat162 h0 = __floats2bfloat162_rn(a, b);
    __nv_bfloat162 h1 = __floats2bfloat162_rn(c, e);
    float2 f0 = __bfloat1622float2(h0), f1 = __bfloat1622float2(h1);
    int tile = t >> 7, r = t & 127;
    int kc = d4 >> 5, cc = d4 & 31;
    *(uint2*)(At + tidx(tile, DINNER >> 5, kc, r, cc, 0)) = make_uint2(*(uint32_t*)&h0, *(uint32_t*)&h1);
    *(uint2*)(At + tidx(tile, DINNER >> 5, kc, r, cc, 1)) = pack4bf(a-f0.x, b-f0.y, c-f1.x, e-f1.y);
}

// ---------------- head ----------------
__global__ void k_head(const float* __restrict__ hw, const float* __restrict__ hb,
                       float* __restrict__ out){
    int idx = blockIdx.x * blockDim.x + threadIdx.x;
    if (idx >= NTOK * KOUT) return;
    int t = idx / KOUT, n = idx % KOUT;
    float acc = hb[n];
    const float* xr = g_xn + (size_t)t * DMODEL;
    for (int k = 0; k < DMODEL; k++) acc += xr[k] * hw[k*KOUT + n];
    out[idx] = acc;
}

// ---------------- host ----------------
extern "C" void kernel_launch(void* const* d_in, const int* in_sizes, int n_in,
                              void* d_out, int out_size){
    const float* x      = (const float*)d_in[0];
    const float* Wembed = (const float*)d_in[1];
    const float* rmsw   = (const float*)d_in[2];
    const float* inw    = (const float*)d_in[3];
    const float* convw  = (const float*)d_in[4];
    const float* convb  = (const float*)d_in[5];
    const float* dtb    = (const float*)d_in[6];
    const float* alog   = (const float*)d_in[7];
    const float* dparam = (const float*)d_in[8];
    const float* gnw    = (const float*)d_in[9];
    const float* outw   = (const float*)d_in[10];
    const float* fnw    = (const float*)d_in[11];
    const float* hw     = (const float*)d_in[12];
    const float* hb     = (const float*)d_in[13];
    float* out = (float*)d_out;

    float *p_h, *p_xn;
    cudaGetSymbolAddress((void**)&p_h,  g_h);
    cudaGetSymbolAddress((void**)&p_xn, g_xn);
    float *p_zx;
    cudaGetSymbolAddress((void**)&p_zx, g_zx);
    __nv_bfloat16 *p_ain, *p_aout, *p_win, *p_wout;
    cudaGetSymbolAddress((void**)&p_ain,  g_ain);
    cudaGetSymbolAddress((void**)&p_aout, g_aout);
    cudaGetSymbolAddress((void**)&p_win,  g_win);
    cudaGetSymbolAddress((void**)&p_wout, g_wout);

    const int SSD1_SMEM = 2*CHUNKL*HD*4;
    const int SSDY_SMEM = (CHUNKL*HD + HD*DSTATE)*4;
    const int TG_SMEM   = 3*65536;
    cudaFuncSetAttribute(k_ssd1,  cudaFuncAttributeMaxDynamicSharedMemorySize, SSD1_SMEM);
    cudaFuncSetAttribute(k_ssd_y, cudaFuncAttributeMaxDynamicSharedMemorySize, SSDY_SMEM);
    cudaFuncSetAttribute(k_tgemm, cudaFuncAttributeMaxDynamicSharedMemorySize, TG_SMEM);

    const size_t WIN_L  = (size_t)(NPAD_IN/128)*(DMODEL/32)*8192;
    const size_t WOUT_L = (size_t)(DMODEL/128)*(DINNER/32)*8192;

    k_prep<<<dim3(DMODEL/32, NPAD_IN/32, NLAYERS), dim3(32,8)>>>(
        inw, p_win, DMODEL, DINPROJ, NPAD_IN);
    k_embed<<<(NTOK*DMODEL + 255)/256, 256>>>(x, Wembed);

    for (int l = 0; l < NLAYERS; l++){
        k_rmsnorm<<<NTOK, 128>>>(p_h, rmsw + (size_t)l*DMODEL, nullptr, p_ain, DMODEL);
        k_tgemm<<<dim3(NPAD_IN/128, NTOK/128), 512, TG_SMEM>>>(
            p_ain, p_win + (size_t)l*WIN_L, p_zx, nullptr, NTOK, DINPROJ, DMODEL);
        if (l == 0)
            k_prep<<<dim3(DINNER/32, DMODEL/32, NLAYERS), dim3(32,8)>>>(
                outw, p_wout, DINNER, DMODEL, DMODEL);
        k_convdt<<<NCONVB + NDTB, 256>>>(convw + (size_t)l*CONVDIM*DCONV,
                                         convb + (size_t)l*CONVDIM,
                                         dtb + (size_t)l*NH, alog + (size_t)l*NH);
        k_ssd1<<<NBC*NH + NBC*4, 256, SSD1_SMEM>>>();
        k_scan<<<BSZ*NH*16, 256>>>();
        k_ssd_y<<<NBC*NH, 256, SSDY_SMEM>>>(dparam + (size_t)l*NH);
        k_gate<<<NTOK, 256>>>(gnw + (size_t)l*DINNER, p_aout);
        k_tgemm<<<dim3(DMODEL/128, NTOK/128), 512, TG_SMEM>>>(
            p_aout, p_wout + (size_t)l*WOUT_L, p_h, p_h, NTOK, DMODEL, DINNER);
    }

    k_rmsnorm<<<NTOK, 128>>>(p_h, fnw, p_xn, p_ain, DMODEL);
    k_head<<<(NTOK*KOUT + 255)/256, 256>>>(hw, hb, out);
}

// round 14
// speedup vs baseline: 1.6566x; 1.0409x over previous
#include <cuda_runtime.h>
#include <cuda_bf16.h>
#include <math.h>
#include <stdint.h>

// ---------------- problem constants ----------------
#define BSZ     2
#define SEQL    2048
#define NTOK    (BSZ*SEQL)        // 4096
#define DMODEL  512
#define DINNER  1024
#define NH      16
#define HD      64
#define DSTATE  64
#define DCONV   4
#define CONVDIM 1152
#define DINPROJ 2192
#define NPAD_IN 2304
#define NLAYERS 12
#define CHUNKL  128
#define NCH     16
#define NBC     (BSZ*NCH)         // 32
#define KOUT    30
#define AWIN    16.0f
#define NCONVB  ((NTOK/4*CONVDIM)/256)
#define NDTB    ((NBC*NH)/2)

// ---------------- scratch ----------
__device__ float g_h   [NTOK*DMODEL];
__device__ float g_xn  [NTOK*DMODEL];
__device__ float g_zx  [NTOK*DINPROJ];
__device__ float g_xc  [NTOK*CONVDIM];
__device__ float g_dtv [NTOK*NH];
__device__ float g_acum[NTOK*NH];
__device__ float g_dec [NBC*NH];
__device__ float g_sc  [NBC*CHUNKL*CHUNKL];
__device__ float g_y   [NTOK*DINNER];
__device__ float g_S   [NBC*NH*HD*DSTATE];
__device__ float g_hs  [NBC*NH*HD*DSTATE];
__device__ __align__(128) __nv_bfloat16 g_ain [(NTOK/128)*(DMODEL/32)*8192];
__device__ __align__(128) __nv_bfloat16 g_aout[(NTOK/128)*(DINNER/32)*8192];
__device__ __align__(128) __nv_bfloat16 g_win [NLAYERS*(NPAD_IN/128)*(DMODEL/32)*8192];
__device__ __align__(128) __nv_bfloat16 g_wout[NLAYERS*(DMODEL/128)*(DINNER/32)*8192];

// ---------------- helpers ----------------
__device__ __forceinline__ uint32_t s2u(const void* p){
    uint32_t a;
    asm("{ .reg .u64 t; cvta.to.shared.u64 t, %1; cvt.u32.u64 %0, t; }" : "=r"(a) : "l"(p));
    return a;
}
__device__ __forceinline__ void ldsm4(uint32_t* r, uint32_t a){
    asm volatile("ldmatrix.sync.aligned.m8n8.x4.shared.b16 {%0,%1,%2,%3}, [%4];"
        : "=r"(r[0]), "=r"(r[1]), "=r"(r[2]), "=r"(r[3]) : "r"(a));
}
__device__ __forceinline__ void mma16816(float* d, const uint32_t* a, uint32_t b0, uint32_t b1){
    asm volatile("mma.sync.aligned.m16n8k16.row.col.f32.bf16.bf16.f32 "
        "{%0,%1,%2,%3}, {%4,%5,%6,%7}, {%8,%9}, {%0,%1,%2,%3};"
        : "+f"(d[0]), "+f"(d[1]), "+f"(d[2]), "+f"(d[3])
        : "r"(a[0]), "r"(a[1]), "r"(a[2]), "r"(a[3]), "r"(b0), "r"(b1));
}
__device__ __forceinline__ void mbar_init(uint32_t m, uint32_t cnt){
    asm volatile("mbarrier.init.shared.b64 [%0], %1;" :: "r"(m), "r"(cnt) : "memory");
}
__device__ __forceinline__ void mbar_expect(uint32_t m, uint32_t bytes){
    asm volatile("mbarrier.arrive.expect_tx.shared.b64 _, [%0], %1;" :: "r"(m), "r"(bytes) : "memory");
}
__device__ __forceinline__ void mbar_wait(uint32_t m, uint32_t phase){
    asm volatile(
        "{\n\t.reg .pred P;\n\t"
        "WL_%=:\n\t"
        "mbarrier.try_wait.parity.acquire.cta.shared::cta.b64 P, [%0], %1, 0x989680;\n\t"
        "@P bra.uni WD_%=;\n\t"
        "bra.uni WL_%=;\n\t"
        "WD_%=:\n\t}"
        :: "r"(m), "r"(phase) : "memory");
}
__device__ __forceinline__ void bulkcp32k(uint32_t sdst, const void* gsrc, uint32_t mbar){
    uint64_t ga;
    asm("cvta.to.global.u64 %0, %1;" : "=l"(ga) : "l"(gsrc));
    asm volatile("cp.async.bulk.shared::cluster.global.mbarrier::complete_tx::bytes [%0], [%1], %2, [%3];"
        :: "r"(sdst), "l"(ga), "r"(32768u), "r"(mbar) : "memory");
}
__device__ __forceinline__ void fence_async(){
    asm volatile("fence.proxy.async.shared::cta;" ::: "memory");
}

__device__ __forceinline__ float softplusf(float x){
    return (x > 20.f) ? x : log1pf(expf(x));
}
__device__ __forceinline__ float siluf(float x){
    return x / (1.f + expf(-x));
}
__device__ __forceinline__ float blockReduceSum(float v){
    __shared__ float sh[32];
    #pragma unroll
    for (int o = 16; o; o >>= 1) v += __shfl_xor_sync(0xffffffffu, v, o);
    int w = threadIdx.x >> 5;
    if ((threadIdx.x & 31) == 0) sh[w] = v;
    __syncthreads();
    int nw = blockDim.x >> 5;
    float r = (threadIdx.x < nw) ? sh[threadIdx.x] : 0.f;
    if (w == 0){
        #pragma unroll
        for (int o = 16; o; o >>= 1) r += __shfl_xor_sync(0xffffffffu, r, o);
        if (threadIdx.x == 0) sh[0] = r;
    }
    __syncthreads();
    return sh[0];
}

// tiled layout index (block 8192 elems = 128 rows x 64 cols bf16, swizzled)
__device__ __forceinline__ size_t tidx(int tile, int nkc, int kc, int r, int c, int part){
    int s = c >> 3, e = c & 7;
    return (((size_t)tile * nkc + kc) << 13) + (size_t)(r * 64) +
           (size_t)((((part * 4 + s) ^ (r & 7))) << 3) + e;
}
__device__ __forceinline__ uint2 pack4bf(float a, float b, float c, float d){
    __nv_bfloat162 p0 = __floats2bfloat162_rn(a, b);
    __nv_bfloat162 p1 = __floats2bfloat162_rn(c, d);
    return make_uint2(*(uint32_t*)&p0, *(uint32_t*)&p1);
}

// ---------------- weight prep ----------------
__global__ void k_prep(const float* __restrict__ W, __nv_bfloat16* __restrict__ Wt,
                       int K, int N, int Npad){
    int l = blockIdx.z;
    W  += (size_t)l * K * N;
    Wt += (size_t)l * (Npad >> 7) * (K >> 5) * 8192;
    __shared__ float t[32][33];
    int k0 = blockIdx.x * 32, n0 = blockIdx.y * 32;
    int tx = threadIdx.x, ty = threadIdx.y;
    int nkc = K >> 5;
    for (int i = ty; i < 32; i += 8){
        float v = 0.f;
        if (n0 + tx < N) v = W[(size_t)(k0 + i) * N + n0 + tx];
        t[i][tx] = v;
    }
    __syncthreads();
    for (int i = ty; i < 32; i += 8){
        float v = t[tx][i];
        __nv_bfloat16 hi = __float2bfloat16_rn(v);
        float lo = v - __bfloat162float(hi);
        int n = n0 + i, k = k0 + tx;
        int tile = n >> 7, r = n & 127, kc = k >> 5, c = k & 31;
        Wt[tidx(tile, nkc, kc, r, c, 0)] = hi;
        Wt[tidx(tile, nkc, kc, r, c, 1)] = __float2bfloat16_rn(lo);
    }
}

// ---------------- GEMM: bulk copy, 3 stages x 64KB, frag double-buffer ------
__global__ void __launch_bounds__(512, 1)
k_tgemm(const __nv_bfloat16* __restrict__ At, const __nv_bfloat16* __restrict__ Bt,
        float* __restrict__ C, const float* __restrict__ R,
        int M, int N, int K)
{
    extern __shared__ char smc[];
    __shared__ __align__(8) uint64_t mbarr[3];
    uint32_t sb  = s2u(smc);
    uint32_t mb0 = s2u(mbarr);
    int tid  = threadIdx.x;
    int lane = tid & 31, w = tid >> 5;
    int wm = w & 3, wn = w >> 2;
    int m0 = blockIdx.y * 128, n0 = blockIdx.x * 128;
    int nkc  = K >> 5;
    int nit  = K >> 6;
    const __nv_bfloat16* gA = At + (((size_t)blockIdx.y * nkc) << 13);
    const __nv_bfloat16* gB = Bt + (((size_t)blockIdx.x * nkc) << 13);

    if (tid == 0){
        #pragma unroll
        for (int s = 0; s < 3; s++) mbar_init(mb0 + s * 8, 1);
    }
    __syncthreads();
    if (tid == 0){
        #pragma unroll
        for (int s = 0; s < 2; s++){
            if (s < nit){
                mbar_expect(mb0 + s * 8, 65536u);
                bulkcp32k(sb + s * 65536u,          gA + ((size_t)(s * 2) << 13), mb0 + s * 8);
                bulkcp32k(sb + s * 65536u + 32768u, gB + ((size_t)(s * 2) << 13), mb0 + s * 8);
            }
        }
    }

    float acc[2][4][4];
    #pragma unroll
    for (int mt = 0; mt < 2; mt++)
        #pragma unroll
        for (int nt = 0; nt < 4; nt++)
            #pragma unroll
            for (int e = 0; e < 4; e++) acc[mt][nt][e] = 0.f;

    uint32_t aoff = sb + (uint32_t)((wm * 32 + (lane & 15)) * 128);
    uint32_t boff = sb + 32768u + (uint32_t)((wn * 32 + (lane & 15)) * 128);
    uint32_t ct[2][2];
    #pragma unroll
    for (int part = 0; part < 2; part++)
        #pragma unroll
        for (int kh = 0; kh < 2; kh++)
            ct[part][kh] = (uint32_t)((((part * 4 + 2 * kh + (lane >> 4))) ^ (lane & 7)) * 16);

    // fragment double-buffer: [buf][8 ldsm groups][4 regs]
    // groups: 0-1 ah(mt0,mt1), 2-3 al, 4-5 bh(g0,g1), 6-7 bl
    uint32_t fr[2][8][4];
    #define LOADF(BUF, BUFO, KH) do {                                           \
        uint32_t blko = (uint32_t)(((KH) >> 1) * 16384);                        \
        int khl = (KH) & 1;                                                     \
        _Pragma("unroll")                                                       \
        for (int mt = 0; mt < 2; mt++){                                         \
            uint32_t base = aoff + (BUFO) + blko + (uint32_t)(mt * 2048);       \
            ldsm4(fr[BUF][0 + mt], base + ct[0][khl]);                          \
            ldsm4(fr[BUF][2 + mt], base + ct[1][khl]);                          \
        }                                                                       \
        _Pragma("unroll")                                                       \
        for (int g = 0; g < 2; g++){                                            \
            uint32_t base = boff + (BUFO) + blko + (uint32_t)(g * 2048);        \
            ldsm4(fr[BUF][4 + g], base + ct[0][khl]);                           \
            ldsm4(fr[BUF][6 + g], base + ct[1][khl]);                           \
        }                                                                       \
    } while(0)
    #define MMAF(BUF) do {                                                      \
        _Pragma("unroll")                                                       \
        for (int mt = 0; mt < 2; mt++)                                          \
            _Pragma("unroll")                                                   \
            for (int nt = 0; nt < 4; nt++){                                     \
                int g = nt >> 1, s = nt & 1;                                    \
                mma16816(acc[mt][nt], fr[BUF][0+mt], fr[BUF][4+g][s], fr[BUF][4+g][s+2]); \
                mma16816(acc[mt][nt], fr[BUF][0+mt], fr[BUF][6+g][s], fr[BUF][6+g][s+2]); \
                mma16816(acc[mt][nt], fr[BUF][2+mt], fr[BUF][4+g][s], fr[BUF][4+g][s+2]); \
            }                                                                   \
    } while(0)

    int cur = 0, nxt = 2;
    uint32_t phase = 0;
    for (int it = 0; it < nit; it++){
        mbar_wait(mb0 + (uint32_t)cur * 8, phase);
        __syncthreads();
        if (tid == 0 && it + 2 < nit){
            fence_async();
            mbar_expect(mb0 + (uint32_t)nxt * 8, 65536u);
            bulkcp32k(sb + (uint32_t)nxt * 65536u,          gA + ((size_t)((it + 2) * 2) << 13), mb0 + (uint32_t)nxt * 8);
            bulkcp32k(sb + (uint32_t)nxt * 65536u + 32768u, gB + ((size_t)((it + 2) * 2) << 13), mb0 + (uint32_t)nxt * 8);
        }

        uint32_t bufo = (uint32_t)cur * 65536u;
        LOADF(0, bufo, 0);
        LOADF(1, bufo, 1);
        MMAF(0);
        LOADF(0, bufo, 2);
        MMAF(1);
        LOADF(1, bufo, 3);
        MMAF(0);
        MMAF(1);

        if (++cur == 3){ cur = 0; phase ^= 1; }
        if (++nxt == 3) nxt = 0;
    }

    #pragma unroll
    for (int mt = 0; mt < 2; mt++){
        int m = m0 + wm * 32 + mt * 16 + (lane >> 2);
        #pragma unroll
        for (int nt = 0; nt < 4; nt++){
            int col = n0 + wn * 32 + nt * 8 + (lane & 3) * 2;
            if (col < N){
                size_t i0 = (size_t)m * N + col;
                size_t i1 = (size_t)(m + 8) * N + col;
                float2 v0 = make_float2(acc[mt][nt][0], acc[mt][nt][1]);
                float2 v1 = make_float2(acc[mt][nt][2], acc[mt][nt][3]);
                if (R){
                    float2 r0 = *(const float2*)(R + i0);
                    float2 r1 = *(const float2*)(R + i1);
                    v0.x += r0.x; v0.y += r0.y;
                    v1.x += r1.x; v1.y += r1.y;
                }
                *(float2*)(C + i0) = v0;
                *(float2*)(C + i1) = v1;
            }
        }
    }
}

// ---------------- embedding ----------------
__global__ void k_embed(const float* __restrict__ x, const float* __restrict__ W){
    int idx = blockIdx.x * blockDim.x + threadIdx.x;
    if (idx >= NTOK * DMODEL) return;
    int t = idx / DMODEL, d = idx % DMODEL;
    float x0 = x[t*3+0]; if (x0 == -100.f) x0 = 0.f;
    float x1 = x[t*3+1]; if (x1 == -100.f) x1 = 0.f;
    float x2 = x[t*3+2]; if (x2 == -100.f) x2 = 0.f;
    float acc = x0 * W[0*DMODEL + d] + x1 * W[1*DMODEL + d] + x2 * W[2*DMODEL + d];
    if (d < 510){
        int c = d / 170, r = d % 170;
        float xv = (c == 0) ? x0 : ((c == 1) ? x1 : x2);
        float pe;
        if (r < 85) pe = sinf(xv * exp2f((float)r));
        else        pe = cosf(xv * exp2f((float)(r - 85)));
        acc += pe;
    }
    g_h[idx] = acc;
}

// ---------------- rmsnorm ----------------
__global__ void k_rmsnorm(const float* __restrict__ x, const float* __restrict__ w,
                          float* __restrict__ o, __nv_bfloat16* __restrict__ At, int D){
    int t = blockIdx.x;
    const float* xr = x + (size_t)t * D;
    float ss = 0.f;
    for (int d4 = threadIdx.x * 4; d4 < D; d4 += blockDim.x * 4){
        float4 v = *(const float4*)(xr + d4);
        ss += v.x*v.x + v.y*v.y + v.z*v.z + v.w*v.w;
    }
    ss = blockReduceSum(ss);
    float rs = rsqrtf(ss / (float)D + 1e-5f);
    int tile = t >> 7, r = t & 127, nkc = D >> 5;
    for (int d4 = threadIdx.x * 4; d4 < D; d4 += blockDim.x * 4){
        float4 v  = *(const float4*)(xr + d4);
        float4 wv = *(const float4*)(w + d4);
        float a = v.x*rs*wv.x, b = v.y*rs*wv.y, c = v.z*rs*wv.z, e = v.w*rs*wv.w;
        if (o) *(float4*)(o + (size_t)t * D + d4) = make_float4(a,b,c,e);
        __nv_bfloat162 h0 = __floats2bfloat162_rn(a, b);
        __nv_bfloat162 h1 = __floats2bfloat162_rn(c, e);
        float2 f0 = __bfloat1622float2(h0), f1 = __bfloat1622float2(h1);
        int kc = d4 >> 5, cc = d4 & 31;
        *(uint2*)(At + tidx(tile, nkc, kc, r, cc, 0)) = make_uint2(*(uint32_t*)&h0, *(uint32_t*)&h1);
        *(uint2*)(At + tidx(tile, nkc, kc, r, cc, 1)) = pack4bf(a-f0.x, b-f0.y, c-f1.x, e-f1.y);
    }
}

// ---------------- fused conv(4 tokens/thread)+silu and dt-cumsum ------------
__global__ void k_convdt(const float* __restrict__ cw, const float* __restrict__ cb,
                         const float* __restrict__ dtb, const float* __restrict__ Alog){
    if (blockIdx.x < NCONVB){
        int idx = blockIdx.x * 256 + threadIdx.x;
        int ch = idx % CONVDIM;
        int t0 = (idx / CONVDIM) * 4;
        int l0 = t0 % SEQL;
        float w0 = cw[ch*DCONV+0], w1 = cw[ch*DCONV+1];
        float w2 = cw[ch*DCONV+2], w3 = cw[ch*DCONV+3];
        float bb = cb[ch];
        float xb[7];
        #pragma unroll
        for (int j = 0; j < 7; j++){
            int l = l0 - 3 + j;
            xb[j] = (l >= 0) ? g_zx[(size_t)(t0 - 3 + j) * DINPROJ + DINNER + ch] : 0.f;
        }
        #pragma unroll
        for (int m = 0; m < 4; m++){
            float acc = bb + xb[m]*w0 + xb[m+1]*w1 + xb[m+2]*w2 + xb[m+3]*w3;
            g_xc[(size_t)(t0 + m) * CONVDIM + ch] = siluf(acc);
        }
    } else {
        __shared__ float sh[2][CHUNKL];
        int pr   = threadIdx.x >> 7;
        int i    = threadIdx.x & 127;
        int flat = (blockIdx.x - NCONVB) * 2 + pr;
        int bc = flat >> 4, h = flat & 15;
        int t  = bc * CHUNKL + i;
        float d = softplusf(g_zx[(size_t)t * DINPROJ + 2176 + h] + dtb[h]);
        float A = -expf(Alog[h]);
        sh[pr][i] = d * A;
        __syncthreads();
        #pragma unroll
        for (int off = 1; off < CHUNKL; off <<= 1){
            float v = (i >= off) ? sh[pr][i - off] : 0.f;
            __syncthreads();
            sh[pr][i] += v;
            __syncthreads();
        }
        g_dtv [t*NH + h] = d;
        g_acum[t*NH + h] = sh[pr][i];
        if (i == CHUNKL - 1) g_dec[flat] = expf(sh[pr][i]);
    }
}

// ---------------- fused state + scores ----------------
__global__ void k_ssd1(){
    extern __shared__ float smf[];
    int tid = threadIdx.x;
    if (blockIdx.x < NBC*NH){
        float* xsh = smf;
        float* bsh = smf + CHUNKL*HD;
        __shared__ float wsh[CHUNKL];
        __shared__ float ash_s[CHUNKL];
        int bc = blockIdx.x >> 4, h = blockIdx.x & 15;
        int t0 = bc * CHUNKL;
        for (int idx = tid; idx < CHUNKL*HD; idx += 256){
            int j = idx >> 6, q = idx & 63;
            xsh[idx] = g_xc[(size_t)(t0+j)*CONVDIM + h*HD + q];
            bsh[idx] = g_xc[(size_t)(t0+j)*CONVDIM + DINNER + q];
        }
        if (tid < CHUNKL) ash_s[tid] = g_acum[(t0 + tid)*NH + h];
        __syncthreads();
        if (tid < CHUNKL){
            float alast = ash_s[CHUNKL - 1];
            wsh[tid] = __expf(alast - ash_s[tid]) * g_dtv[(t0 + tid)*NH + h];
        }
        __syncthreads();
        float alast = ash_s[CHUNKL - 1];
        int lo = 0, hi = CHUNKL - 1;
        while (lo < hi){
            int mid = (lo + hi) >> 1;
            if (ash_s[mid] < alast + AWIN) hi = mid; else lo = mid + 1;
        }
        int p  = tid & 63;
        int n0 = (tid >> 6) << 4;
        float acc[16];
        #pragma unroll
        for (int k = 0; k < 16; k++) acc[k] = 0.f;
        for (int j = lo; j < CHUNKL; j++){
            float xw = xsh[j*HD + p] * wsh[j];
            const float* br = &bsh[j*HD + n0];
            #pragma unroll
            for (int k = 0; k < 16; k++) acc[k] += xw * br[k];
        }
        float* so = g_S + (size_t)blockIdx.x * (HD*DSTATE);
        #pragma unroll
        for (int k = 0; k < 16; k++) so[p*DSTATE + n0 + k] = acc[k];
    } else {
        int bid = blockIdx.x - NBC*NH;
        float* Csh = smf;
        float* Bsh = smf + 32*65;
        int bc = bid >> 2, q = bid & 3;
        int i0 = q * 32, jmax = i0 + 32;
        int t0 = bc * CHUNKL;
        for (int idx = tid; idx < 32*DSTATE; idx += 256){
            int i = idx >> 6, n = idx & 63;
            Csh[i*65 + n] = g_xc[(size_t)(t0+i0+i)*CONVDIM + DINNER + DSTATE + n];
        }
        for (int idx = tid; idx < jmax*DSTATE; idx += 256){
            int j = idx >> 6, n = idx & 63;
            Bsh[j*65 + n] = g_xc[(size_t)(t0+j)*CONVDIM + DINNER + n];
        }
        __syncthreads();
        int ti = (tid >> 4) * 2;
        int tj = (tid & 15) * 8;
        if (tj >= jmax) return;
        float acc[2][8];
        #pragma unroll
        for (int r = 0; r < 2; r++)
            #pragma unroll
            for (int c = 0; c < 8; c++) acc[r][c] = 0.f;
        for (int n = 0; n < DSTATE; n++){
            float a0 = Csh[(ti+0)*65 + n];
            float a1 = Csh[(ti+1)*65 + n];
            float b[8];
            #pragma unroll
            for (int c = 0; c < 8; c++) b[c] = Bsh[(tj+c)*65 + n];
            #pragma unroll
            for (int c = 0; c < 8; c++){ acc[0][c] += a0*b[c]; acc[1][c] += a1*b[c]; }
        }
        float* out = g_sc + (size_t)bc * CHUNKL * CHUNKL;
        #pragma unroll
        for (int r = 0; r < 2; r++)
            #pragma unroll
            for (int c = 0; c < 8; c++)
                out[(i0+ti+r)*CHUNKL + tj + c] = acc[r][c];
    }
}

// ---------------- scan ----------------
__global__ void k_scan(){
    int bid = blockIdx.x;
    int bh  = bid >> 4;
    int grp = bid & 15;
    int b = bh >> 4, h = bh & 15;
    int idx = grp * 256 + threadIdx.x;
    float st = 0.f;
    #pragma unroll 4
    for (int c = 0; c < NCH; c++){
        int bch = (b*NCH + c)*NH + h;
        size_t base = (size_t)bch * (HD*DSTATE);
        float dc = g_dec[bch];
        g_hs[base + idx] = st;
        st = st*dc + g_S[base + idx];
    }
}

// ---------------- fused y, 256 threads ----------------
__global__ void k_ssd_y(const float* __restrict__ Dp){
    extern __shared__ float smf[];
    float* xsh = smf;
    float* hsh = smf + CHUNKL*HD;
    __shared__ float ash[CHUNKL], dsh[CHUNKL];
    int bc = blockIdx.x >> 4, h = blockIdx.x & 15;
    int tid = threadIdx.x;
    int i  = tid & 127, ph = tid >> 7;
    int pb = ph * 32;
    int t0 = bc * CHUNKL;
    if (tid < CHUNKL){
        ash[tid] = g_acum[(t0+tid)*NH + h];
        dsh[tid] = g_dtv [(t0+tid)*NH + h];
    }
    for (int idx = tid; idx < CHUNKL*HD; idx += 256)
        xsh[idx] = g_xc[(size_t)(t0 + (idx >> 6))*CONVDIM + h*HD + (idx & 63)];
    const float* hbase = g_hs + (size_t)blockIdx.x * (HD*DSTATE);
    for (int idx = tid; idx < HD*DSTATE; idx += 256) hsh[idx] = hbase[idx];
    __syncthreads();

    float ai = ash[i];
    float Dh = Dp[h];
    float acc[32];
    #pragma unroll
    for (int p = 0; p < 32; p++) acc[p] = Dh * xsh[i*HD + pb + p];

    int lo = 0, hi = i;
    while (lo < hi){
        int mid = (lo + hi) >> 1;
        if (ash[mid] < ai + AWIN) hi = mid; else lo = mid + 1;
    }
    const float* srow = g_sc + (size_t)bc * CHUNKL * CHUNKL + (size_t)i * CHUNKL;
    for (int j = lo; j <= i; j++){
        float m = srow[j] * __expf(ai - ash[j]) * dsh[j];
        const float* xr = &xsh[j*HD + pb];
        #pragma unroll
        for (int p = 0; p < 32; p++) acc[p] += m * xr[p];
    }

    if (ai > -AWIN){
        float ei = __expf(ai);
        const float* crow = g_xc + (size_t)(t0+i)*CONVDIM + DINNER + DSTATE;
        #pragma unroll
        for (int h2 = 0; h2 < 2; h2++){
            float creg[32];
            #pragma unroll
            for (int n = 0; n < 32; n++) creg[n] = ei * crow[h2*32 + n];
            #pragma unroll 4
            for (int p = 0; p < 32; p++){
                const float4* hr = (const float4*)&hsh[(pb+p)*DSTATE + h2*32];
                float a = 0.f;
                #pragma unroll
                for (int q = 0; q < 8; q++){
                    float4 v = hr[q];
                    a += creg[q*4+0]*v.x + creg[q*4+1]*v.y + creg[q*4+2]*v.z + creg[q*4+3]*v.w;
                }
                acc[p] += a;
            }
        }
    }

    float* yrow = g_y + (size_t)(t0+i)*DINNER + h*HD + pb;
    #pragma unroll
    for (int p = 0; p < 32; p++) yrow[p] = acc[p];
}

// ---------------- gate ----------------
__global__ void k_gate(const float* __restrict__ gw, __nv_bfloat16* __restrict__ At){
    int t = blockIdx.x;
    int tid = threadIdx.x;
    int d4 = tid * 4;
    float4 zv = *(const float4*)(g_zx + (size_t)t*DINPROJ + d4);
    float4 yv = *(const float4*)(g_y  + (size_t)t*DINNER + d4);
    float v0 = yv.x * siluf(zv.x);
    float v1 = yv.y * siluf(zv.y);
    float v2 = yv.z * siluf(zv.z);
    float v3 = yv.w * siluf(zv.w);
    float ss = blockReduceSum(v0*v0 + v1*v1 + v2*v2 + v3*v3);
    float rs = rsqrtf(ss / (float)DINNER + 1e-5f);
    float4 wv = *(const float4*)(gw + d4);
    float a = v0*rs*wv.x, b = v1*rs*wv.y, c = v2*rs*wv.z, e = v3*rs*wv.w;
    __nv_bfloat162 h0 = __floats2bfloat162_rn(a, b);
    __nv_bfloat162 h1 = __floats2bfloat162_rn(c, e);
    float2 f0 = __bfloat1622float2(h0), f1 = __bfloat1622float2(h1);
    int tile = t >> 7, r = t & 127;
    int kc = d4 >> 5, cc = d4 & 31;
    *(uint2*)(At + tidx(tile, DINNER >> 5, kc, r, cc, 0)) = make_uint2(*(uint32_t*)&h0, *(uint32_t*)&h1);
    *(uint2*)(At + tidx(tile, DINNER >> 5, kc, r, cc, 1)) = pack4bf(a-f0.x, b-f0.y, c-f1.x, e-f1.y);
}

// ---------------- head ----------------
__global__ void k_head(const float* __restrict__ hw, const float* __restrict__ hb,
                       float* __restrict__ out){
    int idx = blockIdx.x * blockDim.x + threadIdx.x;
    if (idx >= NTOK * KOUT) return;
    int t = idx / KOUT, n = idx % KOUT;
    float acc = hb[n];
    const float* xr = g_xn + (size_t)t * DMODEL;
    for (int k = 0; k < DMODEL; k++) acc += xr[k] * hw[k*KOUT + n];
    out[idx] = acc;
}

// ---------------- host ----------------
extern "C" void kernel_launch(void* const* d_in, const int* in_sizes, int n_in,
                              void* d_out, int out_size){
    const float* x      = (const float*)d_in[0];
    const float* Wembed = (const float*)d_in[1];
    const float* rmsw   = (const float*)d_in[2];
    const float* inw    = (const float*)d_in[3];
    const float* convw  = (const float*)d_in[4];
    const float* convb  = (const float*)d_in[5];
    const float* dtb    = (const float*)d_in[6];
    const float* alog   = (const float*)d_in[7];
    const float* dparam = (const float*)d_in[8];
    const float* gnw    = (const float*)d_in[9];
    const float* outw   = (const float*)d_in[10];
    const float* fnw    = (const float*)d_in[11];
    const float* hw     = (const float*)d_in[12];
    const float* hb     = (const float*)d_in[13];
    float* out = (float*)d_out;

    float *p_h, *p_xn;
    cudaGetSymbolAddress((void**)&p_h,  g_h);
    cudaGetSymbolAddress((void**)&p_xn, g_xn);
    float *p_zx;
    cudaGetSymbolAddress((void**)&p_zx, g_zx);
    __nv_bfloat16 *p_ain, *p_aout, *p_win, *p_wout;
    cudaGetSymbolAddress((void**)&p_ain,  g_ain);
    cudaGetSymbolAddress((void**)&p_aout, g_aout);
    cudaGetSymbolAddress((void**)&p_win,  g_win);
    cudaGetSymbolAddress((void**)&p_wout, g_wout);

    const int SSD1_SMEM = 2*CHUNKL*HD*4;
    const int SSDY_SMEM = (CHUNKL*HD + HD*DSTATE)*4;
    const int TG_SMEM   = 3*65536;
    cudaFuncSetAttribute(k_ssd1,  cudaFuncAttributeMaxDynamicSharedMemorySize, SSD1_SMEM);
    cudaFuncSetAttribute(k_ssd_y, cudaFuncAttributeMaxDynamicSharedMemorySize, SSDY_SMEM);
    cudaFuncSetAttribute(k_tgemm, cudaFuncAttributeMaxDynamicSharedMemorySize, TG_SMEM);

    const size_t WIN_L  = (size_t)(NPAD_IN/128)*(DMODEL/32)*8192;
    const size_t WOUT_L = (size_t)(DMODEL/128)*(DINNER/32)*8192;

    k_prep<<<dim3(DMODEL/32, NPAD_IN/32, NLAYERS), dim3(32,8)>>>(
        inw, p_win, DMODEL, DINPROJ, NPAD_IN);
    k_embed<<<(NTOK*DMODEL + 255)/256, 256>>>(x, Wembed);

    for (int l = 0; l < NLAYERS; l++){
        k_rmsnorm<<<NTOK, 128>>>(p_h, rmsw + (size_t)l*DMODEL, nullptr, p_ain, DMODEL);
        k_tgemm<<<dim3(NPAD_IN/128, NTOK/128), 512, TG_SMEM>>>(
            p_ain, p_win + (size_t)l*WIN_L, p_zx, nullptr, NTOK, DINPROJ, DMODEL);
        if (l == 0)
            k_prep<<<dim3(DINNER/32, DMODEL/32, NLAYERS), dim3(32,8)>>>(
                outw, p_wout, DINNER, DMODEL, DMODEL);
        k_convdt<<<NCONVB + NDTB, 256>>>(convw + (size_t)l*CONVDIM*DCONV,
                                         convb + (size_t)l*CONVDIM,
                                         dtb + (size_t)l*NH, alog + (size_t)l*NH);
        k_ssd1<<<NBC*NH + NBC*4, 256, SSD1_SMEM>>>();
        k_scan<<<BSZ*NH*16, 256>>>();
        k_ssd_y<<<NBC*NH, 256, SSDY_SMEM>>>(dparam + (size_t)l*NH);
        k_gate<<<NTOK, 256>>>(gnw + (size_t)l*DINNER, p_aout);
        k_tgemm<<<dim3(DMODEL/128, NTOK/128), 512, TG_SMEM>>>(
            p_aout, p_wout + (size_t)l*WOUT_L, p_h, p_h, NTOK, DMODEL, DINNER);
    }

    k_rmsnorm<<<NTOK, 128>>>(p_h, fnw, p_xn, p_ain, DMODEL);
    k_head<<<(NTOK*KOUT + 255)/256, 256>>>(hw, hb, out);
}

// round 15
// speedup vs baseline: 1.7422x; 1.0517x over previous
#include <cuda_runtime.h>
#include <cuda_bf16.h>
#include <math.h>
#include <stdint.h>

// ---------------- problem constants ----------------
#define BSZ     2
#define SEQL    2048
#define NTOK    (BSZ*SEQL)        // 4096
#define DMODEL  512
#define DINNER  1024
#define NH      16
#define HD      64
#define DSTATE  64
#define DCONV   4
#define CONVDIM 1152
#define DINPROJ 2192
#define NPAD_IN 2304
#define NLAYERS 12
#define CHUNKL  128
#define NCH     16
#define NBC     (BSZ*NCH)         // 32
#define KOUT    30
#define AWIN    12.0f
#define NCONVB  ((NTOK/4*CONVDIM)/256)
#define NDTB    ((NBC*NH)/2)

// ---------------- scratch ----------
__device__ float g_h   [NTOK*DMODEL];
__device__ float g_xn  [NTOK*DMODEL];
__device__ float g_zx  [NTOK*DINPROJ];
__device__ float g_xc  [NTOK*CONVDIM];
__device__ float g_dtv [NTOK*NH];
__device__ float g_acum[NTOK*NH];
__device__ float g_dec [NBC*NH];
__device__ float g_sc  [NBC*CHUNKL*CHUNKL];
__device__ float g_y   [NTOK*DINNER];
__device__ float g_S   [NBC*NH*HD*DSTATE];
__device__ float g_hs  [NBC*NH*HD*DSTATE];
__device__ __align__(128) __nv_bfloat16 g_ain [(NTOK/128)*(DMODEL/32)*8192];
__device__ __align__(128) __nv_bfloat16 g_aout[(NTOK/128)*(DINNER/32)*8192];
__device__ __align__(128) __nv_bfloat16 g_win [NLAYERS*(NPAD_IN/128)*(DMODEL/32)*8192];
__device__ __align__(128) __nv_bfloat16 g_wout[NLAYERS*(DMODEL/128)*(DINNER/32)*8192];

// ---------------- helpers ----------------
__device__ __forceinline__ uint32_t s2u(const void* p){
    uint32_t a;
    asm("{ .reg .u64 t; cvta.to.shared.u64 t, %1; cvt.u32.u64 %0, t; }" : "=r"(a) : "l"(p));
    return a;
}
__device__ __forceinline__ void ldsm4(uint32_t* r, uint32_t a){
    asm volatile("ldmatrix.sync.aligned.m8n8.x4.shared.b16 {%0,%1,%2,%3}, [%4];"
        : "=r"(r[0]), "=r"(r[1]), "=r"(r[2]), "=r"(r[3]) : "r"(a));
}
__device__ __forceinline__ void mma16816(float* d, const uint32_t* a, uint32_t b0, uint32_t b1){
    asm volatile("mma.sync.aligned.m16n8k16.row.col.f32.bf16.bf16.f32 "
        "{%0,%1,%2,%3}, {%4,%5,%6,%7}, {%8,%9}, {%0,%1,%2,%3};"
        : "+f"(d[0]), "+f"(d[1]), "+f"(d[2]), "+f"(d[3])
        : "r"(a[0]), "r"(a[1]), "r"(a[2]), "r"(a[3]), "r"(b0), "r"(b1));
}
__device__ __forceinline__ void mbar_init(uint32_t m, uint32_t cnt){
    asm volatile("mbarrier.init.shared.b64 [%0], %1;" :: "r"(m), "r"(cnt) : "memory");
}
__device__ __forceinline__ void mbar_expect(uint32_t m, uint32_t bytes){
    asm volatile("mbarrier.arrive.expect_tx.shared.b64 _, [%0], %1;" :: "r"(m), "r"(bytes) : "memory");
}
__device__ __forceinline__ void mbar_wait(uint32_t m, uint32_t phase){
    asm volatile(
        "{\n\t.reg .pred P;\n\t"
        "WL_%=:\n\t"
        "mbarrier.try_wait.parity.acquire.cta.shared::cta.b64 P, [%0], %1, 0x989680;\n\t"
        "@P bra.uni WD_%=;\n\t"
        "bra.uni WL_%=;\n\t"
        "WD_%=:\n\t}"
        :: "r"(m), "r"(phase) : "memory");
}
__device__ __forceinline__ void bulkcp32k(uint32_t sdst, const void* gsrc, uint32_t mbar){
    uint64_t ga;
    asm("cvta.to.global.u64 %0, %1;" : "=l"(ga) : "l"(gsrc));
    asm volatile("cp.async.bulk.shared::cluster.global.mbarrier::complete_tx::bytes [%0], [%1], %2, [%3];"
        :: "r"(sdst), "l"(ga), "r"(32768u), "r"(mbar) : "memory");
}
__device__ __forceinline__ void fence_async(){
    asm volatile("fence.proxy.async.shared::cta;" ::: "memory");
}

__device__ __forceinline__ float softplusf(float x){
    return (x > 20.f) ? x : log1pf(expf(x));
}
__device__ __forceinline__ float siluf(float x){
    return x / (1.f + expf(-x));
}
__device__ __forceinline__ float blockReduceSum(float v){
    __shared__ float sh[32];
    #pragma unroll
    for (int o = 16; o; o >>= 1) v += __shfl_xor_sync(0xffffffffu, v, o);
    int w = threadIdx.x >> 5;
    if ((threadIdx.x & 31) == 0) sh[w] = v;
    __syncthreads();
    int nw = blockDim.x >> 5;
    float r = (threadIdx.x < nw) ? sh[threadIdx.x] : 0.f;
    if (w == 0){
        #pragma unroll
        for (int o = 16; o; o >>= 1) r += __shfl_xor_sync(0xffffffffu, r, o);
        if (threadIdx.x == 0) sh[0] = r;
    }
    __syncthreads();
    return sh[0];
}

// tiled layout index (block 8192 elems = 128 rows x 64 cols bf16, swizzled)
__device__ __forceinline__ size_t tidx(int tile, int nkc, int kc, int r, int c, int part){
    int s = c >> 3, e = c & 7;
    return (((size_t)tile * nkc + kc) << 13) + (size_t)(r * 64) +
           (size_t)((((part * 4 + s) ^ (r & 7))) << 3) + e;
}
__device__ __forceinline__ uint2 pack4bf(float a, float b, float c, float d){
    __nv_bfloat162 p0 = __floats2bfloat162_rn(a, b);
    __nv_bfloat162 p1 = __floats2bfloat162_rn(c, d);
    return make_uint2(*(uint32_t*)&p0, *(uint32_t*)&p1);
}

// ---------------- weight prep ----------------
__global__ void k_prep(const float* __restrict__ W, __nv_bfloat16* __restrict__ Wt,
                       int K, int N, int Npad){
    int l = blockIdx.z;
    W  += (size_t)l * K * N;
    Wt += (size_t)l * (Npad >> 7) * (K >> 5) * 8192;
    __shared__ float t[32][33];
    int k0 = blockIdx.x * 32, n0 = blockIdx.y * 32;
    int tx = threadIdx.x, ty = threadIdx.y;
    int nkc = K >> 5;
    for (int i = ty; i < 32; i += 8){
        float v = 0.f;
        if (n0 + tx < N) v = W[(size_t)(k0 + i) * N + n0 + tx];
        t[i][tx] = v;
    }
    __syncthreads();
    for (int i = ty; i < 32; i += 8){
        float v = t[tx][i];
        __nv_bfloat16 hi = __float2bfloat16_rn(v);
        float lo = v - __bfloat162float(hi);
        int n = n0 + i, k = k0 + tx;
        int tile = n >> 7, r = n & 127, kc = k >> 5, c = k & 31;
        Wt[tidx(tile, nkc, kc, r, c, 0)] = hi;
        Wt[tidx(tile, nkc, kc, r, c, 1)] = __float2bfloat16_rn(lo);
    }
}

// ---------------- GEMM (unchanged from R13/R14 best) ----------------
__global__ void __launch_bounds__(512, 1)
k_tgemm(const __nv_bfloat16* __restrict__ At, const __nv_bfloat16* __restrict__ Bt,
        float* __restrict__ C, const float* __restrict__ R,
        int M, int N, int K)
{
    extern __shared__ char smc[];
    __shared__ __align__(8) uint64_t mbarr[3];
    uint32_t sb  = s2u(smc);
    uint32_t mb0 = s2u(mbarr);
    int tid  = threadIdx.x;
    int lane = tid & 31, w = tid >> 5;
    int wm = w & 3, wn = w >> 2;
    int m0 = blockIdx.y * 128, n0 = blockIdx.x * 128;
    int nkc  = K >> 5;
    int nit  = K >> 6;
    const __nv_bfloat16* gA = At + (((size_t)blockIdx.y * nkc) << 13);
    const __nv_bfloat16* gB = Bt + (((size_t)blockIdx.x * nkc) << 13);

    if (tid == 0){
        #pragma unroll
        for (int s = 0; s < 3; s++) mbar_init(mb0 + s * 8, 1);
    }
    __syncthreads();
    if (tid == 0){
        #pragma unroll
        for (int s = 0; s < 2; s++){
            if (s < nit){
                mbar_expect(mb0 + s * 8, 65536u);
                bulkcp32k(sb + s * 65536u,          gA + ((size_t)(s * 2) << 13), mb0 + s * 8);
                bulkcp32k(sb + s * 65536u + 32768u, gB + ((size_t)(s * 2) << 13), mb0 + s * 8);
            }
        }
    }

    float acc[2][4][4];
    #pragma unroll
    for (int mt = 0; mt < 2; mt++)
        #pragma unroll
        for (int nt = 0; nt < 4; nt++)
            #pragma unroll
            for (int e = 0; e < 4; e++) acc[mt][nt][e] = 0.f;

    uint32_t aoff = sb + (uint32_t)((wm * 32 + (lane & 15)) * 128);
    uint32_t boff = sb + 32768u + (uint32_t)((wn * 32 + (lane & 15)) * 128);
    uint32_t ct[2][2];
    #pragma unroll
    for (int part = 0; part < 2; part++)
        #pragma unroll
        for (int kh = 0; kh < 2; kh++)
            ct[part][kh] = (uint32_t)((((part * 4 + 2 * kh + (lane >> 4))) ^ (lane & 7)) * 16);

    int cur = 0, nxt = 2;
    uint32_t phase = 0;
    for (int it = 0; it < nit; it++){
        mbar_wait(mb0 + (uint32_t)cur * 8, phase);
        __syncthreads();
        if (tid == 0 && it + 2 < nit){
            fence_async();
            mbar_expect(mb0 + (uint32_t)nxt * 8, 65536u);
            bulkcp32k(sb + (uint32_t)nxt * 65536u,          gA + ((size_t)((it + 2) * 2) << 13), mb0 + (uint32_t)nxt * 8);
            bulkcp32k(sb + (uint32_t)nxt * 65536u + 32768u, gB + ((size_t)((it + 2) * 2) << 13), mb0 + (uint32_t)nxt * 8);
        }

        uint32_t bufo = (uint32_t)cur * 65536u;
        #pragma unroll
        for (int kh = 0; kh < 4; kh++){
            uint32_t blko = (uint32_t)((kh >> 1) * 16384);
            int khl = kh & 1;
            uint32_t ah[2][4], al[2][4], bh[2][4], bl[2][4];
            #pragma unroll
            for (int mt = 0; mt < 2; mt++){
                uint32_t base = aoff + bufo + blko + (uint32_t)(mt * 2048);
                ldsm4(ah[mt], base + ct[0][khl]);
                ldsm4(al[mt], base + ct[1][khl]);
            }
            #pragma unroll
            for (int g = 0; g < 2; g++){
                uint32_t base = boff + bufo + blko + (uint32_t)(g * 2048);
                ldsm4(bh[g], base + ct[0][khl]);
                ldsm4(bl[g], base + ct[1][khl]);
            }
            #pragma unroll
            for (int mt = 0; mt < 2; mt++)
                #pragma unroll
                for (int nt = 0; nt < 4; nt++){
                    int g = nt >> 1, s = nt & 1;
                    mma16816(acc[mt][nt], ah[mt], bh[g][s], bh[g][s + 2]);
                    mma16816(acc[mt][nt], ah[mt], bl[g][s], bl[g][s + 2]);
                    mma16816(acc[mt][nt], al[mt], bh[g][s], bh[g][s + 2]);
                }
        }
        if (++cur == 3){ cur = 0; phase ^= 1; }
        if (++nxt == 3) nxt = 0;
    }

    #pragma unroll
    for (int mt = 0; mt < 2; mt++){
        int m = m0 + wm * 32 + mt * 16 + (lane >> 2);
        #pragma unroll
        for (int nt = 0; nt < 4; nt++){
            int col = n0 + wn * 32 + nt * 8 + (lane & 3) * 2;
            if (col < N){
                size_t i0 = (size_t)m * N + col;
                size_t i1 = (size_t)(m + 8) * N + col;
                float2 v0 = make_float2(acc[mt][nt][0], acc[mt][nt][1]);
                float2 v1 = make_float2(acc[mt][nt][2], acc[mt][nt][3]);
                if (R){
                    float2 r0 = *(const float2*)(R + i0);
                    float2 r1 = *(const float2*)(R + i1);
                    v0.x += r0.x; v0.y += r0.y;
                    v1.x += r1.x; v1.y += r1.y;
                }
                *(float2*)(C + i0) = v0;
                *(float2*)(C + i1) = v1;
            }
        }
    }
}

// ---------------- embedding ----------------
__global__ void k_embed(const float* __restrict__ x, const float* __restrict__ W){
    int idx = blockIdx.x * blockDim.x + threadIdx.x;
    if (idx >= NTOK * DMODEL) return;
    int t = idx / DMODEL, d = idx % DMODEL;
    float x0 = x[t*3+0]; if (x0 == -100.f) x0 = 0.f;
    float x1 = x[t*3+1]; if (x1 == -100.f) x1 = 0.f;
    float x2 = x[t*3+2]; if (x2 == -100.f) x2 = 0.f;
    float acc = x0 * W[0*DMODEL + d] + x1 * W[1*DMODEL + d] + x2 * W[2*DMODEL + d];
    if (d < 510){
        int c = d / 170, r = d % 170;
        float xv = (c == 0) ? x0 : ((c == 1) ? x1 : x2);
        float pe;
        if (r < 85) pe = sinf(xv * exp2f((float)r));
        else        pe = cosf(xv * exp2f((float)(r - 85)));
        acc += pe;
    }
    g_h[idx] = acc;
}

// ---------------- rmsnorm ----------------
__global__ void k_rmsnorm(const float* __restrict__ x, const float* __restrict__ w,
                          float* __restrict__ o, __nv_bfloat16* __restrict__ At, int D){
    int t = blockIdx.x;
    const float* xr = x + (size_t)t * D;
    float ss = 0.f;
    for (int d4 = threadIdx.x * 4; d4 < D; d4 += blockDim.x * 4){
        float4 v = *(const float4*)(xr + d4);
        ss += v.x*v.x + v.y*v.y + v.z*v.z + v.w*v.w;
    }
    ss = blockReduceSum(ss);
    float rs = rsqrtf(ss / (float)D + 1e-5f);
    int tile = t >> 7, r = t & 127, nkc = D >> 5;
    for (int d4 = threadIdx.x * 4; d4 < D; d4 += blockDim.x * 4){
        float4 v  = *(const float4*)(xr + d4);
        float4 wv = *(const float4*)(w + d4);
        float a = v.x*rs*wv.x, b = v.y*rs*wv.y, c = v.z*rs*wv.z, e = v.w*rs*wv.w;
        if (o) *(float4*)(o + (size_t)t * D + d4) = make_float4(a,b,c,e);
        __nv_bfloat162 h0 = __floats2bfloat162_rn(a, b);
        __nv_bfloat162 h1 = __floats2bfloat162_rn(c, e);
        float2 f0 = __bfloat1622float2(h0), f1 = __bfloat1622float2(h1);
        int kc = d4 >> 5, cc = d4 & 31;
        *(uint2*)(At + tidx(tile, nkc, kc, r, cc, 0)) = make_uint2(*(uint32_t*)&h0, *(uint32_t*)&h1);
        *(uint2*)(At + tidx(tile, nkc, kc, r, cc, 1)) = pack4bf(a-f0.x, b-f0.y, c-f1.x, e-f1.y);
    }
}

// ---------------- fused conv(4 tokens/thread)+silu and dt-cumsum ------------
__global__ void k_convdt(const float* __restrict__ cw, const float* __restrict__ cb,
                         const float* __restrict__ dtb, const float* __restrict__ Alog){
    if (blockIdx.x < NCONVB){
        int idx = blockIdx.x * 256 + threadIdx.x;
        int ch = idx % CONVDIM;
        int t0 = (idx / CONVDIM) * 4;
        int l0 = t0 % SEQL;
        float w0 = cw[ch*DCONV+0], w1 = cw[ch*DCONV+1];
        float w2 = cw[ch*DCONV+2], w3 = cw[ch*DCONV+3];
        float bb = cb[ch];
        float xb[7];
        #pragma unroll
        for (int j = 0; j < 7; j++){
            int l = l0 - 3 + j;
            xb[j] = (l >= 0) ? g_zx[(size_t)(t0 - 3 + j) * DINPROJ + DINNER + ch] : 0.f;
        }
        #pragma unroll
        for (int m = 0; m < 4; m++){
            float acc = bb + xb[m]*w0 + xb[m+1]*w1 + xb[m+2]*w2 + xb[m+3]*w3;
            g_xc[(size_t)(t0 + m) * CONVDIM + ch] = siluf(acc);
        }
    } else {
        __shared__ float sh[2][CHUNKL];
        int pr   = threadIdx.x >> 7;
        int i    = threadIdx.x & 127;
        int flat = (blockIdx.x - NCONVB) * 2 + pr;
        int bc = flat >> 4, h = flat & 15;
        int t  = bc * CHUNKL + i;
        float d = softplusf(g_zx[(size_t)t * DINPROJ + 2176 + h] + dtb[h]);
        float A = -expf(Alog[h]);
        sh[pr][i] = d * A;
        __syncthreads();
        #pragma unroll
        for (int off = 1; off < CHUNKL; off <<= 1){
            float v = (i >= off) ? sh[pr][i - off] : 0.f;
            __syncthreads();
            sh[pr][i] += v;
            __syncthreads();
        }
        g_dtv [t*NH + h] = d;
        g_acum[t*NH + h] = sh[pr][i];
        if (i == CHUNKL - 1) g_dec[flat] = expf(sh[pr][i]);
    }
}

// ---------------- fused state (window-clipped) + scores ----------------
__global__ void k_ssd1(){
    extern __shared__ float smf[];
    int tid = threadIdx.x;
    if (blockIdx.x < NBC*NH){
        float* xsh = smf;
        float* bsh = smf + CHUNKL*HD;
        __shared__ float wsh[CHUNKL];
        __shared__ float ash_s[CHUNKL];
        int bc = blockIdx.x >> 4, h = blockIdx.x & 15;
        int t0 = bc * CHUNKL;
        if (tid < CHUNKL) ash_s[tid] = g_acum[(t0 + tid)*NH + h];
        __syncthreads();
        float alast = ash_s[CHUNKL - 1];
        int lo = 0, hi = CHUNKL - 1;
        while (lo < hi){
            int mid = (lo + hi) >> 1;
            if (ash_s[mid] < alast + AWIN) hi = mid; else lo = mid + 1;
        }
        if (tid < CHUNKL && tid >= lo)
            wsh[tid] = __expf(alast - ash_s[tid]) * g_dtv[(t0 + tid)*NH + h];
        // load only rows [lo, 128)
        for (int idx = lo*HD + tid; idx < CHUNKL*HD; idx += 256){
            int j = idx >> 6, q = idx & 63;
            xsh[idx] = g_xc[(size_t)(t0+j)*CONVDIM + h*HD + q];
            bsh[idx] = g_xc[(size_t)(t0+j)*CONVDIM + DINNER + q];
        }
        __syncthreads();
        int p  = tid & 63;
        int n0 = (tid >> 6) << 4;
        float acc[16];
        #pragma unroll
        for (int k = 0; k < 16; k++) acc[k] = 0.f;
        for (int j = lo; j < CHUNKL; j++){
            float xw = xsh[j*HD + p] * wsh[j];
            const float* br = &bsh[j*HD + n0];
            #pragma unroll
            for (int k = 0; k < 16; k++) acc[k] += xw * br[k];
        }
        float* so = g_S + (size_t)blockIdx.x * (HD*DSTATE);
        #pragma unroll
        for (int k = 0; k < 16; k++) so[p*DSTATE + n0 + k] = acc[k];
    } else {
        int bid = blockIdx.x - NBC*NH;
        float* Csh = smf;
        float* Bsh = smf + 32*65;
        int bc = bid >> 2, q = bid & 3;
        int i0 = q * 32, jmax = i0 + 32;
        int t0 = bc * CHUNKL;
        for (int idx = tid; idx < 32*DSTATE; idx += 256){
            int i = idx >> 6, n = idx & 63;
            Csh[i*65 + n] = g_xc[(size_t)(t0+i0+i)*CONVDIM + DINNER + DSTATE + n];
        }
        for (int idx = tid; idx < jmax*DSTATE; idx += 256){
            int j = idx >> 6, n = idx & 63;
            Bsh[j*65 + n] = g_xc[(size_t)(t0+j)*CONVDIM + DINNER + n];
        }
        __syncthreads();
        int ti = (tid >> 4) * 2;
        int tj = (tid & 15) * 8;
        if (tj >= jmax) return;
        float acc[2][8];
        #pragma unroll
        for (int r = 0; r < 2; r++)
            #pragma unroll
            for (int c = 0; c < 8; c++) acc[r][c] = 0.f;
        for (int n = 0; n < DSTATE; n++){
            float a0 = Csh[(ti+0)*65 + n];
            float a1 = Csh[(ti+1)*65 + n];
            float b[8];
            #pragma unroll
            for (int c = 0; c < 8; c++) b[c] = Bsh[(tj+c)*65 + n];
            #pragma unroll
            for (int c = 0; c < 8; c++){ acc[0][c] += a0*b[c]; acc[1][c] += a1*b[c]; }
        }
        float* out = g_sc + (size_t)bc * CHUNKL * CHUNKL;
        #pragma unroll
        for (int r = 0; r < 2; r++)
            #pragma unroll
            for (int c = 0; c < 8; c++)
                out[(i0+ti+r)*CHUNKL + tj + c] = acc[r][c];
    }
}

// ---------------- scan ----------------
__global__ void k_scan(){
    int bid = blockIdx.x;
    int bh  = bid >> 4;
    int grp = bid & 15;
    int b = bh >> 4, h = bh & 15;
    int idx = grp * 256 + threadIdx.x;
    float st = 0.f;
    #pragma unroll 4
    for (int c = 0; c < NCH; c++){
        int bch = (b*NCH + c)*NH + h;
        size_t base = (size_t)bch * (HD*DSTATE);
        float dc = g_dec[bch];
        g_hs[base + idx] = st;
        st = st*dc + g_S[base + idx];
    }
}

// ---------------- fused y, 256 threads, conditional hsh load ---------------
__global__ void k_ssd_y(const float* __restrict__ Dp){
    extern __shared__ float smf[];
    float* xsh = smf;
    float* hsh = smf + CHUNKL*HD;
    __shared__ float ash[CHUNKL], dsh[CHUNKL];
    int bc = blockIdx.x >> 4, h = blockIdx.x & 15;
    int tid = threadIdx.x;
    int i  = tid & 127, ph = tid >> 7;
    int pb = ph * 32;
    int t0 = bc * CHUNKL;
    if (tid < CHUNKL){
        ash[tid] = g_acum[(t0+tid)*NH + h];
        dsh[tid] = g_dtv [(t0+tid)*NH + h];
    }
    for (int idx = tid; idx < CHUNKL*HD; idx += 256)
        xsh[idx] = g_xc[(size_t)(t0 + (idx >> 6))*CONVDIM + h*HD + (idx & 63)];
    // ash[0] is the max of a_cum in this chunk; if <= -AWIN no row needs y_off
    bool any_off = (g_acum[(size_t)t0*NH + h] > -AWIN);
    if (any_off){
        const float* hbase = g_hs + (size_t)blockIdx.x * (HD*DSTATE);
        for (int idx = tid; idx < HD*DSTATE; idx += 256) hsh[idx] = hbase[idx];
    }
    __syncthreads();

    float ai = ash[i];
    float Dh = Dp[h];
    float acc[32];
    #pragma unroll
    for (int p = 0; p < 32; p++) acc[p] = Dh * xsh[i*HD + pb + p];

    int lo = 0, hi = i;
    while (lo < hi){
        int mid = (lo + hi) >> 1;
        if (ash[mid] < ai + AWIN) hi = mid; else lo = mid + 1;
    }
    const float* srow = g_sc + (size_t)bc * CHUNKL * CHUNKL + (size_t)i * CHUNKL;
    for (int j = lo; j <= i; j++){
        float m = srow[j] * __expf(ai - ash[j]) * dsh[j];
        const float* xr = &xsh[j*HD + pb];
        #pragma unroll
        for (int p = 0; p < 32; p++) acc[p] += m * xr[p];
    }

    if (ai > -AWIN){
        float ei = __expf(ai);
        const float* crow = g_xc + (size_t)(t0+i)*CONVDIM + DINNER + DSTATE;
        #pragma unroll
        for (int h2 = 0; h2 < 2; h2++){
            float creg[32];
            #pragma unroll
            for (int n = 0; n < 32; n++) creg[n] = ei * crow[h2*32 + n];
            #pragma unroll 4
            for (int p = 0; p < 32; p++){
                const float4* hr = (const float4*)&hsh[(pb+p)*DSTATE + h2*32];
                float a = 0.f;
                #pragma unroll
                for (int q = 0; q < 8; q++){
                    float4 v = hr[q];
                    a += creg[q*4+0]*v.x + creg[q*4+1]*v.y + creg[q*4+2]*v.z + creg[q*4+3]*v.w;
                }
                acc[p] += a;
            }
        }
    }

    float* yrow = g_y + (size_t)(t0+i)*DINNER + h*HD + pb;
    #pragma unroll
    for (int p = 0; p < 32; p++) yrow[p] = acc[p];
}

// ---------------- gate ----------------
__global__ void k_gate(const float* __restrict__ gw, __nv_bfloat16* __restrict__ At){
    int t = blockIdx.x;
    int tid = threadIdx.x;
    int d4 = tid * 4;
    float4 zv = *(const float4*)(g_zx + (size_t)t*DINPROJ + d4);
    float4 yv = *(const float4*)(g_y  + (size_t)t*DINNER + d4);
    float v0 = yv.x * siluf(zv.x);
    float v1 = yv.y * siluf(zv.y);
    float v2 = yv.z * siluf(zv.z);
    float v3 = yv.w * siluf(zv.w);
    float ss = blockReduceSum(v0*v0 + v1*v1 + v2*v2 + v3*v3);
    float rs = rsqrtf(ss / (float)DINNER + 1e-5f);
    float4 wv = *(const float4*)(gw + d4);
    float a = v0*rs*wv.x, b = v1*rs*wv.y, c = v2*rs*wv.z, e = v3*rs*wv.w;
    __nv_bfloat162 h0 = __floats2bfloat162_rn(a, b);
    __nv_bfloat162 h1 = __floats2bfloat162_rn(c, e);
    float2 f0 = __bfloat1622float2(h0), f1 = __bfloat1622float2(h1);
    int tile = t >> 7, r = t & 127;
    int kc = d4 >> 5, cc = d4 & 31;
    *(uint2*)(At + tidx(tile, DINNER >> 5, kc, r, cc, 0)) = make_uint2(*(uint32_t*)&h0, *(uint32_t*)&h1);
    *(uint2*)(At + tidx(tile, DINNER >> 5, kc, r, cc, 1)) = pack4bf(a-f0.x, b-f0.y, c-f1.x, e-f1.y);
}

// ---------------- head ----------------
__global__ void k_head(const float* __restrict__ hw, const float* __restrict__ hb,
                       float* __restrict__ out){
    int idx = blockIdx.x * blockDim.x + threadIdx.x;
    if (idx >= NTOK * KOUT) return;
    int t = idx / KOUT, n = idx % KOUT;
    float acc = hb[n];
    const float* xr = g_xn + (size_t)t * DMODEL;
    for (int k = 0; k < DMODEL; k++) acc += xr[k] * hw[k*KOUT + n];
    out[idx] = acc;
}

// ---------------- host ----------------
extern "C" void kernel_launch(void* const* d_in, const int* in_sizes, int n_in,
                              void* d_out, int out_size){
    const float* x      = (const float*)d_in[0];
    const float* Wembed = (const float*)d_in[1];
    const float* rmsw   = (const float*)d_in[2];
    const float* inw    = (const float*)d_in[3];
    const float* convw  = (const float*)d_in[4];
    const float* convb  = (const float*)d_in[5];
    const float* dtb    = (const float*)d_in[6];
    const float* alog   = (const float*)d_in[7];
    const float* dparam = (const float*)d_in[8];
    const float* gnw    = (const float*)d_in[9];
    const float* outw   = (const float*)d_in[10];
    const float* fnw    = (const float*)d_in[11];
    const float* hw     = (const float*)d_in[12];
    const float* hb     = (const float*)d_in[13];
    float* out = (float*)d_out;

    float *p_h, *p_xn;
    cudaGetSymbolAddress((void**)&p_h,  g_h);
    cudaGetSymbolAddress((void**)&p_xn, g_xn);
    float *p_zx;
    cudaGetSymbolAddress((void**)&p_zx, g_zx);
    __nv_bfloat16 *p_ain, *p_aout, *p_win, *p_wout;
    cudaGetSymbolAddress((void**)&p_ain,  g_ain);
    cudaGetSymbolAddress((void**)&p_aout, g_aout);
    cudaGetSymbolAddress((void**)&p_win,  g_win);
    cudaGetSymbolAddress((void**)&p_wout, g_wout);

    const int SSD1_SMEM = 2*CHUNKL*HD*4;
    const int SSDY_SMEM = (CHUNKL*HD + HD*DSTATE)*4;
    const int TG_SMEM   = 3*65536;
    cudaFuncSetAttribute(k_ssd1,  cudaFuncAttributeMaxDynamicSharedMemorySize, SSD1_SMEM);
    cudaFuncSetAttribute(k_ssd_y, cudaFuncAttributeMaxDynamicSharedMemorySize, SSDY_SMEM);
    cudaFuncSetAttribute(k_tgemm, cudaFuncAttributeMaxDynamicSharedMemorySize, TG_SMEM);

    const size_t WIN_L  = (size_t)(NPAD_IN/128)*(DMODEL/32)*8192;
    const size_t WOUT_L = (size_t)(DMODEL/128)*(DINNER/32)*8192;

    k_prep<<<dim3(DMODEL/32, NPAD_IN/32, NLAYERS), dim3(32,8)>>>(
        inw, p_win, DMODEL, DINPROJ, NPAD_IN);
    k_embed<<<(NTOK*DMODEL + 255)/256, 256>>>(x, Wembed);

    for (int l = 0; l < NLAYERS; l++){
        k_rmsnorm<<<NTOK, 128>>>(p_h, rmsw + (size_t)l*DMODEL, nullptr, p_ain, DMODEL);
        k_tgemm<<<dim3(NPAD_IN/128, NTOK/128), 512, TG_SMEM>>>(
            p_ain, p_win + (size_t)l*WIN_L, p_zx, nullptr, NTOK, DINPROJ, DMODEL);
        if (l == 0)
            k_prep<<<dim3(DINNER/32, DMODEL/32, NLAYERS), dim3(32,8)>>>(
                outw, p_wout, DINNER, DMODEL, DMODEL);
        k_convdt<<<NCONVB + NDTB, 256>>>(convw + (size_t)l*CONVDIM*DCONV,
                                         convb + (size_t)l*CONVDIM,
                                         dtb + (size_t)l*NH, alog + (size_t)l*NH);
        k_ssd1<<<NBC*NH + NBC*4, 256, SSD1_SMEM>>>();
        k_scan<<<BSZ*NH*16, 256>>>();
        k_ssd_y<<<NBC*NH, 256, SSDY_SMEM>>>(dparam + (size_t)l*NH);
        k_gate<<<NTOK, 256>>>(gnw + (size_t)l*DINNER, p_aout);
        k_tgemm<<<dim3(DMODEL/128, NTOK/128), 512, TG_SMEM>>>(
            p_aout, p_wout + (size_t)l*WOUT_L, p_h, p_h, NTOK, DMODEL, DINNER);
    }

    k_rmsnorm<<<NTOK, 128>>>(p_h, fnw, p_xn, p_ain, DMODEL);
    k_head<<<(NTOK*KOUT + 255)/256, 256>>>(hw, hb, out);
}

// round 16
// speedup vs baseline: 1.8057x; 1.0364x over previous
#include <cuda_runtime.h>
#include <cuda_bf16.h>
#include <math.h>
#include <stdint.h>

// ---------------- problem constants ----------------
#define BSZ     2
#define SEQL    2048
#define NTOK    (BSZ*SEQL)        // 4096
#define DMODEL  512
#define DINNER  1024
#define NH      16
#define HD      64
#define DSTATE  64
#define DCONV   4
#define CONVDIM 1152
#define DINPROJ 2192
#define NPAD_IN 2304
#define NLAYERS 12
#define CHUNKL  128
#define NCH     16
#define NBC     (BSZ*NCH)         // 32
#define KOUT    30
#define AWIN    10.0f
#define NCONVB  ((NTOK/4*CONVDIM)/256)
#define NDTB    ((NBC*NH)/2)

// ---------------- scratch ----------
__device__ float g_h   [NTOK*DMODEL];
__device__ float g_zx  [NTOK*DINPROJ];
__device__ float g_xc  [NTOK*CONVDIM];
__device__ float g_dtv [NTOK*NH];
__device__ float g_acum[NTOK*NH];
__device__ float g_dec [NBC*NH];
__device__ float g_sc  [NBC*CHUNKL*CHUNKL];
__device__ float g_y   [NTOK*DINNER];
__device__ float g_S   [NBC*NH*HD*DSTATE];
__device__ float g_hs  [NBC*NH*HD*DSTATE];
__device__ __align__(128) __nv_bfloat16 g_ain [(NTOK/128)*(DMODEL/32)*8192];
__device__ __align__(128) __nv_bfloat16 g_aout[(NTOK/128)*(DINNER/32)*8192];
__device__ __align__(128) __nv_bfloat16 g_win [NLAYERS*(NPAD_IN/128)*(DMODEL/32)*8192];
__device__ __align__(128) __nv_bfloat16 g_wout[NLAYERS*(DMODEL/128)*(DINNER/32)*8192];

// ---------------- helpers ----------------
__device__ __forceinline__ uint32_t s2u(const void* p){
    uint32_t a;
    asm("{ .reg .u64 t; cvta.to.shared.u64 t, %1; cvt.u32.u64 %0, t; }" : "=r"(a) : "l"(p));
    return a;
}
__device__ __forceinline__ void ldsm4(uint32_t* r, uint32_t a){
    asm volatile("ldmatrix.sync.aligned.m8n8.x4.shared.b16 {%0,%1,%2,%3}, [%4];"
        : "=r"(r[0]), "=r"(r[1]), "=r"(r[2]), "=r"(r[3]) : "r"(a));
}
__device__ __forceinline__ void mma16816(float* d, const uint32_t* a, uint32_t b0, uint32_t b1){
    asm volatile("mma.sync.aligned.m16n8k16.row.col.f32.bf16.bf16.f32 "
        "{%0,%1,%2,%3}, {%4,%5,%6,%7}, {%8,%9}, {%0,%1,%2,%3};"
        : "+f"(d[0]), "+f"(d[1]), "+f"(d[2]), "+f"(d[3])
        : "r"(a[0]), "r"(a[1]), "r"(a[2]), "r"(a[3]), "r"(b0), "r"(b1));
}
__device__ __forceinline__ void mbar_init(uint32_t m, uint32_t cnt){
    asm volatile("mbarrier.init.shared.b64 [%0], %1;" :: "r"(m), "r"(cnt) : "memory");
}
__device__ __forceinline__ void mbar_expect(uint32_t m, uint32_t bytes){
    asm volatile("mbarrier.arrive.expect_tx.shared.b64 _, [%0], %1;" :: "r"(m), "r"(bytes) : "memory");
}
__device__ __forceinline__ void mbar_wait(uint32_t m, uint32_t phase){
    asm volatile(
        "{\n\t.reg .pred P;\n\t"
        "WL_%=:\n\t"
        "mbarrier.try_wait.parity.acquire.cta.shared::cta.b64 P, [%0], %1, 0x989680;\n\t"
        "@P bra.uni WD_%=;\n\t"
        "bra.uni WL_%=;\n\t"
        "WD_%=:\n\t}"
        :: "r"(m), "r"(phase) : "memory");
}
__device__ __forceinline__ void bulkcp32k(uint32_t sdst, const void* gsrc, uint32_t mbar){
    uint64_t ga;
    asm("cvta.to.global.u64 %0, %1;" : "=l"(ga) : "l"(gsrc));
    asm volatile("cp.async.bulk.shared::cluster.global.mbarrier::complete_tx::bytes [%0], [%1], %2, [%3];"
        :: "r"(sdst), "l"(ga), "r"(32768u), "r"(mbar) : "memory");
}
__device__ __forceinline__ void fence_async(){
    asm volatile("fence.proxy.async.shared::cta;" ::: "memory");
}

__device__ __forceinline__ float softplusf(float x){
    return (x > 20.f) ? x : log1pf(expf(x));
}
__device__ __forceinline__ float siluf(float x){
    return x / (1.f + expf(-x));
}
__device__ __forceinline__ float blockReduceSum(float v){
    __shared__ float sh[32];
    #pragma unroll
    for (int o = 16; o; o >>= 1) v += __shfl_xor_sync(0xffffffffu, v, o);
    int w = threadIdx.x >> 5;
    if ((threadIdx.x & 31) == 0) sh[w] = v;
    __syncthreads();
    int nw = blockDim.x >> 5;
    float r = (threadIdx.x < nw) ? sh[threadIdx.x] : 0.f;
    if (w == 0){
        #pragma unroll
        for (int o = 16; o; o >>= 1) r += __shfl_xor_sync(0xffffffffu, r, o);
        if (threadIdx.x == 0) sh[0] = r;
    }
    __syncthreads();
    return sh[0];
}

// tiled layout index (block 8192 elems = 128 rows x 64 cols bf16, swizzled)
__device__ __forceinline__ size_t tidx(int tile, int nkc, int kc, int r, int c, int part){
    int s = c >> 3, e = c & 7;
    return (((size_t)tile * nkc + kc) << 13) + (size_t)(r * 64) +
           (size_t)((((part * 4 + s) ^ (r & 7))) << 3) + e;
}
__device__ __forceinline__ uint2 pack4bf(float a, float b, float c, float d){
    __nv_bfloat162 p0 = __floats2bfloat162_rn(a, b);
    __nv_bfloat162 p1 = __floats2bfloat162_rn(c, d);
    return make_uint2(*(uint32_t*)&p0, *(uint32_t*)&p1);
}

// ---------------- weight prep ----------------
__global__ void k_prep(const float* __restrict__ W, __nv_bfloat16* __restrict__ Wt,
                       int K, int N, int Npad){
    int l = blockIdx.z;
    W  += (size_t)l * K * N;
    Wt += (size_t)l * (Npad >> 7) * (K >> 5) * 8192;
    __shared__ float t[32][33];
    int k0 = blockIdx.x * 32, n0 = blockIdx.y * 32;
    int tx = threadIdx.x, ty = threadIdx.y;
    int nkc = K >> 5;
    for (int i = ty; i < 32; i += 8){
        float v = 0.f;
        if (n0 + tx < N) v = W[(size_t)(k0 + i) * N + n0 + tx];
        t[i][tx] = v;
    }
    __syncthreads();
    for (int i = ty; i < 32; i += 8){
        float v = t[tx][i];
        __nv_bfloat16 hi = __float2bfloat16_rn(v);
        float lo = v - __bfloat162float(hi);
        int n = n0 + i, k = k0 + tx;
        int tile = n >> 7, r = n & 127, kc = k >> 5, c = k & 31;
        Wt[tidx(tile, nkc, kc, r, c, 0)] = hi;
        Wt[tidx(tile, nkc, kc, r, c, 1)] = __float2bfloat16_rn(lo);
    }
}

// ---------------- GEMM (frozen) ----------------
__global__ void __launch_bounds__(512, 1)
k_tgemm(const __nv_bfloat16* __restrict__ At, const __nv_bfloat16* __restrict__ Bt,
        float* __restrict__ C, const float* __restrict__ R,
        int M, int N, int K)
{
    extern __shared__ char smc[];
    __shared__ __align__(8) uint64_t mbarr[3];
    uint32_t sb  = s2u(smc);
    uint32_t mb0 = s2u(mbarr);
    int tid  = threadIdx.x;
    int lane = tid & 31, w = tid >> 5;
    int wm = w & 3, wn = w >> 2;
    int m0 = blockIdx.y * 128, n0 = blockIdx.x * 128;
    int nkc  = K >> 5;
    int nit  = K >> 6;
    const __nv_bfloat16* gA = At + (((size_t)blockIdx.y * nkc) << 13);
    const __nv_bfloat16* gB = Bt + (((size_t)blockIdx.x * nkc) << 13);

    if (tid == 0){
        #pragma unroll
        for (int s = 0; s < 3; s++) mbar_init(mb0 + s * 8, 1);
    }
    __syncthreads();
    if (tid == 0){
        #pragma unroll
        for (int s = 0; s < 2; s++){
            if (s < nit){
                mbar_expect(mb0 + s * 8, 65536u);
                bulkcp32k(sb + s * 65536u,          gA + ((size_t)(s * 2) << 13), mb0 + s * 8);
                bulkcp32k(sb + s * 65536u + 32768u, gB + ((size_t)(s * 2) << 13), mb0 + s * 8);
            }
        }
    }

    float acc[2][4][4];
    #pragma unroll
    for (int mt = 0; mt < 2; mt++)
        #pragma unroll
        for (int nt = 0; nt < 4; nt++)
            #pragma unroll
            for (int e = 0; e < 4; e++) acc[mt][nt][e] = 0.f;

    uint32_t aoff = sb + (uint32_t)((wm * 32 + (lane & 15)) * 128);
    uint32_t boff = sb + 32768u + (uint32_t)((wn * 32 + (lane & 15)) * 128);
    uint32_t ct[2][2];
    #pragma unroll
    for (int part = 0; part < 2; part++)
        #pragma unroll
        for (int kh = 0; kh < 2; kh++)
            ct[part][kh] = (uint32_t)((((part * 4 + 2 * kh + (lane >> 4))) ^ (lane & 7)) * 16);

    int cur = 0, nxt = 2;
    uint32_t phase = 0;
    for (int it = 0; it < nit; it++){
        mbar_wait(mb0 + (uint32_t)cur * 8, phase);
        __syncthreads();
        if (tid == 0 && it + 2 < nit){
            fence_async();
            mbar_expect(mb0 + (uint32_t)nxt * 8, 65536u);
            bulkcp32k(sb + (uint32_t)nxt * 65536u,          gA + ((size_t)((it + 2) * 2) << 13), mb0 + (uint32_t)nxt * 8);
            bulkcp32k(sb + (uint32_t)nxt * 65536u + 32768u, gB + ((size_t)((it + 2) * 2) << 13), mb0 + (uint32_t)nxt * 8);
        }

        uint32_t bufo = (uint32_t)cur * 65536u;
        #pragma unroll
        for (int kh = 0; kh < 4; kh++){
            uint32_t blko = (uint32_t)((kh >> 1) * 16384);
            int khl = kh & 1;
            uint32_t ah[2][4], al[2][4], bh[2][4], bl[2][4];
            #pragma unroll
            for (int mt = 0; mt < 2; mt++){
                uint32_t base = aoff + bufo + blko + (uint32_t)(mt * 2048);
                ldsm4(ah[mt], base + ct[0][khl]);
                ldsm4(al[mt], base + ct[1][khl]);
            }
            #pragma unroll
            for (int g = 0; g < 2; g++){
                uint32_t base = boff + bufo + blko + (uint32_t)(g * 2048);
                ldsm4(bh[g], base + ct[0][khl]);
                ldsm4(bl[g], base + ct[1][khl]);
            }
            #pragma unroll
            for (int mt = 0; mt < 2; mt++)
                #pragma unroll
                for (int nt = 0; nt < 4; nt++){
                    int g = nt >> 1, s = nt & 1;
                    mma16816(acc[mt][nt], ah[mt], bh[g][s], bh[g][s + 2]);
                    mma16816(acc[mt][nt], ah[mt], bl[g][s], bl[g][s + 2]);
                    mma16816(acc[mt][nt], al[mt], bh[g][s], bh[g][s + 2]);
                }
        }
        if (++cur == 3){ cur = 0; phase ^= 1; }
        if (++nxt == 3) nxt = 0;
    }

    #pragma unroll
    for (int mt = 0; mt < 2; mt++){
        int m = m0 + wm * 32 + mt * 16 + (lane >> 2);
        #pragma unroll
        for (int nt = 0; nt < 4; nt++){
            int col = n0 + wn * 32 + nt * 8 + (lane & 3) * 2;
            if (col < N){
                size_t i0 = (size_t)m * N + col;
                size_t i1 = (size_t)(m + 8) * N + col;
                float2 v0 = make_float2(acc[mt][nt][0], acc[mt][nt][1]);
                float2 v1 = make_float2(acc[mt][nt][2], acc[mt][nt][3]);
                if (R){
                    float2 r0 = *(const float2*)(R + i0);
                    float2 r1 = *(const float2*)(R + i1);
                    v0.x += r0.x; v0.y += r0.y;
                    v1.x += r1.x; v1.y += r1.y;
                }
                *(float2*)(C + i0) = v0;
                *(float2*)(C + i1) = v1;
            }
        }
    }
}

// ---------------- embedding ----------------
__global__ void k_embed(const float* __restrict__ x, const float* __restrict__ W){
    int idx = blockIdx.x * blockDim.x + threadIdx.x;
    if (idx >= NTOK * DMODEL) return;
    int t = idx / DMODEL, d = idx % DMODEL;
    float x0 = x[t*3+0]; if (x0 == -100.f) x0 = 0.f;
    float x1 = x[t*3+1]; if (x1 == -100.f) x1 = 0.f;
    float x2 = x[t*3+2]; if (x2 == -100.f) x2 = 0.f;
    float acc = x0 * W[0*DMODEL + d] + x1 * W[1*DMODEL + d] + x2 * W[2*DMODEL + d];
    if (d < 510){
        int c = d / 170, r = d % 170;
        float xv = (c == 0) ? x0 : ((c == 1) ? x1 : x2);
        float pe;
        if (r < 85) pe = sinf(xv * exp2f((float)r));
        else        pe = cosf(xv * exp2f((float)(r - 85)));
        acc += pe;
    }
    g_h[idx] = acc;
}

// ---------------- rmsnorm -> tiled bf16 hi/lo ----------------
__global__ void k_rmsnorm(const float* __restrict__ x, const float* __restrict__ w,
                          __nv_bfloat16* __restrict__ At, int D){
    int t = blockIdx.x;
    const float* xr = x + (size_t)t * D;
    float ss = 0.f;
    for (int d4 = threadIdx.x * 4; d4 < D; d4 += blockDim.x * 4){
        float4 v = *(const float4*)(xr + d4);
        ss += v.x*v.x + v.y*v.y + v.z*v.z + v.w*v.w;
    }
    ss = blockReduceSum(ss);
    float rs = rsqrtf(ss / (float)D + 1e-5f);
    int tile = t >> 7, r = t & 127, nkc = D >> 5;
    for (int d4 = threadIdx.x * 4; d4 < D; d4 += blockDim.x * 4){
        float4 v  = *(const float4*)(xr + d4);
        float4 wv = *(const float4*)(w + d4);
        float a = v.x*rs*wv.x, b = v.y*rs*wv.y, c = v.z*rs*wv.z, e = v.w*rs*wv.w;
        __nv_bfloat162 h0 = __floats2bfloat162_rn(a, b);
        __nv_bfloat162 h1 = __floats2bfloat162_rn(c, e);
        float2 f0 = __bfloat1622float2(h0), f1 = __bfloat1622float2(h1);
        int kc = d4 >> 5, cc = d4 & 31;
        *(uint2*)(At + tidx(tile, nkc, kc, r, cc, 0)) = make_uint2(*(uint32_t*)&h0, *(uint32_t*)&h1);
        *(uint2*)(At + tidx(tile, nkc, kc, r, cc, 1)) = pack4bf(a-f0.x, b-f0.y, c-f1.x, e-f1.y);
    }
}

// ---------------- fused conv(4 tokens/thread)+silu and dt-cumsum ------------
__global__ void k_convdt(const float* __restrict__ cw, const float* __restrict__ cb,
                         const float* __restrict__ dtb, const float* __restrict__ Alog){
    if (blockIdx.x < NCONVB){
        int idx = blockIdx.x * 256 + threadIdx.x;
        int ch = idx % CONVDIM;
        int t0 = (idx / CONVDIM) * 4;
        int l0 = t0 % SEQL;
        float w0 = cw[ch*DCONV+0], w1 = cw[ch*DCONV+1];
        float w2 = cw[ch*DCONV+2], w3 = cw[ch*DCONV+3];
        float bb = cb[ch];
        float xb[7];
        #pragma unroll
        for (int j = 0; j < 7; j++){
            int l = l0 - 3 + j;
            xb[j] = (l >= 0) ? g_zx[(size_t)(t0 - 3 + j) * DINPROJ + DINNER + ch] : 0.f;
        }
        #pragma unroll
        for (int m = 0; m < 4; m++){
            float acc = bb + xb[m]*w0 + xb[m+1]*w1 + xb[m+2]*w2 + xb[m+3]*w3;
            g_xc[(size_t)(t0 + m) * CONVDIM + ch] = siluf(acc);
        }
    } else {
        __shared__ float sh[2][CHUNKL];
        int pr   = threadIdx.x >> 7;
        int i    = threadIdx.x & 127;
        int flat = (blockIdx.x - NCONVB) * 2 + pr;
        int bc = flat >> 4, h = flat & 15;
        int t  = bc * CHUNKL + i;
        float d = softplusf(g_zx[(size_t)t * DINPROJ + 2176 + h] + dtb[h]);
        float A = -expf(Alog[h]);
        sh[pr][i] = d * A;
        __syncthreads();
        #pragma unroll
        for (int off = 1; off < CHUNKL; off <<= 1){
            float v = (i >= off) ? sh[pr][i - off] : 0.f;
            __syncthreads();
            sh[pr][i] += v;
            __syncthreads();
        }
        g_dtv [t*NH + h] = d;
        g_acum[t*NH + h] = sh[pr][i];
        if (i == CHUNKL - 1) g_dec[flat] = expf(sh[pr][i]);
    }
}

// ---------------- fused state (window-clipped) + scores (band-clipped) ------
__global__ void k_ssd1(){
    extern __shared__ float smf[];
    int tid = threadIdx.x;
    if (blockIdx.x < NBC*NH){
        float* xsh = smf;
        float* bsh = smf + CHUNKL*HD;
        __shared__ float wsh[CHUNKL];
        __shared__ float ash_s[CHUNKL];
        int bc = blockIdx.x >> 4, h = blockIdx.x & 15;
        int t0 = bc * CHUNKL;
        if (tid < CHUNKL) ash_s[tid] = g_acum[(t0 + tid)*NH + h];
        __syncthreads();
        float alast = ash_s[CHUNKL - 1];
        int lo = 0, hi = CHUNKL - 1;
        while (lo < hi){
            int mid = (lo + hi) >> 1;
            if (ash_s[mid] < alast + AWIN) hi = mid; else lo = mid + 1;
        }
        if (tid < CHUNKL && tid >= lo)
            wsh[tid] = __expf(alast - ash_s[tid]) * g_dtv[(t0 + tid)*NH + h];
        for (int idx = lo*HD + tid; idx < CHUNKL*HD; idx += 256){
            int j = idx >> 6, q = idx & 63;
            xsh[idx] = g_xc[(size_t)(t0+j)*CONVDIM + h*HD + q];
            bsh[idx] = g_xc[(size_t)(t0+j)*CONVDIM + DINNER + q];
        }
        __syncthreads();
        int p  = tid & 63;
        int n0 = (tid >> 6) << 4;
        float acc[16];
        #pragma unroll
        for (int k = 0; k < 16; k++) acc[k] = 0.f;
        for (int j = lo; j < CHUNKL; j++){
            float xw = xsh[j*HD + p] * wsh[j];
            const float* br = &bsh[j*HD + n0];
            #pragma unroll
            for (int k = 0; k < 16; k++) acc[k] += xw * br[k];
        }
        float* so = g_S + (size_t)blockIdx.x * (HD*DSTATE);
        #pragma unroll
        for (int k = 0; k < 16; k++) so[p*DSTATE + n0 + k] = acc[k];
    } else {
        int bid = blockIdx.x - NBC*NH;
        float* Csh = smf;                 // [32][65]
        float* Bsh = smf + 32*65;         // [128][65]
        float* ach = smf + 32*65 + 128*65;// [16][128] acum per head (h-major)
        __shared__ int lou[32];           // union window start per row
        int bc = bid >> 2, q = bid & 3;
        int i0 = q * 32, jmax = i0 + 32;
        int t0 = bc * CHUNKL;
        for (int idx = tid; idx < 32*DSTATE; idx += 256){
            int i = idx >> 6, n = idx & 63;
            Csh[i*65 + n] = g_xc[(size_t)(t0+i0+i)*CONVDIM + DINNER + DSTATE + n];
        }
        for (int idx = tid; idx < jmax*DSTATE; idx += 256){
            int j = idx >> 6, n = idx & 63;
            Bsh[j*65 + n] = g_xc[(size_t)(t0+j)*CONVDIM + DINNER + n];
        }
        // load acum [jmax rows][16 heads], transpose to h-major
        for (int idx = tid; idx < jmax*NH; idx += 256){
            int j = idx >> 4, h = idx & 15;
            ach[h*CHUNKL + j] = g_acum[(size_t)(t0+j)*NH + h];
        }
        __syncthreads();
        // per-row union window start (rows i0..i0+31)
        if (tid < 32){
            int i = i0 + tid;
            int lmin = i;
            #pragma unroll
            for (int h = 0; h < NH; h++){
                const float* a = &ach[h*CHUNKL];
                float ai = a[i];
                int lo = 0, hi = i;
                while (lo < hi){
                    int mid = (lo + hi) >> 1;
                    if (a[mid] < ai + AWIN) hi = mid; else lo = mid + 1;
                }
                if (lo < lmin) lmin = lo;
            }
            lou[tid] = lmin;
        }
        __syncthreads();
        int ti = (tid >> 4) * 2;
        int tj = (tid & 15) * 8;
        if (tj >= jmax) return;
        // skip tiles entirely below both rows' union windows (never read)
        int lmin2 = min(lou[ti], lou[ti+1]);
        if (tj + 8 <= lmin2) return;
        float acc[2][8];
        #pragma unroll
        for (int r = 0; r < 2; r++)
            #pragma unroll
            for (int c = 0; c < 8; c++) acc[r][c] = 0.f;
        for (int n = 0; n < DSTATE; n++){
            float a0 = Csh[(ti+0)*65 + n];
            float a1 = Csh[(ti+1)*65 + n];
            float b[8];
            #pragma unroll
            for (int c = 0; c < 8; c++) b[c] = Bsh[(tj+c)*65 + n];
            #pragma unroll
            for (int c = 0; c < 8; c++){ acc[0][c] += a0*b[c]; acc[1][c] += a1*b[c]; }
        }
        float* out = g_sc + (size_t)bc * CHUNKL * CHUNKL;
        #pragma unroll
        for (int r = 0; r < 2; r++)
            #pragma unroll
            for (int c = 0; c < 8; c++)
                out[(i0+ti+r)*CHUNKL + tj + c] = acc[r][c];
    }
}

// ---------------- scan ----------------
__global__ void k_scan(){
    int bid = blockIdx.x;
    int bh  = bid >> 4;
    int grp = bid & 15;
    int b = bh >> 4, h = bh & 15;
    int idx = grp * 256 + threadIdx.x;
    float st = 0.f;
    #pragma unroll 4
    for (int c = 0; c < NCH; c++){
        int bch = (b*NCH + c)*NH + h;
        size_t base = (size_t)bch * (HD*DSTATE);
        float dc = g_dec[bch];
        g_hs[base + idx] = st;
        st = st*dc + g_S[base + idx];
    }
}

// ---------------- fused y, 256 threads, conditional hsh load ---------------
__global__ void k_ssd_y(const float* __restrict__ Dp){
    extern __shared__ float smf[];
    float* xsh = smf;
    float* hsh = smf + CHUNKL*HD;
    __shared__ float ash[CHUNKL], dsh[CHUNKL];
    int bc = blockIdx.x >> 4, h = blockIdx.x & 15;
    int tid = threadIdx.x;
    int i  = tid & 127, ph = tid >> 7;
    int pb = ph * 32;
    int t0 = bc * CHUNKL;
    if (tid < CHUNKL){
        ash[tid] = g_acum[(t0+tid)*NH + h];
        dsh[tid] = g_dtv [(t0+tid)*NH + h];
    }
    for (int idx = tid; idx < CHUNKL*HD; idx += 256)
        xsh[idx] = g_xc[(size_t)(t0 + (idx >> 6))*CONVDIM + h*HD + (idx & 63)];
    bool any_off = (g_acum[(size_t)t0*NH + h] > -AWIN);
    if (any_off){
        const float* hbase = g_hs + (size_t)blockIdx.x * (HD*DSTATE);
        for (int idx = tid; idx < HD*DSTATE; idx += 256) hsh[idx] = hbase[idx];
    }
    __syncthreads();

    float ai = ash[i];
    float Dh = Dp[h];
    float acc[32];
    #pragma unroll
    for (int p = 0; p < 32; p++) acc[p] = Dh * xsh[i*HD + pb + p];

    int lo = 0, hi = i;
    while (lo < hi){
        int mid = (lo + hi) >> 1;
        if (ash[mid] < ai + AWIN) hi = mid; else lo = mid + 1;
    }
    const float* srow = g_sc + (size_t)bc * CHUNKL * CHUNKL + (size_t)i * CHUNKL;
    for (int j = lo; j <= i; j++){
        float m = srow[j] * __expf(ai - ash[j]) * dsh[j];
        const float* xr = &xsh[j*HD + pb];
        #pragma unroll
        for (int p = 0; p < 32; p++) acc[p] += m * xr[p];
    }

    if (ai > -AWIN){
        float ei = __expf(ai);
        const float* crow = g_xc + (size_t)(t0+i)*CONVDIM + DINNER + DSTATE;
        #pragma unroll
        for (int h2 = 0; h2 < 2; h2++){
            float creg[32];
            #pragma unroll
            for (int n = 0; n < 32; n++) creg[n] = ei * crow[h2*32 + n];
            #pragma unroll 4
            for (int p = 0; p < 32; p++){
                const float4* hr = (const float4*)&hsh[(pb+p)*DSTATE + h2*32];
                float a = 0.f;
                #pragma unroll
                for (int q = 0; q < 8; q++){
                    float4 v = hr[q];
                    a += creg[q*4+0]*v.x + creg[q*4+1]*v.y + creg[q*4+2]*v.z + creg[q*4+3]*v.w;
                }
                acc[p] += a;
            }
        }
    }

    float* yrow = g_y + (size_t)(t0+i)*DINNER + h*HD + pb;
    #pragma unroll
    for (int p = 0; p < 32; p++) yrow[p] = acc[p];
}

// ---------------- gate ----------------
__global__ void k_gate(const float* __restrict__ gw, __nv_bfloat16* __restrict__ At){
    int t = blockIdx.x;
    int tid = threadIdx.x;
    int d4 = tid * 4;
    float4 zv = *(const float4*)(g_zx + (size_t)t*DINPROJ + d4);
    float4 yv = *(const float4*)(g_y  + (size_t)t*DINNER + d4);
    float v0 = yv.x * siluf(zv.x);
    float v1 = yv.y * siluf(zv.y);
    float v2 = yv.z * siluf(zv.z);
    float v3 = yv.w * siluf(zv.w);
    float ss = blockReduceSum(v0*v0 + v1*v1 + v2*v2 + v3*v3);
    float rs = rsqrtf(ss / (float)DINNER + 1e-5f);
    float4 wv = *(const float4*)(gw + d4);
    float a = v0*rs*wv.x, b = v1*rs*wv.y, c = v2*rs*wv.z, e = v3*rs*wv.w;
    __nv_bfloat162 h0 = __floats2bfloat162_rn(a, b);
    __nv_bfloat162 h1 = __floats2bfloat162_rn(c, e);
    float2 f0 = __bfloat1622float2(h0), f1 = __bfloat1622float2(h1);
    int tile = t >> 7, r = t & 127;
    int kc = d4 >> 5, cc = d4 & 31;
    *(uint2*)(At + tidx(tile, DINNER >> 5, kc, r, cc, 0)) = make_uint2(*(uint32_t*)&h0, *(uint32_t*)&h1);
    *(uint2*)(At + tidx(tile, DINNER >> 5, kc, r, cc, 1)) = pack4bf(a-f0.x, b-f0.y, c-f1.x, e-f1.y);
}

// ---------------- fused final rmsnorm + head ----------------
// 128 threads per token: rmsnorm g_h row into smem, then 30 outputs (4 partials each)
__global__ void k_finhead(const float* __restrict__ fnw,
                          const float* __restrict__ hw, const float* __restrict__ hb,
                          float* __restrict__ out){
    __shared__ float xn[DMODEL];
    int t = blockIdx.x;
    int tid = threadIdx.x;
    const float* xr = g_h + (size_t)t * DMODEL;
    float ss = 0.f;
    #pragma unroll
    for (int k = 0; k < 4; k++){
        int d = tid * 4 + k * 0;  (void)d;
    }
    int d4 = tid * 4;
    float4 v = *(const float4*)(xr + d4);
    ss = v.x*v.x + v.y*v.y + v.z*v.z + v.w*v.w;
    ss = blockReduceSum(ss);
    float rs = rsqrtf(ss / (float)DMODEL + 1e-5f);
    float4 wv = *(const float4*)(fnw + d4);
    xn[d4+0] = v.x*rs*wv.x; xn[d4+1] = v.y*rs*wv.y;
    xn[d4+2] = v.z*rs*wv.z; xn[d4+3] = v.w*rs*wv.w;
    __syncthreads();
    if (tid < 120){
        int n = tid >> 2, qd = tid & 3;
        float acc = 0.f;
        #pragma unroll 16
        for (int k = qd*128; k < qd*128 + 128; k++)
            acc += xn[k] * hw[k*KOUT + n];
        acc += __shfl_down_sync(0xffffffffu, acc, 2);
        acc += __shfl_down_sync(0xffffffffu, acc, 1);
        if (qd == 0) out[(size_t)t * KOUT + n] = acc + hb[n];
    }
}

// ---------------- host ----------------
extern "C" void kernel_launch(void* const* d_in, const int* in_sizes, int n_in,
                              void* d_out, int out_size){
    const float* x      = (const float*)d_in[0];
    const float* Wembed = (const float*)d_in[1];
    const float* rmsw   = (const float*)d_in[2];
    const float* inw    = (const float*)d_in[3];
    const float* convw  = (const float*)d_in[4];
    const float* convb  = (const float*)d_in[5];
    const float* dtb    = (const float*)d_in[6];
    const float* alog   = (const float*)d_in[7];
    const float* dparam = (const float*)d_in[8];
    const float* gnw    = (const float*)d_in[9];
    const float* outw   = (const float*)d_in[10];
    const float* fnw    = (const float*)d_in[11];
    const float* hw     = (const float*)d_in[12];
    const float* hb     = (const float*)d_in[13];
    float* out = (float*)d_out;

    float *p_h, *p_zx;
    cudaGetSymbolAddress((void**)&p_h,  g_h);
    cudaGetSymbolAddress((void**)&p_zx, g_zx);
    __nv_bfloat16 *p_ain, *p_aout, *p_win, *p_wout;
    cudaGetSymbolAddress((void**)&p_ain,  g_ain);
    cudaGetSymbolAddress((void**)&p_aout, g_aout);
    cudaGetSymbolAddress((void**)&p_win,  g_win);
    cudaGetSymbolAddress((void**)&p_wout, g_wout);

    const int SSD1_SMEM = (CHUNKL*HD*2)*4;               // 65536 (state); scores fits: (32+128)*65*4 + 16*128*4 = 49792
    const int SSDY_SMEM = (CHUNKL*HD + HD*DSTATE)*4;
    const int TG_SMEM   = 3*65536;
    cudaFuncSetAttribute(k_ssd1,  cudaFuncAttributeMaxDynamicSharedMemorySize, SSD1_SMEM);
    cudaFuncSetAttribute(k_ssd_y, cudaFuncAttributeMaxDynamicSharedMemorySize, SSDY_SMEM);
    cudaFuncSetAttribute(k_tgemm, cudaFuncAttributeMaxDynamicSharedMemorySize, TG_SMEM);

    const size_t WIN_L  = (size_t)(NPAD_IN/128)*(DMODEL/32)*8192;
    const size_t WOUT_L = (size_t)(DMODEL/128)*(DINNER/32)*8192;

    k_prep<<<dim3(DMODEL/32, NPAD_IN/32, NLAYERS), dim3(32,8)>>>(
        inw, p_win, DMODEL, DINPROJ, NPAD_IN);
    k_embed<<<(NTOK*DMODEL + 255)/256, 256>>>(x, Wembed);

    for (int l = 0; l < NLAYERS; l++){
        k_rmsnorm<<<NTOK, 128>>>(p_h, rmsw + (size_t)l*DMODEL, p_ain, DMODEL);
        k_tgemm<<<dim3(NPAD_IN/128, NTOK/128), 512, TG_SMEM>>>(
            p_ain, p_win + (size_t)l*WIN_L, p_zx, nullptr, NTOK, DINPROJ, DMODEL);
        if (l == 0)
            k_prep<<<dim3(DINNER/32, DMODEL/32, NLAYERS), dim3(32,8)>>>(
                outw, p_wout, DINNER, DMODEL, DMODEL);
        k_convdt<<<NCONVB + NDTB, 256>>>(convw + (size_t)l*CONVDIM*DCONV,
                                         convb + (size_t)l*CONVDIM,
                                         dtb + (size_t)l*NH, alog + (size_t)l*NH);
        k_ssd1<<<NBC*NH + NBC*4, 256, SSD1_SMEM>>>();
        k_scan<<<BSZ*NH*16, 256>>>();
        k_ssd_y<<<NBC*NH, 256, SSDY_SMEM>>>(dparam + (size_t)l*NH);
        k_gate<<<NTOK, 256>>>(gnw + (size_t)l*DINNER, p_aout);
        k_tgemm<<<dim3(DMODEL/128, NTOK/128), 512, TG_SMEM>>>(
            p_aout, p_wout + (size_t)l*WOUT_L, p_h, p_h, NTOK, DMODEL, DINNER);
    }

    k_finhead<<<NTOK, 128>>>(fnw, hw, hb, out);
}